// round 2
// baseline (speedup 1.0000x reference)
#include <cuda_runtime.h>
#include <math.h>

#define BB 128
#define NN 1024
#define DD 256
#define KS 8
#define HID 1024
#define EPSF 1e-6f
#define LN_EPS 1e-6f
#define SCALE_QK 0.0625f

// ---------------- device scratch (no allocations allowed) ----------------
__device__ float g_x[BB * NN * DD];        // LN'd tokens        (134 MB)
__device__ float g_k[BB * NN * DD];        // k projection       (134 MB)
__device__ float g_v[BB * NN * DD];        // v projection       (134 MB)
__device__ float g_slots[BB * KS * DD];    // slots (in-place across iters)
__device__ float g_q[BB * KS * DD];
__device__ float g_masks[BB * KS * NN];    // softmax-over-slots masks (output #2)
__device__ float g_invden[BB * KS];        // 1/(rowsum + N*eps + eps)
__device__ float g_updates[BB * KS * DD];
__device__ float g_hidden[BB * KS * HID];

// ---------------- init slots ----------------
__global__ void k_init_slots(const float* __restrict__ init_slots) {
    int i = blockIdx.x * 256 + threadIdx.x;
    g_slots[i] = init_slots[i];
}

// ---------------- LN over tokens: one warp per row ----------------
__global__ __launch_bounds__(256) void k_ln_tokens(const float* __restrict__ t,
                                                   const float* __restrict__ g,
                                                   const float* __restrict__ b) {
    int row  = blockIdx.x * 8 + (threadIdx.x >> 5);
    int lane = threadIdx.x & 31;
    const float* p = t + (size_t)row * DD;
    float vals[8];
    float s = 0.f, s2 = 0.f;
#pragma unroll
    for (int i = 0; i < 8; i++) {
        float x = p[lane + i * 32];
        vals[i] = x; s += x; s2 += x * x;
    }
#pragma unroll
    for (int o = 16; o; o >>= 1) {
        s  += __shfl_xor_sync(0xFFFFFFFFu, s,  o);
        s2 += __shfl_xor_sync(0xFFFFFFFFu, s2, o);
    }
    float mean = s * (1.f / DD);
    float var  = s2 * (1.f / DD) - mean * mean;
    float inv  = rsqrtf(var + LN_EPS);
#pragma unroll
    for (int i = 0; i < 8; i++) {
        int c = lane + i * 32;
        g_x[(size_t)row * DD + c] = (vals[i] - mean) * inv * g[c] + b[c];
    }
}

// ---------------- big GEMM: C(131072x512) = g_x @ [Wk|Wv] + [bk|bv] ----------------
// 128x128 tile, BK=8, 8x8 per thread, 256 threads.
__global__ __launch_bounds__(256) void k_gemm_kv(const float* __restrict__ Wk,
                                                 const float* __restrict__ bk,
                                                 const float* __restrict__ Wv,
                                                 const float* __restrict__ bv) {
    __shared__ float As[8][128];
    __shared__ float Bs[8][128];
    int row0 = blockIdx.x * 128;
    int col0 = blockIdx.y * 128;      // 0..511
    const float* W    = (col0 < 256) ? Wk : Wv;
    const float* bias = (col0 < 256) ? bk : bv;
    int wcol0 = (col0 < 256) ? col0 : col0 - 256;

    int tid = threadIdx.x;
    int tm = tid >> 4, tn = tid & 15;
    int ar = tid >> 1;              // 0..127
    int ak = (tid & 1) * 4;         // 0 or 4
    int brow = tid >> 5;            // 0..7
    int bc = (tid & 31) * 4;        // 0..124

    float acc[8][8];
#pragma unroll
    for (int i = 0; i < 8; i++)
#pragma unroll
        for (int j = 0; j < 8; j++) acc[i][j] = 0.f;

    for (int k0 = 0; k0 < 256; k0 += 8) {
        float4 a = *(const float4*)(g_x + (size_t)(row0 + ar) * 256 + k0 + ak);
        As[ak + 0][ar] = a.x; As[ak + 1][ar] = a.y;
        As[ak + 2][ar] = a.z; As[ak + 3][ar] = a.w;
        float4 bfr = *(const float4*)(W + (size_t)(k0 + brow) * 256 + wcol0 + bc);
        *(float4*)&Bs[brow][bc] = bfr;
        __syncthreads();
#pragma unroll
        for (int kk = 0; kk < 8; kk++) {
            float af[8], bf[8];
            *(float4*)(af)     = *(float4*)&As[kk][tm * 8];
            *(float4*)(af + 4) = *(float4*)&As[kk][tm * 8 + 4];
            *(float4*)(bf)     = *(float4*)&Bs[kk][tn * 8];
            *(float4*)(bf + 4) = *(float4*)&Bs[kk][tn * 8 + 4];
#pragma unroll
            for (int i = 0; i < 8; i++)
#pragma unroll
                for (int j = 0; j < 8; j++) acc[i][j] += af[i] * bf[j];
        }
        __syncthreads();
    }

    float* out = (col0 < 256) ? g_k : g_v;
#pragma unroll
    for (int i = 0; i < 8; i++) {
        int r = row0 + tm * 8 + i;
        int c = wcol0 + tn * 8;
        float4 o0, o1;
        o0.x = acc[i][0] + bias[c + 0]; o0.y = acc[i][1] + bias[c + 1];
        o0.z = acc[i][2] + bias[c + 2]; o0.w = acc[i][3] + bias[c + 3];
        o1.x = acc[i][4] + bias[c + 4]; o1.y = acc[i][5] + bias[c + 5];
        o1.z = acc[i][6] + bias[c + 6]; o1.w = acc[i][7] + bias[c + 7];
        *(float4*)(out + (size_t)r * 256 + c)     = o0;
        *(float4*)(out + (size_t)r * 256 + c + 4) = o1;
    }
}

// ---------------- q = LN(slots) @ Wq + bq : one block per batch (8 rows) ----------------
__global__ __launch_bounds__(256) void k_qproj(const float* __restrict__ lg,
                                               const float* __restrict__ lb,
                                               const float* __restrict__ Wq,
                                               const float* __restrict__ bq) {
    __shared__ float sx[8][DD];
    int b = blockIdx.x;
    int tid = threadIdx.x, warp = tid >> 5, lane = tid & 31;

    const float* p = g_slots + ((size_t)b * KS + warp) * DD;
    float vals[8]; float s = 0.f, s2 = 0.f;
#pragma unroll
    for (int i = 0; i < 8; i++) { float x = p[lane + i * 32]; vals[i] = x; s += x; s2 += x * x; }
#pragma unroll
    for (int o = 16; o; o >>= 1) {
        s  += __shfl_xor_sync(0xFFFFFFFFu, s,  o);
        s2 += __shfl_xor_sync(0xFFFFFFFFu, s2, o);
    }
    float mean = s * (1.f / DD);
    float inv  = rsqrtf(s2 * (1.f / DD) - mean * mean + LN_EPS);
#pragma unroll
    for (int i = 0; i < 8; i++) {
        int c = lane + i * 32;
        sx[warp][c] = (vals[i] - mean) * inv * lg[c] + lb[c];
    }
    __syncthreads();

    float acc[8];
#pragma unroll
    for (int r = 0; r < 8; r++) acc[r] = 0.f;
    for (int i = 0; i < 256; i++) {
        float w = Wq[i * 256 + tid];
#pragma unroll
        for (int r = 0; r < 8; r++) acc[r] += sx[r][i] * w;
    }
    float bqv = bq[tid];
#pragma unroll
    for (int r = 0; r < 8; r++)
        g_q[((size_t)b * KS + r) * DD + tid] = acc[r] + bqv;
}

// ---------------- logits + softmax over slots. Block: (32 tokens) x 8 slots ----------------
__global__ __launch_bounds__(256) void k_logits_softmax() {
    __shared__ float qs[256][8];      // [i][slot]
    __shared__ float ks[256][33];     // [i][tok], padded
    int b  = blockIdx.y;
    int n0 = blockIdx.x * 32;
    int tid = threadIdx.x;

#pragma unroll
    for (int t = 0; t < 8; t++) {
        int flat = tid + t * 256; int s = flat >> 8; int i = flat & 255;
        qs[i][s] = g_q[((size_t)b * KS + s) * DD + i];
    }
#pragma unroll 4
    for (int t = 0; t < 32; t++) {
        int flat = tid + t * 256; int tok = flat >> 8; int i = flat & 255;
        ks[i][tok] = g_k[((size_t)b * NN + n0 + tok) * DD + i];
    }
    __syncthreads();

    int tok = tid >> 3, s = tid & 7;
    float acc = 0.f;
#pragma unroll 4
    for (int i = 0; i < 256; i++) acc += qs[i][s] * ks[i][tok];
    acc *= SCALE_QK;

    float m = acc;
#pragma unroll
    for (int o = 1; o < 8; o <<= 1) m = fmaxf(m, __shfl_xor_sync(0xFFFFFFFFu, m, o));
    float e = expf(acc - m);
    float sum = e;
#pragma unroll
    for (int o = 1; o < 8; o <<= 1) sum += __shfl_xor_sync(0xFFFFFFFFu, sum, o);
    g_masks[((size_t)b * KS + s) * NN + n0 + tok] = e / sum;
}

// ---------------- per-(b,k) row sum over N -> inverse denominator ----------------
__global__ __launch_bounds__(256) void k_rowsum() {
    int bk = blockIdx.x;                // 0..1023
    const float* row = g_masks + (size_t)bk * NN;
    int tid = threadIdx.x;
    float s = 0.f;
    for (int i = tid; i < NN; i += 256) s += row[i];
#pragma unroll
    for (int o = 16; o; o >>= 1) s += __shfl_xor_sync(0xFFFFFFFFu, s, o);
    __shared__ float red[8];
    if ((tid & 31) == 0) red[tid >> 5] = s;
    __syncthreads();
    if (tid == 0) {
        float tot = 0.f;
#pragma unroll
        for (int w = 0; w < 8; w++) tot += red[w];
        g_invden[bk] = 1.f / (tot + (float)NN * EPSF + EPSF);
    }
}

// ---------------- updates = attn_norm @ v : one block per batch, thread = d ----------------
__global__ __launch_bounds__(256) void k_updates() {
    int b = blockIdx.x;
    int tid = threadIdx.x;
    __shared__ float attw[8][64];
    __shared__ float invd[8];
    if (tid < 8) invd[tid] = g_invden[b * KS + tid];

    float acc[8];
#pragma unroll
    for (int k = 0; k < 8; k++) acc[k] = 0.f;

    for (int n0 = 0; n0 < NN; n0 += 64) {
        __syncthreads();
#pragma unroll
        for (int t = 0; t < 2; t++) {
            int flat = tid + t * 256; int kk = flat >> 6; int j = flat & 63;
            attw[kk][j] = (g_masks[((size_t)b * KS + kk) * NN + n0 + j] + EPSF) * invd[kk];
        }
        __syncthreads();
        for (int j = 0; j < 64; j++) {
            float vj = g_v[((size_t)b * NN + n0 + j) * DD + tid];
#pragma unroll
            for (int kk = 0; kk < 8; kk++) acc[kk] += attw[kk][j] * vj;
        }
    }
#pragma unroll
    for (int kk = 0; kk < 8; kk++)
        g_updates[((size_t)b * KS + kk) * DD + tid] = acc[kk];
}

// ---------------- GRU cell: one block per batch ----------------
__global__ __launch_bounds__(256) void k_gru(const float* __restrict__ W_ih,
                                             const float* __restrict__ b_ih,
                                             const float* __restrict__ W_hh,
                                             const float* __restrict__ b_hh) {
    int b = blockIdx.x;
    int tid = threadIdx.x;
    __shared__ float us[8][256];
    __shared__ float ss[8][256];
#pragma unroll
    for (int t = 0; t < 8; t++) {
        int flat = tid + t * 256; int r = flat >> 8; int i = flat & 255;
        us[r][i] = g_updates[((size_t)b * KS + r) * DD + i];
        ss[r][i] = g_slots[((size_t)b * KS + r) * DD + i];
    }
    __syncthreads();

    float agi[3][8], agh[3][8];
#pragma unroll
    for (int c = 0; c < 3; c++)
#pragma unroll
        for (int r = 0; r < 8; r++) { agi[c][r] = 0.f; agh[c][r] = 0.f; }

    for (int i = 0; i < 256; i++) {
        float wih[3], whh[3];
#pragma unroll
        for (int c = 0; c < 3; c++) {
            wih[c] = W_ih[i * 768 + c * 256 + tid];
            whh[c] = W_hh[i * 768 + c * 256 + tid];
        }
#pragma unroll
        for (int r = 0; r < 8; r++) {
            float u = us[r][i], sv = ss[r][i];
#pragma unroll
            for (int c = 0; c < 3; c++) { agi[c][r] += u * wih[c]; agh[c][r] += sv * whh[c]; }
        }
    }
    float bi0 = b_ih[tid], bi1 = b_ih[256 + tid], bi2 = b_ih[512 + tid];
    float bh0 = b_hh[tid], bh1 = b_hh[256 + tid], bh2 = b_hh[512 + tid];
#pragma unroll
    for (int r = 0; r < 8; r++) {
        float ir = agi[0][r] + bi0, hr = agh[0][r] + bh0;
        float iz = agi[1][r] + bi1, hz = agh[1][r] + bh1;
        float in = agi[2][r] + bi2, hn = agh[2][r] + bh2;
        float rr = 1.f / (1.f + expf(-(ir + hr)));
        float z  = 1.f / (1.f + expf(-(iz + hz)));
        float nn = tanhf(in + rr * hn);
        g_slots[((size_t)b * KS + r) * DD + tid] = (1.f - z) * nn + z * ss[r][tid];
    }
}

// ---------------- MLP part 1: hidden = gelu(LN(slots) @ W1 + b1) ----------------
__global__ __launch_bounds__(256) void k_mlp1(const float* __restrict__ lg,
                                              const float* __restrict__ lb,
                                              const float* __restrict__ W1,
                                              const float* __restrict__ b1) {
    __shared__ float sx[8][256];
    int b = blockIdx.x;
    int tid = threadIdx.x, warp = tid >> 5, lane = tid & 31;

    const float* p = g_slots + ((size_t)b * KS + warp) * DD;
    float vals[8]; float s = 0.f, s2 = 0.f;
#pragma unroll
    for (int i = 0; i < 8; i++) { float x = p[lane + i * 32]; vals[i] = x; s += x; s2 += x * x; }
#pragma unroll
    for (int o = 16; o; o >>= 1) {
        s  += __shfl_xor_sync(0xFFFFFFFFu, s,  o);
        s2 += __shfl_xor_sync(0xFFFFFFFFu, s2, o);
    }
    float mean = s * (1.f / DD);
    float inv  = rsqrtf(s2 * (1.f / DD) - mean * mean + LN_EPS);
#pragma unroll
    for (int i = 0; i < 8; i++) {
        int c = lane + i * 32;
        sx[warp][c] = (vals[i] - mean) * inv * lg[c] + lb[c];
    }
    __syncthreads();

    float acc[4][8];
#pragma unroll
    for (int c = 0; c < 4; c++)
#pragma unroll
        for (int r = 0; r < 8; r++) acc[c][r] = 0.f;

    for (int i = 0; i < 256; i++) {
        float w[4];
#pragma unroll
        for (int c = 0; c < 4; c++) w[c] = W1[i * 1024 + c * 256 + tid];
#pragma unroll
        for (int r = 0; r < 8; r++) {
            float xr = sx[r][i];
#pragma unroll
            for (int c = 0; c < 4; c++) acc[c][r] += xr * w[c];
        }
    }
#pragma unroll
    for (int c = 0; c < 4; c++) {
        float bv = b1[c * 256 + tid];
#pragma unroll
        for (int r = 0; r < 8; r++) {
            float x = acc[c][r] + bv;
            float ge = 0.5f * x * (1.f + erff(x * 0.70710678118f));
            g_hidden[((size_t)b * KS + r) * HID + c * 256 + tid] = ge;
        }
    }
}

// ---------------- MLP part 2: slots += hidden @ W2 + b2 ----------------
__global__ __launch_bounds__(256) void k_mlp2(const float* __restrict__ W2,
                                              const float* __restrict__ b2) {
    __shared__ float hs[8][1024];     // 32 KB
    int b = blockIdx.x;
    int tid = threadIdx.x;
#pragma unroll
    for (int t = 0; t < 32; t++) {
        int flat = tid + t * 256; int r = flat >> 10; int i = flat & 1023;
        hs[r][i] = g_hidden[((size_t)b * KS + r) * HID + i];
    }
    __syncthreads();

    float acc[8];
#pragma unroll
    for (int r = 0; r < 8; r++) acc[r] = 0.f;
    for (int i = 0; i < 1024; i++) {
        float w = W2[i * 256 + tid];
#pragma unroll
        for (int r = 0; r < 8; r++) acc[r] += hs[r][i] * w;
    }
    float bv = b2[tid];
#pragma unroll
    for (int r = 0; r < 8; r++)
        g_slots[((size_t)b * KS + r) * DD + tid] += acc[r] + bv;
}

// ---------------- pack output: [slots (262144) | masks (1048576)] ----------------
__global__ void k_out(float* __restrict__ out, int total) {
    for (int idx = blockIdx.x * blockDim.x + threadIdx.x; idx < total;
         idx += gridDim.x * blockDim.x) {
        out[idx] = (idx < BB * KS * DD) ? g_slots[idx] : g_masks[idx - BB * KS * DD];
    }
}

// ---------------- launch ----------------
extern "C" void kernel_launch(void* const* d_in, const int* in_sizes, int n_in,
                              void* d_out, int out_size) {
    const float* tokens     = (const float*)d_in[0];
    const float* init_slots = (const float*)d_in[1];
    const float* ln_in_g    = (const float*)d_in[2];
    const float* ln_in_b    = (const float*)d_in[3];
    const float* Wk         = (const float*)d_in[4];
    const float* bk         = (const float*)d_in[5];
    const float* Wv         = (const float*)d_in[6];
    const float* bv         = (const float*)d_in[7];
    const float* ln_s_g     = (const float*)d_in[8];
    const float* ln_s_b     = (const float*)d_in[9];
    const float* Wq         = (const float*)d_in[10];
    const float* bq         = (const float*)d_in[11];
    const float* W_ih       = (const float*)d_in[12];
    const float* b_ih       = (const float*)d_in[13];
    const float* W_hh       = (const float*)d_in[14];
    const float* b_hh       = (const float*)d_in[15];
    const float* ln_m_g     = (const float*)d_in[16];
    const float* ln_m_b     = (const float*)d_in[17];
    const float* W1         = (const float*)d_in[18];
    const float* b1         = (const float*)d_in[19];
    const float* W2         = (const float*)d_in[20];
    const float* b2         = (const float*)d_in[21];

    k_init_slots<<<BB * KS * DD / 256, 256>>>(init_slots);
    k_ln_tokens<<<BB * NN / 8, 256>>>(tokens, ln_in_g, ln_in_b);
    dim3 gkv(BB * NN / 128, 512 / 128);
    k_gemm_kv<<<gkv, 256>>>(Wk, bk, Wv, bv);

    for (int it = 0; it < 3; it++) {
        k_qproj<<<BB, 256>>>(ln_s_g, ln_s_b, Wq, bq);
        dim3 gls(NN / 32, BB);
        k_logits_softmax<<<gls, 256>>>();
        k_rowsum<<<BB * KS, 256>>>();
        k_updates<<<BB, 256>>>();
        k_gru<<<BB, 256>>>(W_ih, b_ih, W_hh, b_hh);
        k_mlp1<<<BB, 256>>>(ln_m_g, ln_m_b, W1, b1);
        k_mlp2<<<BB, 256>>>(W2, b2);
    }

    k_out<<<2560, 256>>>((float*)d_out, out_size);
}

// round 5
// speedup vs baseline: 2.6209x; 2.6209x over previous
#include <cuda_runtime.h>
#include <math.h>

#define BB 128
#define NN 1024
#define DD 256
#define KS 8
#define HID 1024
#define EPSF 1e-6f
#define LN_EPS 1e-6f
#define SCALE_QK 0.0625f

// ---------------- device scratch ----------------
__device__ float g_x[BB * NN * DD];            // LN'd tokens (tf32-ready fp32)
__device__ float g_kv[(size_t)BB * NN * 512];  // [token][0:256]=k, [256:512]=v
__device__ float g_slots[BB * KS * DD];
__device__ float g_sln[BB * KS * DD];          // LN'd slots (GEMM A)
__device__ float g_q[BB * KS * DD];
__device__ float g_masks[BB * KS * NN];
__device__ float g_invden[BB * KS];
__device__ float g_upart[8][BB * KS * DD];
__device__ float g_updates[BB * KS * DD];
__device__ float g_gates[BB * KS * 1024];      // [rsum|zsum|inn|hn]
__device__ float g_hidden[BB * KS * HID];
__device__ float g_wgru[512 * 1024];           // padded GRU weight
__device__ float g_bgru[1024];

// cvt.rna.tf32.f32 requires a .b32 destination register (PTX ISA) — use "=r".
__device__ __forceinline__ float to_tf32(float x) {
    unsigned u;
    asm("cvt.rna.tf32.f32 %0, %1;" : "=r"(u) : "f"(x));
    return __uint_as_float(u);
}

__device__ __forceinline__ void mma_tf32(float* d, const unsigned* a, const unsigned* b) {
    asm volatile(
        "mma.sync.aligned.m16n8k8.row.col.f32.tf32.tf32.f32 "
        "{%0,%1,%2,%3}, {%4,%5,%6,%7}, {%8,%9}, {%0,%1,%2,%3};\n"
        : "+f"(d[0]), "+f"(d[1]), "+f"(d[2]), "+f"(d[3])
        : "r"(a[0]), "r"(a[1]), "r"(a[2]), "r"(a[3]), "r"(b[0]), "r"(b[1]));
}

// ---------------- init slots ----------------
__global__ void k_init_slots(const float* __restrict__ init_slots) {
    int i = blockIdx.x * 256 + threadIdx.x;
    g_slots[i] = init_slots[i];
}

// ---------------- LN over tokens ----------------
__global__ __launch_bounds__(256) void k_ln_tokens(const float* __restrict__ t,
                                                   const float* __restrict__ g,
                                                   const float* __restrict__ b) {
    int row  = blockIdx.x * 8 + (threadIdx.x >> 5);
    int lane = threadIdx.x & 31;
    const float* p = t + (size_t)row * DD;
    float vals[8]; float s = 0.f, s2 = 0.f;
#pragma unroll
    for (int i = 0; i < 8; i++) { float x = p[lane + i * 32]; vals[i] = x; s += x; s2 += x * x; }
#pragma unroll
    for (int o = 16; o; o >>= 1) {
        s  += __shfl_xor_sync(0xFFFFFFFFu, s,  o);
        s2 += __shfl_xor_sync(0xFFFFFFFFu, s2, o);
    }
    float mean = s * (1.f / DD);
    float inv  = rsqrtf(s2 * (1.f / DD) - mean * mean + LN_EPS);
#pragma unroll
    for (int i = 0; i < 8; i++) {
        int c = lane + i * 32;
        g_x[(size_t)row * DD + c] = (vals[i] - mean) * inv * g[c] + b[c];
    }
}

// ---------------- GRU weight/bias prep ----------------
// g_wgru[k][c]: rows 0-255 from W_ih, rows 256-511 from W_hh.
// col groups: [0:256)=r, [256:512)=z, [512:768)=inn (W_ih only), [768:1024)=hn (W_hh only)
__global__ void k_prep_gru(const float* __restrict__ Wih, const float* __restrict__ Whh,
                           const float* __restrict__ bih, const float* __restrict__ bhh) {
    int idx = blockIdx.x * 256 + threadIdx.x;      // over 512*1024
    int k = idx >> 10, c = idx & 1023;
    int grp = c >> 8, cc = c & 255;
    float v = 0.f;
    if (k < 256) {
        if (grp < 3) v = Wih[k * 768 + grp * 256 + cc];
    } else {
        int kk = k - 256;
        if (grp < 2)       v = Whh[kk * 768 + grp * 256 + cc];
        else if (grp == 3) v = Whh[kk * 768 + 512 + cc];
    }
    g_wgru[idx] = v;
    if (idx < 1024) {
        int g2 = idx >> 8, c2 = idx & 255;
        float bb;
        if (g2 < 2)       bb = bih[g2 * 256 + c2] + bhh[g2 * 256 + c2];
        else if (g2 == 2) bb = bih[512 + c2];
        else              bb = bhh[512 + c2];
        g_bgru[idx] = bb;
    }
}

// ---------------- unified tf32 GEMM ----------------
// MODE 0: kv   C[131072,512]=g_x@[Wk|Wv]+[bk|bv]   (BSPLIT)
// MODE 1: qprj C[1024,256]=g_sln@Wq+bq
// MODE 2: gru  C[1024,1024]=[g_updates|g_slots]@g_wgru+g_bgru (ASPLIT)
// MODE 3: mlp1 C[1024,1024]=gelu(g_sln@W1+b1) -> g_hidden
// MODE 4: mlp2 g_slots += g_hidden@W2+b2 (resid)
template<int MODE>
__global__ void gemm_k(const float* __restrict__ W, const float* __restrict__ W2,
                       const float* __restrict__ bias_in, const float* __restrict__ bias2_in) {
    constexpr int BM  = (MODE == 0) ? 128 : 64;
    constexpr int BN  = 64;
    constexpr int BK  = 16;
    constexpr int WGM = (MODE == 0) ? 4 : 2;   // warps along M (32 rows each)
    constexpr int NT  = WGM * 2 * 32;
    constexpr int N   = (MODE == 0) ? 512 : (MODE == 2 || MODE == 3) ? 1024 : 256;
    constexpr int K   = (MODE == 0) ? 256 : (MODE == 2) ? 512 : (MODE == 4) ? 1024 : 256;
    constexpr int LDB = (MODE == 2 || MODE == 3) ? 1024 : 256;
    constexpr bool ASPLIT = (MODE == 2);
    constexpr bool BSPLIT = (MODE == 0);
    constexpr int LDA_S = BK + 4;   // smem A stride (floats)
    constexpr int LDB_S = BN + 8;   // smem B stride

    __shared__ float As[2][BM][LDA_S];
    __shared__ float Bs[2][BK][LDB_S];

    const float* Ag  = (MODE == 0) ? g_x : (MODE == 1 || MODE == 3) ? g_sln
                     : (MODE == 2) ? g_updates : g_hidden;
    const float* A2g = g_slots;
    const float* Bg  = (MODE == 2) ? g_wgru : W;
    const float* bi0 = (MODE == 2) ? g_bgru : bias_in;
    float* C = (MODE == 0) ? g_kv : (MODE == 1) ? g_q : (MODE == 2) ? g_gates
             : (MODE == 3) ? g_hidden : g_slots;

    int tid = threadIdx.x;
    int warp = tid >> 5, lane = tid & 31;
    int wm = warp % WGM, wn = warp / WGM;
    int row0 = blockIdx.y * BM;
    int col0 = blockIdx.x * BN;

    const float* Bp = Bg; const float* biasp = bi0; int bcol0 = col0;
    if (BSPLIT && col0 >= 256) { Bp = W2; biasp = bias2_in; bcol0 = col0 - 256; }

    constexpr int A_PER = BM * BK / 4 / NT;   // 2
    constexpr int B_PER = BK * BN / 4 / NT;   // 1 or 2
    float4 aReg[A_PER], bReg[B_PER];

    int nstage = K / BK;

    // ---- prologue load k0=0 ----
    {
        int k0 = 0;
        const float* Ab = Ag; int koff = k0; // k0<256 always here
#pragma unroll
        for (int l = 0; l < A_PER; l++) {
            int idx = tid + l * NT; int r = idx >> 2, c4 = (idx & 3) * 4;
            int lda = ASPLIT ? 256 : K;
            aReg[l] = *(const float4*)(Ab + (size_t)(row0 + r) * lda + koff + c4);
        }
#pragma unroll
        for (int l = 0; l < B_PER; l++) {
            int idx = tid + l * NT; int r = idx / (BN / 4), c4 = (idx % (BN / 4)) * 4;
            bReg[l] = *(const float4*)(Bp + (size_t)(k0 + r) * LDB + bcol0 + c4);
        }
    }
    // store stage 0
#pragma unroll
    for (int l = 0; l < A_PER; l++) {
        int idx = tid + l * NT; int r = idx >> 2, c4 = (idx & 3) * 4;
        float4 t; t.x = to_tf32(aReg[l].x); t.y = to_tf32(aReg[l].y);
        t.z = to_tf32(aReg[l].z); t.w = to_tf32(aReg[l].w);
        *(float4*)&As[0][r][c4] = t;
    }
#pragma unroll
    for (int l = 0; l < B_PER; l++) {
        int idx = tid + l * NT; int r = idx / (BN / 4), c4 = (idx % (BN / 4)) * 4;
        float4 t; t.x = to_tf32(bReg[l].x); t.y = to_tf32(bReg[l].y);
        t.z = to_tf32(bReg[l].z); t.w = to_tf32(bReg[l].w);
        *(float4*)&Bs[0][r][c4] = t;
    }
    __syncthreads();

    float acc[2][4][4];
#pragma unroll
    for (int mt = 0; mt < 2; mt++)
#pragma unroll
        for (int nt = 0; nt < 4; nt++)
#pragma unroll
            for (int i = 0; i < 4; i++) acc[mt][nt][i] = 0.f;

    for (int s = 0; s < nstage; s++) {
        if (s + 1 < nstage) {
            int k0 = (s + 1) * BK;
            const float* Ab = Ag; int koff = k0;
            if (ASPLIT && k0 >= 256) { Ab = A2g; koff = k0 - 256; }
#pragma unroll
            for (int l = 0; l < A_PER; l++) {
                int idx = tid + l * NT; int r = idx >> 2, c4 = (idx & 3) * 4;
                int lda = ASPLIT ? 256 : K;
                aReg[l] = *(const float4*)(Ab + (size_t)(row0 + r) * lda + koff + c4);
            }
#pragma unroll
            for (int l = 0; l < B_PER; l++) {
                int idx = tid + l * NT; int r = idx / (BN / 4), c4 = (idx % (BN / 4)) * 4;
                bReg[l] = *(const float4*)(Bp + (size_t)(k0 + r) * LDB + bcol0 + c4);
            }
        }
        int bf = s & 1;
#pragma unroll
        for (int ks = 0; ks < 2; ks++) {
            int kb = ks * 8;
            unsigned afr[2][4], bfr[4][2];
            int lr = lane >> 2, lc = lane & 3;
#pragma unroll
            for (int mt = 0; mt < 2; mt++) {
                int r = wm * 32 + mt * 16 + lr;
                afr[mt][0] = __float_as_uint(As[bf][r][kb + lc]);
                afr[mt][1] = __float_as_uint(As[bf][r + 8][kb + lc]);
                afr[mt][2] = __float_as_uint(As[bf][r][kb + lc + 4]);
                afr[mt][3] = __float_as_uint(As[bf][r + 8][kb + lc + 4]);
            }
#pragma unroll
            for (int nt = 0; nt < 4; nt++) {
                int cc = wn * 32 + nt * 8 + lr;
                bfr[nt][0] = __float_as_uint(Bs[bf][kb + lc][cc]);
                bfr[nt][1] = __float_as_uint(Bs[bf][kb + lc + 4][cc]);
            }
#pragma unroll
            for (int mt = 0; mt < 2; mt++)
#pragma unroll
                for (int nt = 0; nt < 4; nt++)
                    mma_tf32(acc[mt][nt], afr[mt], bfr[nt]);
        }
        if (s + 1 < nstage) {
            int nb = (s + 1) & 1;
#pragma unroll
            for (int l = 0; l < A_PER; l++) {
                int idx = tid + l * NT; int r = idx >> 2, c4 = (idx & 3) * 4;
                float4 t; t.x = to_tf32(aReg[l].x); t.y = to_tf32(aReg[l].y);
                t.z = to_tf32(aReg[l].z); t.w = to_tf32(aReg[l].w);
                *(float4*)&As[nb][r][c4] = t;
            }
#pragma unroll
            for (int l = 0; l < B_PER; l++) {
                int idx = tid + l * NT; int r = idx / (BN / 4), c4 = (idx % (BN / 4)) * 4;
                float4 t; t.x = to_tf32(bReg[l].x); t.y = to_tf32(bReg[l].y);
                t.z = to_tf32(bReg[l].z); t.w = to_tf32(bReg[l].w);
                *(float4*)&Bs[nb][r][c4] = t;
            }
        }
        __syncthreads();
    }

    // ---- epilogue ----
    int lr = lane >> 2, lc = lane & 3;
#pragma unroll
    for (int mt = 0; mt < 2; mt++)
#pragma unroll
        for (int nt = 0; nt < 4; nt++) {
            int r = row0 + wm * 32 + mt * 16 + lr;
            int c = col0 + wn * 32 + nt * 8 + lc * 2;
            int bc = c - (col0 - bcol0);
            float b0 = biasp[bc], b1 = biasp[bc + 1];
            float v0 = acc[mt][nt][0] + b0, v1 = acc[mt][nt][1] + b1;
            float v2 = acc[mt][nt][2] + b0, v3 = acc[mt][nt][3] + b1;
            if (MODE == 3) {
                v0 = 0.5f * v0 * (1.f + erff(v0 * 0.70710678118654752f));
                v1 = 0.5f * v1 * (1.f + erff(v1 * 0.70710678118654752f));
                v2 = 0.5f * v2 * (1.f + erff(v2 * 0.70710678118654752f));
                v3 = 0.5f * v3 * (1.f + erff(v3 * 0.70710678118654752f));
            }
            if (MODE == 4) {
                v0 += g_slots[(size_t)r * N + c];     v1 += g_slots[(size_t)r * N + c + 1];
                v2 += g_slots[(size_t)(r + 8) * N + c]; v3 += g_slots[(size_t)(r + 8) * N + c + 1];
            }
            C[(size_t)r * N + c] = v0;       C[(size_t)r * N + c + 1] = v1;
            C[(size_t)(r + 8) * N + c] = v2; C[(size_t)(r + 8) * N + c + 1] = v3;
        }
}

// ---------------- LN of slots -> g_sln (one row per block) ----------------
__global__ __launch_bounds__(256) void k_ln_slots(const float* __restrict__ g,
                                                  const float* __restrict__ b) {
    int row = blockIdx.x, c = threadIdx.x;
    float x = g_slots[row * DD + c];
    float s1 = x, s2 = x * x;
#pragma unroll
    for (int o = 16; o; o >>= 1) {
        s1 += __shfl_xor_sync(0xFFFFFFFFu, s1, o);
        s2 += __shfl_xor_sync(0xFFFFFFFFu, s2, o);
    }
    __shared__ float r1[8], r2[8];
    if ((c & 31) == 0) { r1[c >> 5] = s1; r2[c >> 5] = s2; }
    __syncthreads();
    float t1 = 0.f, t2 = 0.f;
#pragma unroll
    for (int w = 0; w < 8; w++) { t1 += r1[w]; t2 += r2[w]; }
    float mean = t1 * (1.f / DD);
    float inv  = rsqrtf(t2 * (1.f / DD) - mean * mean + LN_EPS);
    g_sln[row * DD + c] = (x - mean) * inv * g[c] + b[c];
}

// ---------------- logits + softmax over slots ----------------
__global__ __launch_bounds__(256) void k_logits_softmax() {
    __shared__ float qs[256][8];
    __shared__ float ks[256][33];
    int b  = blockIdx.y;
    int n0 = blockIdx.x * 32;
    int tid = threadIdx.x;
#pragma unroll
    for (int t = 0; t < 8; t++) {
        int flat = tid + t * 256; int s = flat >> 8; int i = flat & 255;
        qs[i][s] = g_q[((size_t)b * KS + s) * DD + i];
    }
#pragma unroll 4
    for (int t = 0; t < 32; t++) {
        int flat = tid + t * 256; int tok = flat >> 8; int i = flat & 255;
        ks[i][tok] = g_kv[(size_t)(b * NN + n0 + tok) * 512 + i];
    }
    __syncthreads();
    int tok = tid >> 3, s = tid & 7;
    float acc = 0.f;
#pragma unroll 4
    for (int i = 0; i < 256; i++) acc += qs[i][s] * ks[i][tok];
    acc *= SCALE_QK;
    float m = acc;
#pragma unroll
    for (int o = 1; o < 8; o <<= 1) m = fmaxf(m, __shfl_xor_sync(0xFFFFFFFFu, m, o));
    float e = expf(acc - m);
    float sum = e;
#pragma unroll
    for (int o = 1; o < 8; o <<= 1) sum += __shfl_xor_sync(0xFFFFFFFFu, sum, o);
    g_masks[((size_t)b * KS + s) * NN + n0 + tok] = e / sum;
}

// ---------------- rowsum over N -> inverse denominator ----------------
__global__ __launch_bounds__(256) void k_rowsum() {
    int bk = blockIdx.x;
    const float* row = g_masks + (size_t)bk * NN;
    int tid = threadIdx.x;
    float s = 0.f;
    for (int i = tid; i < NN; i += 256) s += row[i];
#pragma unroll
    for (int o = 16; o; o >>= 1) s += __shfl_xor_sync(0xFFFFFFFFu, s, o);
    __shared__ float red[8];
    if ((tid & 31) == 0) red[tid >> 5] = s;
    __syncthreads();
    if (tid == 0) {
        float tot = 0.f;
#pragma unroll
        for (int w = 0; w < 8; w++) tot += red[w];
        g_invden[bk] = 1.f / (tot + (float)NN * EPSF + EPSF);
    }
}

// ---------------- updates partials: (mask+eps) @ v over 128-token chunks ----------------
__global__ __launch_bounds__(256) void k_updates() {
    int b = blockIdx.x, ch = blockIdx.y;
    int n0 = ch * 128;
    int tid = threadIdx.x;
    __shared__ float attw[KS][128];
#pragma unroll
    for (int t = 0; t < 4; t++) {
        int flat = tid + t * 256; int kk = flat >> 7; int j = flat & 127;
        attw[kk][j] = g_masks[((size_t)b * KS + kk) * NN + n0 + j] + EPSF;
    }
    __syncthreads();
    float acc[KS];
#pragma unroll
    for (int k = 0; k < KS; k++) acc[k] = 0.f;
    for (int j = 0; j < 128; j++) {
        float vj = g_kv[(size_t)(b * NN + n0 + j) * 512 + 256 + tid];
#pragma unroll
        for (int kk = 0; kk < KS; kk++) acc[kk] += attw[kk][j] * vj;
    }
#pragma unroll
    for (int kk = 0; kk < KS; kk++)
        g_upart[ch][(b * KS + kk) * DD + tid] = acc[kk];
}

// ---------------- reduce partials, apply invden ----------------
__global__ __launch_bounds__(256) void k_ureduce() {
    int row = blockIdx.x;          // 0..1023 = b*8+k
    int tid = threadIdx.x;
    float s = 0.f;
#pragma unroll
    for (int c = 0; c < 8; c++) s += g_upart[c][row * DD + tid];
    g_updates[row * DD + tid] = s * g_invden[row];
}

// ---------------- GRU gating + LN(slots) for MLP ----------------
__global__ __launch_bounds__(256) void k_gru_combine_ln(const float* __restrict__ lg,
                                                        const float* __restrict__ lb) {
    int row = blockIdx.x, c = threadIdx.x;
    const float* gt = g_gates + (size_t)row * 1024;
    float sp = g_slots[row * DD + c];
    float r = 1.f / (1.f + expf(-gt[c]));
    float z = 1.f / (1.f + expf(-gt[256 + c]));
    float n = tanhf(gt[512 + c] + r * gt[768 + c]);
    float sN = (1.f - z) * n + z * sp;
    g_slots[row * DD + c] = sN;
    float s1 = sN, s2 = sN * sN;
#pragma unroll
    for (int o = 16; o; o >>= 1) {
        s1 += __shfl_xor_sync(0xFFFFFFFFu, s1, o);
        s2 += __shfl_xor_sync(0xFFFFFFFFu, s2, o);
    }
    __shared__ float r1[8], r2[8];
    if ((c & 31) == 0) { r1[c >> 5] = s1; r2[c >> 5] = s2; }
    __syncthreads();
    float t1 = 0.f, t2 = 0.f;
#pragma unroll
    for (int w = 0; w < 8; w++) { t1 += r1[w]; t2 += r2[w]; }
    float mean = t1 * (1.f / DD);
    float inv  = rsqrtf(t2 * (1.f / DD) - mean * mean + LN_EPS);
    g_sln[row * DD + c] = (sN - mean) * inv * lg[c] + lb[c];
}

// ---------------- pack output ----------------
__global__ void k_out(float* __restrict__ out, int total) {
    for (int idx = blockIdx.x * blockDim.x + threadIdx.x; idx < total;
         idx += gridDim.x * blockDim.x) {
        out[idx] = (idx < BB * KS * DD) ? g_slots[idx] : g_masks[idx - BB * KS * DD];
    }
}

// ---------------- launch ----------------
extern "C" void kernel_launch(void* const* d_in, const int* in_sizes, int n_in,
                              void* d_out, int out_size) {
    const float* tokens     = (const float*)d_in[0];
    const float* init_slots = (const float*)d_in[1];
    const float* ln_in_g    = (const float*)d_in[2];
    const float* ln_in_b    = (const float*)d_in[3];
    const float* Wk         = (const float*)d_in[4];
    const float* bk         = (const float*)d_in[5];
    const float* Wv         = (const float*)d_in[6];
    const float* bv         = (const float*)d_in[7];
    const float* ln_s_g     = (const float*)d_in[8];
    const float* ln_s_b     = (const float*)d_in[9];
    const float* Wq         = (const float*)d_in[10];
    const float* bq         = (const float*)d_in[11];
    const float* W_ih       = (const float*)d_in[12];
    const float* b_ih       = (const float*)d_in[13];
    const float* W_hh       = (const float*)d_in[14];
    const float* b_hh       = (const float*)d_in[15];
    const float* ln_m_g     = (const float*)d_in[16];
    const float* ln_m_b     = (const float*)d_in[17];
    const float* W1         = (const float*)d_in[18];
    const float* b1         = (const float*)d_in[19];
    const float* W2         = (const float*)d_in[20];
    const float* b2         = (const float*)d_in[21];

    k_init_slots<<<BB * KS * DD / 256, 256>>>(init_slots);
    k_ln_tokens<<<BB * NN / 8, 256>>>(tokens, ln_in_g, ln_in_b);
    k_prep_gru<<<512 * 1024 / 256, 256>>>(W_ih, W_hh, b_ih, b_hh);
    gemm_k<0><<<dim3(8, 1024), 256>>>(Wk, Wv, bk, bv);

    for (int it = 0; it < 3; it++) {
        k_ln_slots<<<BB * KS, 256>>>(ln_s_g, ln_s_b);
        gemm_k<1><<<dim3(4, 16), 128>>>(Wq, nullptr, bq, nullptr);
        k_logits_softmax<<<dim3(NN / 32, BB), 256>>>();
        k_rowsum<<<BB * KS, 256>>>();
        k_updates<<<dim3(BB, 8), 256>>>();
        k_ureduce<<<BB * KS, 256>>>();
        gemm_k<2><<<dim3(16, 16), 128>>>(nullptr, nullptr, nullptr, nullptr);
        k_gru_combine_ln<<<BB * KS, 256>>>(ln_m_g, ln_m_b);
        gemm_k<3><<<dim3(16, 16), 128>>>(W1, nullptr, b1, nullptr);
        gemm_k<4><<<dim3(4, 16), 128>>>(W2, nullptr, b2, nullptr);
    }

    k_out<<<2560, 256>>>((float*)d_out, out_size);
}

// round 7
// speedup vs baseline: 2.6341x; 1.0051x over previous
#include <cuda_runtime.h>
#include <math.h>

#define BB 128
#define NN 1024
#define DD 256
#define KS 8
#define HID 1024
#define EPSF 1e-6f
#define LN_EPS 1e-6f
#define SCALE_QK 0.0625f

// ---------------- device scratch ----------------
__device__ float g_kv[(size_t)BB * NN * 512];  // [token][0:256]=k, [256:512]=v
__device__ float g_lnm[BB * NN];               // token LN mean
__device__ float g_lni[BB * NN];               // token LN rsqrt(var+eps)
__device__ float g_slots[BB * KS * DD];
__device__ float g_sln[BB * KS * DD];          // LN'd slots (GEMM A)
__device__ float g_q[BB * KS * DD];
__device__ float g_masks[BB * KS * NN];        // softmax masks (output #2)
__device__ float g_msum[BB * KS * 32];         // per-chunk mask partial sums
__device__ float g_upart[8][BB * KS * DD];
__device__ float g_updates[BB * KS * DD];
__device__ float g_gates[BB * KS * 1024];      // [rsum|zsum|inn|hn]
__device__ float g_hidden[BB * KS * HID];
__device__ float g_wgru[512 * 1024];           // padded GRU weight
__device__ float g_bgru[1024];

__device__ __forceinline__ float to_tf32(float x) {
    unsigned u;
    asm("cvt.rna.tf32.f32 %0, %1;" : "=r"(u) : "f"(x));
    return __uint_as_float(u);
}

__device__ __forceinline__ void mma_tf32(float* d, const unsigned* a, const unsigned* b) {
    asm volatile(
        "mma.sync.aligned.m16n8k8.row.col.f32.tf32.tf32.f32 "
        "{%0,%1,%2,%3}, {%4,%5,%6,%7}, {%8,%9}, {%0,%1,%2,%3};\n"
        : "+f"(d[0]), "+f"(d[1]), "+f"(d[2]), "+f"(d[3])
        : "r"(a[0]), "r"(a[1]), "r"(a[2]), "r"(a[3]), "r"(b[0]), "r"(b[1]));
}

// ---------------- init slots ----------------
__global__ void k_init_slots(const float* __restrict__ init_slots) {
    int i = blockIdx.x * 256 + threadIdx.x;
    g_slots[i] = init_slots[i];
}

// ---------------- token LN statistics only (mean, inv-std) ----------------
__global__ __launch_bounds__(256) void k_ln_stats(const float* __restrict__ t) {
    int row  = blockIdx.x * 8 + (threadIdx.x >> 5);
    int lane = threadIdx.x & 31;
    const float* p = t + (size_t)row * DD;
    float s = 0.f, s2 = 0.f;
#pragma unroll
    for (int i = 0; i < 8; i++) { float x = p[lane + i * 32]; s += x; s2 += x * x; }
#pragma unroll
    for (int o = 16; o; o >>= 1) {
        s  += __shfl_xor_sync(0xFFFFFFFFu, s,  o);
        s2 += __shfl_xor_sync(0xFFFFFFFFu, s2, o);
    }
    float mean = s * (1.f / DD);
    float inv  = rsqrtf(s2 * (1.f / DD) - mean * mean + LN_EPS);
    if (lane == 0) { g_lnm[row] = mean; g_lni[row] = inv; }
}

// ---------------- GRU weight/bias prep ----------------
__global__ void k_prep_gru(const float* __restrict__ Wih, const float* __restrict__ Whh,
                           const float* __restrict__ bih, const float* __restrict__ bhh) {
    int idx = blockIdx.x * 256 + threadIdx.x;      // over 512*1024
    int k = idx >> 10, c = idx & 1023;
    int grp = c >> 8, cc = c & 255;
    float v = 0.f;
    if (k < 256) {
        if (grp < 3) v = Wih[k * 768 + grp * 256 + cc];
    } else {
        int kk = k - 256;
        if (grp < 2)       v = Whh[kk * 768 + grp * 256 + cc];
        else if (grp == 3) v = Whh[kk * 768 + 512 + cc];
    }
    g_wgru[idx] = v;
    if (idx < 1024) {
        int g2 = idx >> 8, c2 = idx & 255;
        float bb;
        if (g2 < 2)       bb = bih[g2 * 256 + c2] + bhh[g2 * 256 + c2];
        else if (g2 == 2) bb = bih[512 + c2];
        else              bb = bhh[512 + c2];
        g_bgru[idx] = bb;
    }
}

// ---------------- KV GEMM with fused token-LN on A load ----------------
// C[131072, 512] = LN(tokens) @ [Wk|Wv] + [bk|bv], BM=BN=128, BK=16,
// 8 warps (2 along M x 4 along N), warp tile 64x32.
__global__ __launch_bounds__(256) void k_gemm_kv2(
    const float* __restrict__ tokens,
    const float* __restrict__ lng, const float* __restrict__ lnb,
    const float* __restrict__ Wk, const float* __restrict__ bk,
    const float* __restrict__ Wv, const float* __restrict__ bv) {
    __shared__ float As[2][128][20];
    __shared__ float Bs[2][16][136];

    int tid = threadIdx.x;
    int warp = tid >> 5, lane = tid & 31;
    int wm = warp & 1, wn = warp >> 1;          // wm: 0..1 (64 rows), wn: 0..3 (32 cols)
    int lr = lane >> 2, lc = lane & 3;
    int col0 = blockIdx.x * 128;
    int row0 = blockIdx.y * 128;

    const float* W; const float* bias; int wcol0;
    if (col0 < 256) { W = Wk; bias = bk; wcol0 = col0; }
    else            { W = Wv; bias = bv; wcol0 = col0 - 256; }

    // A loader: 2 threads per row, 8 cols each
    int ar  = tid >> 1;                 // 0..127
    int ac  = (tid & 1) * 8;            // 0 or 8
    float am = g_lnm[row0 + ar];
    float ai = g_lni[row0 + ar];
    const float* arow = tokens + (size_t)(row0 + ar) * DD;
    // B loader: 16 threads per row, 8 cols each
    int br  = tid >> 4;                 // 0..15
    int bc8 = (tid & 15) * 8;
    const float* wbase = W + wcol0 + bc8;

    float4 aR0, aR1, bR0, bR1;

    // ---- prologue: stage 0 (k0 = 0) ----
    {
        const float* ap = arow + ac;
        aR0 = *(const float4*)(ap);
        aR1 = *(const float4*)(ap + 4);
        const float* wp = wbase + (size_t)br * DD;
        bR0 = *(const float4*)(wp);
        bR1 = *(const float4*)(wp + 4);
    }
    {
        const float* gp = lng + ac; const float* bp = lnb + ac;
        float* dst = &As[0][ar][ac];
        dst[0] = to_tf32((aR0.x - am) * ai * gp[0] + bp[0]);
        dst[1] = to_tf32((aR0.y - am) * ai * gp[1] + bp[1]);
        dst[2] = to_tf32((aR0.z - am) * ai * gp[2] + bp[2]);
        dst[3] = to_tf32((aR0.w - am) * ai * gp[3] + bp[3]);
        dst[4] = to_tf32((aR1.x - am) * ai * gp[4] + bp[4]);
        dst[5] = to_tf32((aR1.y - am) * ai * gp[5] + bp[5]);
        dst[6] = to_tf32((aR1.z - am) * ai * gp[6] + bp[6]);
        dst[7] = to_tf32((aR1.w - am) * ai * gp[7] + bp[7]);
        float* bd = &Bs[0][br][bc8];
        bd[0] = to_tf32(bR0.x); bd[1] = to_tf32(bR0.y);
        bd[2] = to_tf32(bR0.z); bd[3] = to_tf32(bR0.w);
        bd[4] = to_tf32(bR1.x); bd[5] = to_tf32(bR1.y);
        bd[6] = to_tf32(bR1.z); bd[7] = to_tf32(bR1.w);
    }
    __syncthreads();

    float acc[4][4][4];
#pragma unroll
    for (int mt = 0; mt < 4; mt++)
#pragma unroll
        for (int nt = 0; nt < 4; nt++)
#pragma unroll
            for (int i = 0; i < 4; i++) acc[mt][nt][i] = 0.f;

    for (int s = 0; s < 16; s++) {
        if (s < 15) {
            int k0 = (s + 1) * 16;
            const float* ap = arow + k0 + ac;
            aR0 = *(const float4*)(ap);
            aR1 = *(const float4*)(ap + 4);
            const float* wp = wbase + (size_t)(k0 + br) * DD;
            bR0 = *(const float4*)(wp);
            bR1 = *(const float4*)(wp + 4);
        }
        int bf = s & 1;
#pragma unroll
        for (int ks = 0; ks < 2; ks++) {
            int kb = ks * 8;
            unsigned afr[4][4], bfr[4][2];
#pragma unroll
            for (int mt = 0; mt < 4; mt++) {
                int r = wm * 64 + mt * 16 + lr;
                afr[mt][0] = __float_as_uint(As[bf][r][kb + lc]);
                afr[mt][1] = __float_as_uint(As[bf][r + 8][kb + lc]);
                afr[mt][2] = __float_as_uint(As[bf][r][kb + lc + 4]);
                afr[mt][3] = __float_as_uint(As[bf][r + 8][kb + lc + 4]);
            }
#pragma unroll
            for (int nt = 0; nt < 4; nt++) {
                int cc = wn * 32 + nt * 8 + lr;
                bfr[nt][0] = __float_as_uint(Bs[bf][kb + lc][cc]);
                bfr[nt][1] = __float_as_uint(Bs[bf][kb + lc + 4][cc]);
            }
#pragma unroll
            for (int mt = 0; mt < 4; mt++)
#pragma unroll
                for (int nt = 0; nt < 4; nt++)
                    mma_tf32(acc[mt][nt], afr[mt], bfr[nt]);
        }
        if (s < 15) {
            int nb = (s + 1) & 1;
            int k0 = (s + 1) * 16;
            const float* gp = lng + k0 + ac; const float* bp = lnb + k0 + ac;
            float* dst = &As[nb][ar][ac];
            dst[0] = to_tf32((aR0.x - am) * ai * gp[0] + bp[0]);
            dst[1] = to_tf32((aR0.y - am) * ai * gp[1] + bp[1]);
            dst[2] = to_tf32((aR0.z - am) * ai * gp[2] + bp[2]);
            dst[3] = to_tf32((aR0.w - am) * ai * gp[3] + bp[3]);
            dst[4] = to_tf32((aR1.x - am) * ai * gp[4] + bp[4]);
            dst[5] = to_tf32((aR1.y - am) * ai * gp[5] + bp[5]);
            dst[6] = to_tf32((aR1.z - am) * ai * gp[6] + bp[6]);
            dst[7] = to_tf32((aR1.w - am) * ai * gp[7] + bp[7]);
            float* bd = &Bs[nb][br][bc8];
            bd[0] = to_tf32(bR0.x); bd[1] = to_tf32(bR0.y);
            bd[2] = to_tf32(bR0.z); bd[3] = to_tf32(bR0.w);
            bd[4] = to_tf32(bR1.x); bd[5] = to_tf32(bR1.y);
            bd[6] = to_tf32(bR1.z); bd[7] = to_tf32(bR1.w);
        }
        __syncthreads();
    }

    // ---- epilogue ----
#pragma unroll
    for (int mt = 0; mt < 4; mt++)
#pragma unroll
        for (int nt = 0; nt < 4; nt++) {
            int r  = row0 + wm * 64 + mt * 16 + lr;
            int cl = wn * 32 + nt * 8 + lc * 2;
            int wc = wcol0 + cl;
            float b0 = bias[wc], b1 = bias[wc + 1];
            size_t o0 = (size_t)r * 512 + col0 + cl;
            size_t o1 = (size_t)(r + 8) * 512 + col0 + cl;
            g_kv[o0]     = acc[mt][nt][0] + b0;
            g_kv[o0 + 1] = acc[mt][nt][1] + b1;
            g_kv[o1]     = acc[mt][nt][2] + b0;
            g_kv[o1 + 1] = acc[mt][nt][3] + b1;
        }
}

// ---------------- unified small tf32 GEMM (iteration chain) ----------------
// MODE 1: qprj C[1024,256]=g_sln@Wq+bq
// MODE 2: gru  C[1024,1024]=[g_updates|g_slots]@g_wgru+g_bgru (ASPLIT)
// MODE 3: mlp1 C[1024,1024]=gelu(g_sln@W1+b1) -> g_hidden
// MODE 4: mlp2 g_slots += g_hidden@W2+b2 (resid)
template<int MODE>
__global__ void gemm_k(const float* __restrict__ W, const float* __restrict__ bias_in) {
    constexpr int BM  = 64;
    constexpr int BN  = 64;
    constexpr int BK  = 16;
    constexpr int WGM = 2;
    constexpr int NT  = 128;
    constexpr int N   = (MODE == 2 || MODE == 3) ? 1024 : 256;
    constexpr int K   = (MODE == 2) ? 512 : (MODE == 4) ? 1024 : 256;
    constexpr int LDB = (MODE == 2 || MODE == 3) ? 1024 : 256;
    constexpr bool ASPLIT = (MODE == 2);
    constexpr int LDA_S = BK + 4;
    constexpr int LDB_S = BN + 8;

    __shared__ float As[2][BM][LDA_S];
    __shared__ float Bs[2][BK][LDB_S];

    const float* Ag  = (MODE == 2) ? g_updates : (MODE == 4) ? g_hidden : g_sln;
    const float* A2g = g_slots;
    const float* Bp  = (MODE == 2) ? g_wgru : W;
    const float* biasp = (MODE == 2) ? g_bgru : bias_in;
    float* C = (MODE == 1) ? g_q : (MODE == 2) ? g_gates
             : (MODE == 3) ? g_hidden : g_slots;

    int tid = threadIdx.x;
    int warp = tid >> 5, lane = tid & 31;
    int wm = warp % WGM, wn = warp / WGM;
    int row0 = blockIdx.y * BM;
    int col0 = blockIdx.x * BN;

    constexpr int A_PER = BM * BK / 4 / NT;   // 2
    constexpr int B_PER = BK * BN / 4 / NT;   // 2
    float4 aReg[A_PER], bReg[B_PER];

    int nstage = K / BK;

    {
#pragma unroll
        for (int l = 0; l < A_PER; l++) {
            int idx = tid + l * NT; int r = idx >> 2, c4 = (idx & 3) * 4;
            int lda = ASPLIT ? 256 : K;
            aReg[l] = *(const float4*)(Ag + (size_t)(row0 + r) * lda + c4);
        }
#pragma unroll
        for (int l = 0; l < B_PER; l++) {
            int idx = tid + l * NT; int r = idx / (BN / 4), c4 = (idx % (BN / 4)) * 4;
            bReg[l] = *(const float4*)(Bp + (size_t)r * LDB + col0 + c4);
        }
    }
#pragma unroll
    for (int l = 0; l < A_PER; l++) {
        int idx = tid + l * NT; int r = idx >> 2, c4 = (idx & 3) * 4;
        float4 t; t.x = to_tf32(aReg[l].x); t.y = to_tf32(aReg[l].y);
        t.z = to_tf32(aReg[l].z); t.w = to_tf32(aReg[l].w);
        *(float4*)&As[0][r][c4] = t;
    }
#pragma unroll
    for (int l = 0; l < B_PER; l++) {
        int idx = tid + l * NT; int r = idx / (BN / 4), c4 = (idx % (BN / 4)) * 4;
        float4 t; t.x = to_tf32(bReg[l].x); t.y = to_tf32(bReg[l].y);
        t.z = to_tf32(bReg[l].z); t.w = to_tf32(bReg[l].w);
        *(float4*)&Bs[0][r][c4] = t;
    }
    __syncthreads();

    float acc[2][4][4];
#pragma unroll
    for (int mt = 0; mt < 2; mt++)
#pragma unroll
        for (int nt = 0; nt < 4; nt++)
#pragma unroll
            for (int i = 0; i < 4; i++) acc[mt][nt][i] = 0.f;

    for (int s = 0; s < nstage; s++) {
        if (s + 1 < nstage) {
            int k0 = (s + 1) * BK;
            const float* Ab = Ag; int koff = k0;
            if (ASPLIT && k0 >= 256) { Ab = A2g; koff = k0 - 256; }
#pragma unroll
            for (int l = 0; l < A_PER; l++) {
                int idx = tid + l * NT; int r = idx >> 2, c4 = (idx & 3) * 4;
                int lda = ASPLIT ? 256 : K;
                aReg[l] = *(const float4*)(Ab + (size_t)(row0 + r) * lda + koff + c4);
            }
#pragma unroll
            for (int l = 0; l < B_PER; l++) {
                int idx = tid + l * NT; int r = idx / (BN / 4), c4 = (idx % (BN / 4)) * 4;
                bReg[l] = *(const float4*)(Bp + (size_t)(k0 + r) * LDB + col0 + c4);
            }
        }
        int bf = s & 1;
#pragma unroll
        for (int ks = 0; ks < 2; ks++) {
            int kb = ks * 8;
            unsigned afr[2][4], bfr[4][2];
            int lr = lane >> 2, lc = lane & 3;
#pragma unroll
            for (int mt = 0; mt < 2; mt++) {
                int r = wm * 32 + mt * 16 + lr;
                afr[mt][0] = __float_as_uint(As[bf][r][kb + lc]);
                afr[mt][1] = __float_as_uint(As[bf][r + 8][kb + lc]);
                afr[mt][2] = __float_as_uint(As[bf][r][kb + lc + 4]);
                afr[mt][3] = __float_as_uint(As[bf][r + 8][kb + lc + 4]);
            }
#pragma unroll
            for (int nt = 0; nt < 4; nt++) {
                int cc = wn * 32 + nt * 8 + lr;
                bfr[nt][0] = __float_as_uint(Bs[bf][kb + lc][cc]);
                bfr[nt][1] = __float_as_uint(Bs[bf][kb + lc + 4][cc]);
            }
#pragma unroll
            for (int mt = 0; mt < 2; mt++)
#pragma unroll
                for (int nt = 0; nt < 4; nt++)
                    mma_tf32(acc[mt][nt], afr[mt], bfr[nt]);
        }
        if (s + 1 < nstage) {
            int nb = (s + 1) & 1;
#pragma unroll
            for (int l = 0; l < A_PER; l++) {
                int idx = tid + l * NT; int r = idx >> 2, c4 = (idx & 3) * 4;
                float4 t; t.x = to_tf32(aReg[l].x); t.y = to_tf32(aReg[l].y);
                t.z = to_tf32(aReg[l].z); t.w = to_tf32(aReg[l].w);
                *(float4*)&As[nb][r][c4] = t;
            }
#pragma unroll
            for (int l = 0; l < B_PER; l++) {
                int idx = tid + l * NT; int r = idx / (BN / 4), c4 = (idx % (BN / 4)) * 4;
                float4 t; t.x = to_tf32(bReg[l].x); t.y = to_tf32(bReg[l].y);
                t.z = to_tf32(bReg[l].z); t.w = to_tf32(bReg[l].w);
                *(float4*)&Bs[nb][r][c4] = t;
            }
        }
        __syncthreads();
    }

    int lr = lane >> 2, lc = lane & 3;
#pragma unroll
    for (int mt = 0; mt < 2; mt++)
#pragma unroll
        for (int nt = 0; nt < 4; nt++) {
            int r = row0 + wm * 32 + mt * 16 + lr;
            int c = col0 + wn * 32 + nt * 8 + lc * 2;
            float b0 = biasp[c], b1 = biasp[c + 1];
            float v0 = acc[mt][nt][0] + b0, v1 = acc[mt][nt][1] + b1;
            float v2 = acc[mt][nt][2] + b0, v3 = acc[mt][nt][3] + b1;
            if (MODE == 3) {
                v0 = 0.5f * v0 * (1.f + erff(v0 * 0.70710678118654752f));
                v1 = 0.5f * v1 * (1.f + erff(v1 * 0.70710678118654752f));
                v2 = 0.5f * v2 * (1.f + erff(v2 * 0.70710678118654752f));
                v3 = 0.5f * v3 * (1.f + erff(v3 * 0.70710678118654752f));
            }
            if (MODE == 4) {
                v0 += g_slots[(size_t)r * N + c];       v1 += g_slots[(size_t)r * N + c + 1];
                v2 += g_slots[(size_t)(r + 8) * N + c]; v3 += g_slots[(size_t)(r + 8) * N + c + 1];
            }
            C[(size_t)r * N + c] = v0;       C[(size_t)r * N + c + 1] = v1;
            C[(size_t)(r + 8) * N + c] = v2; C[(size_t)(r + 8) * N + c + 1] = v3;
        }
}

// ---------------- LN of slots -> g_sln ----------------
__global__ __launch_bounds__(256) void k_ln_slots(const float* __restrict__ g,
                                                  const float* __restrict__ b) {
    int row = blockIdx.x, c = threadIdx.x;
    float x = g_slots[row * DD + c];
    float s1 = x, s2 = x * x;
#pragma unroll
    for (int o = 16; o; o >>= 1) {
        s1 += __shfl_xor_sync(0xFFFFFFFFu, s1, o);
        s2 += __shfl_xor_sync(0xFFFFFFFFu, s2, o);
    }
    __shared__ float r1[8], r2[8];
    if ((c & 31) == 0) { r1[c >> 5] = s1; r2[c >> 5] = s2; }
    __syncthreads();
    float t1 = 0.f, t2 = 0.f;
#pragma unroll
    for (int w = 0; w < 8; w++) { t1 += r1[w]; t2 += r2[w]; }
    float mean = t1 * (1.f / DD);
    float inv  = rsqrtf(t2 * (1.f / DD) - mean * mean + LN_EPS);
    g_sln[row * DD + c] = (x - mean) * inv * g[c] + b[c];
}

// ---------------- logits + softmax over slots + per-chunk mask sums ----------------
__global__ __launch_bounds__(256) void k_logits_softmax() {
    __shared__ float qs[256][8];
    __shared__ float ks[256][33];
    __shared__ float msm[8][33];
    int b  = blockIdx.y;
    int n0 = blockIdx.x * 32;
    int tid = threadIdx.x;
#pragma unroll
    for (int t = 0; t < 8; t++) {
        int flat = tid + t * 256; int s = flat >> 8; int i = flat & 255;
        qs[i][s] = g_q[((size_t)b * KS + s) * DD + i];
    }
#pragma unroll 4
    for (int t = 0; t < 32; t++) {
        int flat = tid + t * 256; int tok = flat >> 8; int i = flat & 255;
        ks[i][tok] = g_kv[(size_t)(b * NN + n0 + tok) * 512 + i];
    }
    __syncthreads();
    int tok = tid >> 3, s = tid & 7;
    float acc = 0.f;
#pragma unroll 4
    for (int i = 0; i < 256; i++) acc += qs[i][s] * ks[i][tok];
    acc *= SCALE_QK;
    float m = acc;
#pragma unroll
    for (int o = 1; o < 8; o <<= 1) m = fmaxf(m, __shfl_xor_sync(0xFFFFFFFFu, m, o));
    float e = expf(acc - m);
    float sum = e;
#pragma unroll
    for (int o = 1; o < 8; o <<= 1) sum += __shfl_xor_sync(0xFFFFFFFFu, sum, o);
    float mask = e / sum;
    g_masks[((size_t)b * KS + s) * NN + n0 + tok] = mask;
    msm[s][tok] = mask;
    __syncthreads();
    if (tid < 8) {
        float tot = 0.f;
#pragma unroll
        for (int j = 0; j < 32; j++) tot += msm[tid][j];
        g_msum[((size_t)b * KS + tid) * 32 + blockIdx.x] = tot;
    }
}

// ---------------- updates partials: (mask+eps) @ v over 128-token chunks ----------------
__global__ __launch_bounds__(256) void k_updates() {
    int b = blockIdx.x, ch = blockIdx.y;
    int n0 = ch * 128;
    int tid = threadIdx.x;
    __shared__ float attw[KS][128];
#pragma unroll
    for (int t = 0; t < 4; t++) {
        int flat = tid + t * 256; int kk = flat >> 7; int j = flat & 127;
        attw[kk][j] = g_masks[((size_t)b * KS + kk) * NN + n0 + j] + EPSF;
    }
    __syncthreads();
    float acc[KS];
#pragma unroll
    for (int k = 0; k < KS; k++) acc[k] = 0.f;
    for (int j = 0; j < 128; j++) {
        float vj = g_kv[(size_t)(b * NN + n0 + j) * 512 + 256 + tid];
#pragma unroll
        for (int kk = 0; kk < KS; kk++) acc[kk] += attw[kk][j] * vj;
    }
#pragma unroll
    for (int kk = 0; kk < KS; kk++)
        g_upart[ch][(b * KS + kk) * DD + tid] = acc[kk];
}

// ---------------- reduce partials; compute invden from chunk sums ----------------
__global__ __launch_bounds__(256) void k_ureduce() {
    int row = blockIdx.x;          // 0..1023 = b*8+k
    int tid = threadIdx.x;
    __shared__ float sden;
    if (tid < 32) {
        float p = g_msum[(size_t)row * 32 + tid];
#pragma unroll
        for (int o = 16; o; o >>= 1) p += __shfl_xor_sync(0xFFFFFFFFu, p, o);
        if (tid == 0) sden = 1.f / (p + (float)NN * EPSF + EPSF);
    }
    __syncthreads();
    float inv = sden;
    float s = 0.f;
#pragma unroll
    for (int c = 0; c < 8; c++) s += g_upart[c][row * DD + tid];
    g_updates[row * DD + tid] = s * inv;
}

// ---------------- GRU gating + LN(slots) for MLP ----------------
__global__ __launch_bounds__(256) void k_gru_combine_ln(const float* __restrict__ lg,
                                                        const float* __restrict__ lb) {
    int row = blockIdx.x, c = threadIdx.x;
    const float* gt = g_gates + (size_t)row * 1024;
    float sp = g_slots[row * DD + c];
    float r = 1.f / (1.f + expf(-gt[c]));
    float z = 1.f / (1.f + expf(-gt[256 + c]));
    float n = tanhf(gt[512 + c] + r * gt[768 + c]);
    float sN = (1.f - z) * n + z * sp;
    g_slots[row * DD + c] = sN;
    float s1 = sN, s2 = sN * sN;
#pragma unroll
    for (int o = 16; o; o >>= 1) {
        s1 += __shfl_xor_sync(0xFFFFFFFFu, s1, o);
        s2 += __shfl_xor_sync(0xFFFFFFFFu, s2, o);
    }
    __shared__ float r1[8], r2[8];
    if ((c & 31) == 0) { r1[c >> 5] = s1; r2[c >> 5] = s2; }
    __syncthreads();
    float t1 = 0.f, t2 = 0.f;
#pragma unroll
    for (int w = 0; w < 8; w++) { t1 += r1[w]; t2 += r2[w]; }
    float mean = t1 * (1.f / DD);
    float inv  = rsqrtf(t2 * (1.f / DD) - mean * mean + LN_EPS);
    g_sln[row * DD + c] = (sN - mean) * inv * lg[c] + lb[c];
}

// ---------------- pack output ----------------
__global__ void k_out(float* __restrict__ out, int total) {
    for (int idx = blockIdx.x * blockDim.x + threadIdx.x; idx < total;
         idx += gridDim.x * blockDim.x) {
        out[idx] = (idx < BB * KS * DD) ? g_slots[idx] : g_masks[idx - BB * KS * DD];
    }
}

// ---------------- launch ----------------
extern "C" void kernel_launch(void* const* d_in, const int* in_sizes, int n_in,
                              void* d_out, int out_size) {
    const float* tokens     = (const float*)d_in[0];
    const float* init_slots = (const float*)d_in[1];
    const float* ln_in_g    = (const float*)d_in[2];
    const float* ln_in_b    = (const float*)d_in[3];
    const float* Wk         = (const float*)d_in[4];
    const float* bk         = (const float*)d_in[5];
    const float* Wv         = (const float*)d_in[6];
    const float* bv         = (const float*)d_in[7];
    const float* ln_s_g     = (const float*)d_in[8];
    const float* ln_s_b     = (const float*)d_in[9];
    const float* Wq         = (const float*)d_in[10];
    const float* bq         = (const float*)d_in[11];
    const float* W_ih       = (const float*)d_in[12];
    const float* b_ih       = (const float*)d_in[13];
    const float* W_hh       = (const float*)d_in[14];
    const float* b_hh       = (const float*)d_in[15];
    const float* ln_m_g     = (const float*)d_in[16];
    const float* ln_m_b     = (const float*)d_in[17];
    const float* W1         = (const float*)d_in[18];
    const float* b1         = (const float*)d_in[19];
    const float* W2         = (const float*)d_in[20];
    const float* b2         = (const float*)d_in[21];

    k_init_slots<<<BB * KS * DD / 256, 256>>>(init_slots);
    k_ln_stats<<<BB * NN / 8, 256>>>(tokens);
    k_prep_gru<<<512 * 1024 / 256, 256>>>(W_ih, W_hh, b_ih, b_hh);
    k_gemm_kv2<<<dim3(4, 1024), 256>>>(tokens, ln_in_g, ln_in_b, Wk, bk, Wv, bv);

    for (int it = 0; it < 3; it++) {
        k_ln_slots<<<BB * KS, 256>>>(ln_s_g, ln_s_b);
        gemm_k<1><<<dim3(4, 16), 128>>>(Wq, bq);
        k_logits_softmax<<<dim3(NN / 32, BB), 256>>>();
        k_updates<<<dim3(BB, 8), 256>>>();
        k_ureduce<<<BB * KS, 256>>>();
        gemm_k<2><<<dim3(16, 16), 128>>>(nullptr, nullptr);
        k_gru_combine_ln<<<BB * KS, 256>>>(ln_m_g, ln_m_b);
        gemm_k<3><<<dim3(16, 16), 128>>>(W1, b1);
        gemm_k<4><<<dim3(4, 16), 128>>>(W2, b2);
    }

    k_out<<<2560, 256>>>((float*)d_out, out_size);
}

// round 9
// speedup vs baseline: 2.9548x; 1.1217x over previous
#include <cuda_runtime.h>
#include <cuda_fp16.h>
#include <math.h>

#define BB 128
#define NN 1024
#define DD 256
#define KS 8
#define HID 1024
#define EPSF 1e-6f
#define LN_EPS 1e-6f
#define SCALE_QK 0.0625f

// ---------------- device scratch ----------------
__device__ float g_kv[(size_t)BB * NN * 512];  // [token][0:256]=k, [256:512]=v
__device__ float g_lnm[BB * NN];               // token LN mean
__device__ float g_lni[BB * NN];               // token LN rsqrt(var+eps)
__device__ float g_slots[BB * KS * DD];
__device__ float g_sln[BB * KS * DD];          // LN'd slots (GEMM A)
__device__ float g_q[BB * KS * DD];
__device__ float g_masks[BB * KS * NN];        // softmax masks (output #2)
__device__ float g_msum[BB * KS * 32];         // per-chunk mask partial sums
__device__ float g_upart[8][BB * KS * DD];
__device__ float g_updates[BB * KS * DD];
__device__ float g_gates[BB * KS * 1024];      // [rsum|zsum|inn|hn]
__device__ float g_hidden[BB * KS * HID];
__device__ float g_wgru[512 * 1024];           // padded GRU weight
__device__ float g_bgru[1024];

// ---------------- fp16 MMA helpers (base sm_100 ISA) ----------------
__device__ __forceinline__ unsigned smem_u32(const void* p) {
    unsigned a;
    asm("{ .reg .u64 t; cvta.to.shared.u64 t, %1; cvt.u32.u64 %0, t; }" : "=r"(a) : "l"(p));
    return a;
}
__device__ __forceinline__ void ldsm_x4(unsigned* r, unsigned addr) {
    asm volatile("ldmatrix.sync.aligned.m8n8.x4.shared.b16 {%0,%1,%2,%3}, [%4];"
                 : "=r"(r[0]), "=r"(r[1]), "=r"(r[2]), "=r"(r[3]) : "r"(addr));
}
__device__ __forceinline__ void ldsm_x4_t(unsigned* r, unsigned addr) {
    asm volatile("ldmatrix.sync.aligned.m8n8.x4.trans.shared.b16 {%0,%1,%2,%3}, [%4];"
                 : "=r"(r[0]), "=r"(r[1]), "=r"(r[2]), "=r"(r[3]) : "r"(addr));
}
__device__ __forceinline__ void mma_f16(float* d, const unsigned* a, const unsigned* b) {
    asm volatile(
        "mma.sync.aligned.m16n8k16.row.col.f32.f16.f16.f32 "
        "{%0,%1,%2,%3}, {%4,%5,%6,%7}, {%8,%9}, {%0,%1,%2,%3};\n"
        : "+f"(d[0]), "+f"(d[1]), "+f"(d[2]), "+f"(d[3])
        : "r"(a[0]), "r"(a[1]), "r"(a[2]), "r"(a[3]), "r"(b[0]), "r"(b[1]));
}
// pack 8 floats -> 8 halves (uint4), memory order preserved
__device__ __forceinline__ uint4 pack8(const float* f) {
    __half2 h0 = __floats2half2_rn(f[0], f[1]);
    __half2 h1 = __floats2half2_rn(f[2], f[3]);
    __half2 h2 = __floats2half2_rn(f[4], f[5]);
    __half2 h3 = __floats2half2_rn(f[6], f[7]);
    uint4 u;
    u.x = *(unsigned*)&h0; u.y = *(unsigned*)&h1;
    u.z = *(unsigned*)&h2; u.w = *(unsigned*)&h3;
    return u;
}

// ---------------- init slots ----------------
__global__ void k_init_slots(const float* __restrict__ init_slots) {
    int i = blockIdx.x * 256 + threadIdx.x;
    g_slots[i] = init_slots[i];
}

// ---------------- token LN statistics only (mean, inv-std) ----------------
__global__ __launch_bounds__(256) void k_ln_stats(const float* __restrict__ t) {
    int row  = blockIdx.x * 8 + (threadIdx.x >> 5);
    int lane = threadIdx.x & 31;
    const float* p = t + (size_t)row * DD;
    float s = 0.f, s2 = 0.f;
#pragma unroll
    for (int i = 0; i < 8; i++) { float x = p[lane + i * 32]; s += x; s2 += x * x; }
#pragma unroll
    for (int o = 16; o; o >>= 1) {
        s  += __shfl_xor_sync(0xFFFFFFFFu, s,  o);
        s2 += __shfl_xor_sync(0xFFFFFFFFu, s2, o);
    }
    float mean = s * (1.f / DD);
    float inv  = rsqrtf(s2 * (1.f / DD) - mean * mean + LN_EPS);
    if (lane == 0) { g_lnm[row] = mean; g_lni[row] = inv; }
}

// ---------------- GRU weight/bias prep ----------------
__global__ void k_prep_gru(const float* __restrict__ Wih, const float* __restrict__ Whh,
                           const float* __restrict__ bih, const float* __restrict__ bhh) {
    int idx = blockIdx.x * 256 + threadIdx.x;      // over 512*1024
    int k = idx >> 10, c = idx & 1023;
    int grp = c >> 8, cc = c & 255;
    float v = 0.f;
    if (k < 256) {
        if (grp < 3) v = Wih[k * 768 + grp * 256 + cc];
    } else {
        int kk = k - 256;
        if (grp < 2)       v = Whh[kk * 768 + grp * 256 + cc];
        else if (grp == 3) v = Whh[kk * 768 + 512 + cc];
    }
    g_wgru[idx] = v;
    if (idx < 1024) {
        int g2 = idx >> 8, c2 = idx & 255;
        float bb;
        if (g2 < 2)       bb = bih[g2 * 256 + c2] + bhh[g2 * 256 + c2];
        else if (g2 == 2) bb = bih[512 + c2];
        else              bb = bhh[512 + c2];
        g_bgru[idx] = bb;
    }
}

// ================= fp16 KV GEMM with fused token-LN =================
// C[131072,512] = LN(tokens) @ [Wk|Wv] + bias.  BM=BN=128, BK=32 (halves).
// 8 warps (2 M x 4 N), warp tile 64x32, ldmatrix + mma.m16n8k16.
__global__ __launch_bounds__(256) void k_gemm_kv_h(
    const float* __restrict__ tokens,
    const float* __restrict__ lng, const float* __restrict__ lnb,
    const float* __restrict__ Wk, const float* __restrict__ bk,
    const float* __restrict__ Wv, const float* __restrict__ bv) {
    __shared__ __half sA[2][128 * 40];   // stride 40 halves (80B): ldmatrix conflict-free
    __shared__ __half sB[2][32 * 136];   // stride 136 halves (272B): conflict-free

    int tid = threadIdx.x;
    int warp = tid >> 5, lane = tid & 31;
    int wm = warp & 1, wn = warp >> 1;          // 2 x 4 warps; warp tile 64 x 32
    int lr = lane >> 2, lc = lane & 3;
    int col0 = blockIdx.x * 128;
    int row0 = blockIdx.y * 128;

    const float* W; const float* bias; int wcol0;
    if (col0 < 256) { W = Wk; bias = bk; wcol0 = col0; }
    else            { W = Wv; bias = bv; wcol0 = col0 - 256; }

    // A loader: 2 threads/row, 16 cols each
    int arow = tid >> 1, aseg = tid & 1;
    float am = g_lnm[row0 + arow];
    float ai = g_lni[row0 + arow];
    const float* ap0 = tokens + (size_t)(row0 + arow) * DD + aseg * 16;
    // B loader: 8 threads/row, 16 cols each
    int brow = tid >> 3, bseg = tid & 7;
    const float* wp0 = W + (size_t)brow * DD + wcol0 + bseg * 16;

    float fA[16], fB[16];

    auto fetch = [&](int k0) {
#pragma unroll
        for (int q = 0; q < 4; q++) {
            float4 x = *(const float4*)(ap0 + k0 + q * 4);
            fA[q * 4 + 0] = x.x; fA[q * 4 + 1] = x.y;
            fA[q * 4 + 2] = x.z; fA[q * 4 + 3] = x.w;
        }
        const float* wp = wp0 + (size_t)k0 * DD;
#pragma unroll
        for (int q = 0; q < 4; q++) {
            float4 x = *(const float4*)(wp + q * 4);
            fB[q * 4 + 0] = x.x; fB[q * 4 + 1] = x.y;
            fB[q * 4 + 2] = x.z; fB[q * 4 + 3] = x.w;
        }
    };
    auto stage = [&](int k0, int bf) {
#pragma unroll
        for (int j = 0; j < 16; j++) {
            int kg = k0 + aseg * 16 + j;
            fA[j] = (fA[j] - am) * ai * lng[kg] + lnb[kg];
        }
        uint4* dA = (uint4*)&sA[bf][arow * 40 + aseg * 16];
        dA[0] = pack8(fA); dA[1] = pack8(fA + 8);
        uint4* dB = (uint4*)&sB[bf][brow * 136 + bseg * 16];
        dB[0] = pack8(fB); dB[1] = pack8(fB + 8);
    };

    fetch(0);
    stage(0, 0);
    __syncthreads();

    float acc[4][4][4];
#pragma unroll
    for (int mt = 0; mt < 4; mt++)
#pragma unroll
        for (int nt = 0; nt < 4; nt++)
#pragma unroll
            for (int i = 0; i < 4; i++) acc[mt][nt][i] = 0.f;

    for (int s = 0; s < 8; s++) {
        if (s < 7) fetch((s + 1) * 32);
        int bf = s & 1;
        unsigned baseA = smem_u32(&sA[bf][0]);
        unsigned baseB = smem_u32(&sB[bf][0]);
#pragma unroll
        for (int ks = 0; ks < 2; ks++) {
            int kb = ks * 16;
            unsigned a[4][4], b[2][4];
#pragma unroll
            for (int mt = 0; mt < 4; mt++) {
                int r = wm * 64 + mt * 16 + (lane & 15);
                ldsm_x4(a[mt], baseA + (unsigned)(r * 40 + kb + (lane >> 4) * 8) * 2);
            }
#pragma unroll
            for (int p = 0; p < 2; p++) {
                int kr = kb + (lane & 7) + ((lane >> 3) & 1) * 8;
                int cn = wn * 32 + p * 16 + (lane >> 4) * 8;
                ldsm_x4_t(b[p], baseB + (unsigned)(kr * 136 + cn) * 2);
            }
#pragma unroll
            for (int mt = 0; mt < 4; mt++)
#pragma unroll
                for (int p = 0; p < 2; p++) {
                    mma_f16(acc[mt][2 * p],     a[mt], &b[p][0]);
                    mma_f16(acc[mt][2 * p + 1], a[mt], &b[p][2]);
                }
        }
        if (s < 7) stage((s + 1) * 32, (s + 1) & 1);
        __syncthreads();
    }

    // ---- epilogue ----
#pragma unroll
    for (int mt = 0; mt < 4; mt++)
#pragma unroll
        for (int nt = 0; nt < 4; nt++) {
            int r  = row0 + wm * 64 + mt * 16 + lr;
            int cl = wn * 32 + nt * 8 + lc * 2;
            int wc = wcol0 + cl;
            float b0 = bias[wc], b1 = bias[wc + 1];
            size_t o0 = (size_t)r * 512 + col0 + cl;
            size_t o1 = (size_t)(r + 8) * 512 + col0 + cl;
            g_kv[o0]     = acc[mt][nt][0] + b0;
            g_kv[o0 + 1] = acc[mt][nt][1] + b1;
            g_kv[o1]     = acc[mt][nt][2] + b0;
            g_kv[o1 + 1] = acc[mt][nt][3] + b1;
        }
}

// ================= unified small fp16 GEMM (iteration chain) =================
// MODE 1: qprj C[1024,256]=g_sln@Wq+bq
// MODE 2: gru  C[1024,1024]=[g_updates|g_slots]@g_wgru+g_bgru (ASPLIT)
// MODE 3: mlp1 C[1024,1024]=gelu(g_sln@W1+b1) -> g_hidden
// MODE 4: mlp2 g_slots += g_hidden@W2+b2 (resid)
// BM=BN=64, BK=32, 128 threads (4 warps 2x2), warp tile 32x32.
template<int MODE>
__global__ __launch_bounds__(128) void hgemm(const float* __restrict__ W,
                                             const float* __restrict__ bias_in) {
    constexpr int N   = (MODE == 2 || MODE == 3) ? 1024 : 256;
    constexpr int K   = (MODE == 2) ? 512 : (MODE == 4) ? 1024 : 256;
    constexpr int LDB = (MODE == 2 || MODE == 3) ? 1024 : 256;
    constexpr bool ASPLIT = (MODE == 2);
    constexpr int LDA = ASPLIT ? 256 : K;

    __shared__ __half sA[2][64 * 40];
    __shared__ __half sB[2][32 * 72];

    const float* Ag  = (MODE == 2) ? g_updates : (MODE == 4) ? g_hidden : g_sln;
    const float* Bp  = (MODE == 2) ? g_wgru : W;
    const float* biasp = (MODE == 2) ? g_bgru : bias_in;
    float* C = (MODE == 1) ? g_q : (MODE == 2) ? g_gates
             : (MODE == 3) ? g_hidden : g_slots;

    int tid = threadIdx.x;
    int warp = tid >> 5, lane = tid & 31;
    int wm = warp & 1, wn = warp >> 1;
    int lr = lane >> 2, lc = lane & 3;
    int row0 = blockIdx.y * 64;
    int col0 = blockIdx.x * 64;

    int arow = tid >> 1, aseg = tid & 1;      // 64 rows x 2
    int brow = tid >> 2, bseg = tid & 3;      // 32 rows x 4

    float fA[16], fB[16];

    auto fetch = [&](int k0) {
        const float* Ab = Ag; int koff = k0;
        if (ASPLIT && k0 >= 256) { Ab = g_slots; koff = k0 - 256; }
        const float* ap = Ab + (size_t)(row0 + arow) * LDA + koff + aseg * 16;
#pragma unroll
        for (int q = 0; q < 4; q++) {
            float4 x = *(const float4*)(ap + q * 4);
            fA[q * 4 + 0] = x.x; fA[q * 4 + 1] = x.y;
            fA[q * 4 + 2] = x.z; fA[q * 4 + 3] = x.w;
        }
        const float* bp = Bp + (size_t)(k0 + brow) * LDB + col0 + bseg * 16;
#pragma unroll
        for (int q = 0; q < 4; q++) {
            float4 x = *(const float4*)(bp + q * 4);
            fB[q * 4 + 0] = x.x; fB[q * 4 + 1] = x.y;
            fB[q * 4 + 2] = x.z; fB[q * 4 + 3] = x.w;
        }
    };
    auto stage = [&](int bf) {
        uint4* dA = (uint4*)&sA[bf][arow * 40 + aseg * 16];
        dA[0] = pack8(fA); dA[1] = pack8(fA + 8);
        uint4* dB = (uint4*)&sB[bf][brow * 72 + bseg * 16];
        dB[0] = pack8(fB); dB[1] = pack8(fB + 8);
    };

    fetch(0);
    stage(0);
    __syncthreads();

    float acc[2][4][4];
#pragma unroll
    for (int mt = 0; mt < 2; mt++)
#pragma unroll
        for (int nt = 0; nt < 4; nt++)
#pragma unroll
            for (int i = 0; i < 4; i++) acc[mt][nt][i] = 0.f;

    constexpr int NSTAGE = K / 32;
    for (int s = 0; s < NSTAGE; s++) {
        if (s + 1 < NSTAGE) fetch((s + 1) * 32);
        int bf = s & 1;
        unsigned baseA = smem_u32(&sA[bf][0]);
        unsigned baseB = smem_u32(&sB[bf][0]);
#pragma unroll
        for (int ks = 0; ks < 2; ks++) {
            int kb = ks * 16;
            unsigned a[2][4], b[2][4];
#pragma unroll
            for (int mt = 0; mt < 2; mt++) {
                int r = wm * 32 + mt * 16 + (lane & 15);
                ldsm_x4(a[mt], baseA + (unsigned)(r * 40 + kb + (lane >> 4) * 8) * 2);
            }
#pragma unroll
            for (int p = 0; p < 2; p++) {
                int kr = kb + (lane & 7) + ((lane >> 3) & 1) * 8;
                int cn = wn * 32 + p * 16 + (lane >> 4) * 8;
                ldsm_x4_t(b[p], baseB + (unsigned)(kr * 72 + cn) * 2);
            }
#pragma unroll
            for (int mt = 0; mt < 2; mt++)
#pragma unroll
                for (int p = 0; p < 2; p++) {
                    mma_f16(acc[mt][2 * p],     a[mt], &b[p][0]);
                    mma_f16(acc[mt][2 * p + 1], a[mt], &b[p][2]);
                }
        }
        if (s + 1 < NSTAGE) stage((s + 1) & 1);
        __syncthreads();
    }

#pragma unroll
    for (int mt = 0; mt < 2; mt++)
#pragma unroll
        for (int nt = 0; nt < 4; nt++) {
            int r = row0 + wm * 32 + mt * 16 + lr;
            int c = col0 + wn * 32 + nt * 8 + lc * 2;
            float b0 = biasp[c], b1 = biasp[c + 1];
            float v0 = acc[mt][nt][0] + b0, v1 = acc[mt][nt][1] + b1;
            float v2 = acc[mt][nt][2] + b0, v3 = acc[mt][nt][3] + b1;
            if (MODE == 3) {
                v0 = 0.5f * v0 * (1.f + erff(v0 * 0.70710678118654752f));
                v1 = 0.5f * v1 * (1.f + erff(v1 * 0.70710678118654752f));
                v2 = 0.5f * v2 * (1.f + erff(v2 * 0.70710678118654752f));
                v3 = 0.5f * v3 * (1.f + erff(v3 * 0.70710678118654752f));
            }
            if (MODE == 4) {
                v0 += g_slots[(size_t)r * N + c];       v1 += g_slots[(size_t)r * N + c + 1];
                v2 += g_slots[(size_t)(r + 8) * N + c]; v3 += g_slots[(size_t)(r + 8) * N + c + 1];
            }
            C[(size_t)r * N + c] = v0;       C[(size_t)r * N + c + 1] = v1;
            C[(size_t)(r + 8) * N + c] = v2; C[(size_t)(r + 8) * N + c + 1] = v3;
        }
}

// ---------------- LN of slots -> g_sln ----------------
__global__ __launch_bounds__(256) void k_ln_slots(const float* __restrict__ g,
                                                  const float* __restrict__ b) {
    int row = blockIdx.x, c = threadIdx.x;
    float x = g_slots[row * DD + c];
    float s1 = x, s2 = x * x;
#pragma unroll
    for (int o = 16; o; o >>= 1) {
        s1 += __shfl_xor_sync(0xFFFFFFFFu, s1, o);
        s2 += __shfl_xor_sync(0xFFFFFFFFu, s2, o);
    }
    __shared__ float r1[8], r2[8];
    if ((c & 31) == 0) { r1[c >> 5] = s1; r2[c >> 5] = s2; }
    __syncthreads();
    float t1 = 0.f, t2 = 0.f;
#pragma unroll
    for (int w = 0; w < 8; w++) { t1 += r1[w]; t2 += r2[w]; }
    float mean = t1 * (1.f / DD);
    float inv  = rsqrtf(t2 * (1.f / DD) - mean * mean + LN_EPS);
    g_sln[row * DD + c] = (x - mean) * inv * g[c] + b[c];
}

// ---------------- logits + softmax over slots + per-chunk mask sums ----------------
__global__ __launch_bounds__(256) void k_logits_softmax() {
    __shared__ float qs[256][8];
    __shared__ float ks[256][33];
    __shared__ float msm[8][33];
    int b  = blockIdx.y;
    int n0 = blockIdx.x * 32;
    int tid = threadIdx.x;
#pragma unroll
    for (int t = 0; t < 8; t++) {
        int flat = tid + t * 256; int s = flat >> 8; int i = flat & 255;
        qs[i][s] = g_q[((size_t)b * KS + s) * DD + i];
    }
#pragma unroll 4
    for (int t = 0; t < 32; t++) {
        int flat = tid + t * 256; int tok = flat >> 8; int i = flat & 255;
        ks[i][tok] = g_kv[(size_t)(b * NN + n0 + tok) * 512 + i];
    }
    __syncthreads();
    int tok = tid >> 3, s = tid & 7;
    float acc = 0.f;
#pragma unroll 4
    for (int i = 0; i < 256; i++) acc += qs[i][s] * ks[i][tok];
    acc *= SCALE_QK;
    float m = acc;
#pragma unroll
    for (int o = 1; o < 8; o <<= 1) m = fmaxf(m, __shfl_xor_sync(0xFFFFFFFFu, m, o));
    float e = expf(acc - m);
    float sum = e;
#pragma unroll
    for (int o = 1; o < 8; o <<= 1) sum += __shfl_xor_sync(0xFFFFFFFFu, sum, o);
    float mask = e / sum;
    g_masks[((size_t)b * KS + s) * NN + n0 + tok] = mask;
    msm[s][tok] = mask;
    __syncthreads();
    if (tid < 8) {
        float tot = 0.f;
#pragma unroll
        for (int j = 0; j < 32; j++) tot += msm[tid][j];
        g_msum[((size_t)b * KS + tid) * 32 + blockIdx.x] = tot;
    }
}

// ---------------- updates partials: (mask+eps) @ v over 128-token chunks ----------------
__global__ __launch_bounds__(256) void k_updates() {
    int b = blockIdx.x, ch = blockIdx.y;
    int n0 = ch * 128;
    int tid = threadIdx.x;
    __shared__ float attw[KS][128];
#pragma unroll
    for (int t = 0; t < 4; t++) {
        int flat = tid + t * 256; int kk = flat >> 7; int j = flat & 127;
        attw[kk][j] = g_masks[((size_t)b * KS + kk) * NN + n0 + j] + EPSF;
    }
    __syncthreads();
    float acc[KS];
#pragma unroll
    for (int k = 0; k < KS; k++) acc[k] = 0.f;
    for (int j = 0; j < 128; j++) {
        float vj = g_kv[(size_t)(b * NN + n0 + j) * 512 + 256 + tid];
#pragma unroll
        for (int kk = 0; kk < KS; kk++) acc[kk] += attw[kk][j] * vj;
    }
#pragma unroll
    for (int kk = 0; kk < KS; kk++)
        g_upart[ch][(b * KS + kk) * DD + tid] = acc[kk];
}

// ---------------- reduce partials; compute invden from chunk sums ----------------
__global__ __launch_bounds__(256) void k_ureduce() {
    int row = blockIdx.x;          // 0..1023 = b*8+k
    int tid = threadIdx.x;
    __shared__ float sden;
    if (tid < 32) {
        float p = g_msum[(size_t)row * 32 + tid];
#pragma unroll
        for (int o = 16; o; o >>= 1) p += __shfl_xor_sync(0xFFFFFFFFu, p, o);
        if (tid == 0) sden = 1.f / (p + (float)NN * EPSF + EPSF);
    }
    __syncthreads();
    float inv = sden;
    float s = 0.f;
#pragma unroll
    for (int c = 0; c < 8; c++) s += g_upart[c][row * DD + tid];
    g_updates[row * DD + tid] = s * inv;
}

// ---------------- GRU gating + LN(slots) for MLP ----------------
__global__ __launch_bounds__(256) void k_gru_combine_ln(const float* __restrict__ lg,
                                                        const float* __restrict__ lb) {
    int row = blockIdx.x, c = threadIdx.x;
    const float* gt = g_gates + (size_t)row * 1024;
    float sp = g_slots[row * DD + c];
    float r = 1.f / (1.f + expf(-gt[c]));
    float z = 1.f / (1.f + expf(-gt[256 + c]));
    float n = tanhf(gt[512 + c] + r * gt[768 + c]);
    float sN = (1.f - z) * n + z * sp;
    g_slots[row * DD + c] = sN;
    float s1 = sN, s2 = sN * sN;
#pragma unroll
    for (int o = 16; o; o >>= 1) {
        s1 += __shfl_xor_sync(0xFFFFFFFFu, s1, o);
        s2 += __shfl_xor_sync(0xFFFFFFFFu, s2, o);
    }
    __shared__ float r1[8], r2[8];
    if ((c & 31) == 0) { r1[c >> 5] = s1; r2[c >> 5] = s2; }
    __syncthreads();
    float t1 = 0.f, t2 = 0.f;
#pragma unroll
    for (int w = 0; w < 8; w++) { t1 += r1[w]; t2 += r2[w]; }
    float mean = t1 * (1.f / DD);
    float inv  = rsqrtf(t2 * (1.f / DD) - mean * mean + LN_EPS);
    g_sln[row * DD + c] = (sN - mean) * inv * lg[c] + lb[c];
}

// ---------------- pack output ----------------
__global__ void k_out(float* __restrict__ out, int total) {
    for (int idx = blockIdx.x * blockDim.x + threadIdx.x; idx < total;
         idx += gridDim.x * blockDim.x) {
        out[idx] = (idx < BB * KS * DD) ? g_slots[idx] : g_masks[idx - BB * KS * DD];
    }
}

// ---------------- launch ----------------
extern "C" void kernel_launch(void* const* d_in, const int* in_sizes, int n_in,
                              void* d_out, int out_size) {
    const float* tokens     = (const float*)d_in[0];
    const float* init_slots = (const float*)d_in[1];
    const float* ln_in_g    = (const float*)d_in[2];
    const float* ln_in_b    = (const float*)d_in[3];
    const float* Wk         = (const float*)d_in[4];
    const float* bk         = (const float*)d_in[5];
    const float* Wv         = (const float*)d_in[6];
    const float* bv         = (const float*)d_in[7];
    const float* ln_s_g     = (const float*)d_in[8];
    const float* ln_s_b     = (const float*)d_in[9];
    const float* Wq         = (const float*)d_in[10];
    const float* bq         = (const float*)d_in[11];
    const float* W_ih       = (const float*)d_in[12];
    const float* b_ih       = (const float*)d_in[13];
    const float* W_hh       = (const float*)d_in[14];
    const float* b_hh       = (const float*)d_in[15];
    const float* ln_m_g     = (const float*)d_in[16];
    const float* ln_m_b     = (const float*)d_in[17];
    const float* W1         = (const float*)d_in[18];
    const float* b1         = (const float*)d_in[19];
    const float* W2         = (const float*)d_in[20];
    const float* b2         = (const float*)d_in[21];

    k_init_slots<<<BB * KS * DD / 256, 256>>>(init_slots);
    k_ln_stats<<<BB * NN / 8, 256>>>(tokens);
    k_prep_gru<<<512 * 1024 / 256, 256>>>(W_ih, W_hh, b_ih, b_hh);
    k_gemm_kv_h<<<dim3(4, 1024), 256>>>(tokens, ln_in_g, ln_in_b, Wk, bk, Wv, bv);

    for (int it = 0; it < 3; it++) {
        k_ln_slots<<<BB * KS, 256>>>(ln_s_g, ln_s_b);
        hgemm<1><<<dim3(4, 16), 128>>>(Wq, bq);
        k_logits_softmax<<<dim3(NN / 32, BB), 256>>>();
        k_updates<<<dim3(BB, 8), 256>>>();
        k_ureduce<<<BB * KS, 256>>>();
        hgemm<2><<<dim3(16, 16), 128>>>(nullptr, nullptr);
        k_gru_combine_ln<<<BB * KS, 256>>>(ln_m_g, ln_m_b);
        hgemm<3><<<dim3(16, 16), 128>>>(W1, b1);
        hgemm<4><<<dim3(4, 16), 128>>>(W2, b2);
    }

    k_out<<<2560, 256>>>((float*)d_out, out_size);
}

// round 10
// speedup vs baseline: 3.7010x; 1.2525x over previous
#include <cuda_runtime.h>
#include <cuda_fp16.h>
#include <math.h>

#define BB 128
#define NN 1024
#define DD 256
#define KS 8
#define HID 1024
#define EPSF 1e-6f
#define LN_EPS 1e-6f
#define SCALE_QK 0.0625f

// ---------------- device scratch ----------------
__device__ float g_kv[(size_t)BB * NN * 512];  // [token][0:256]=k, [256:512]=v
__device__ __half g_xh[(size_t)BB * NN * DD];  // LN'd tokens, fp16
__device__ __half g_wh[256 * 512];             // [Wk|Wv] fp16, k-major
__device__ float g_slots[BB * KS * DD];
__device__ float g_sln[BB * KS * DD];          // LN'd slots (GEMM A)
__device__ float g_q[BB * KS * DD];
__device__ float g_masks[BB * KS * NN];        // softmax masks (output #2)
__device__ float g_msum[BB * KS * 32];         // per-chunk mask partial sums
__device__ float g_upart[8][BB * KS * DD];
__device__ float g_updates[BB * KS * DD];
__device__ float g_gates[BB * KS * 1024];      // [rsum|zsum|inn|hn]
__device__ float g_hidden[BB * KS * HID];
__device__ float g_wgru[512 * 1024];           // padded GRU weight
__device__ float g_bgru[1024];

// ---------------- fp16 MMA helpers (base sm_100 ISA) ----------------
__device__ __forceinline__ unsigned smem_u32(const void* p) {
    unsigned a;
    asm("{ .reg .u64 t; cvta.to.shared.u64 t, %1; cvt.u32.u64 %0, t; }" : "=r"(a) : "l"(p));
    return a;
}
__device__ __forceinline__ void ldsm_x4(unsigned* r, unsigned addr) {
    asm volatile("ldmatrix.sync.aligned.m8n8.x4.shared.b16 {%0,%1,%2,%3}, [%4];"
                 : "=r"(r[0]), "=r"(r[1]), "=r"(r[2]), "=r"(r[3]) : "r"(addr));
}
__device__ __forceinline__ void ldsm_x4_t(unsigned* r, unsigned addr) {
    asm volatile("ldmatrix.sync.aligned.m8n8.x4.trans.shared.b16 {%0,%1,%2,%3}, [%4];"
                 : "=r"(r[0]), "=r"(r[1]), "=r"(r[2]), "=r"(r[3]) : "r"(addr));
}
__device__ __forceinline__ void mma_f16(float* d, const unsigned* a, const unsigned* b) {
    asm volatile(
        "mma.sync.aligned.m16n8k16.row.col.f32.f16.f16.f32 "
        "{%0,%1,%2,%3}, {%4,%5,%6,%7}, {%8,%9}, {%0,%1,%2,%3};\n"
        : "+f"(d[0]), "+f"(d[1]), "+f"(d[2]), "+f"(d[3])
        : "r"(a[0]), "r"(a[1]), "r"(a[2]), "r"(a[3]), "r"(b[0]), "r"(b[1]));
}
__device__ __forceinline__ void cp_async16(unsigned dst, const void* src) {
    asm volatile("cp.async.cg.shared.global [%0], [%1], 16;" :: "r"(dst), "l"(src) : "memory");
}
#define CP_COMMIT() asm volatile("cp.async.commit_group;" ::: "memory")
#define CP_WAIT1()  asm volatile("cp.async.wait_group 1;" ::: "memory")
#define CP_WAIT0()  asm volatile("cp.async.wait_group 0;" ::: "memory")
// pack 8 floats -> 8 halves (uint4)
__device__ __forceinline__ uint4 pack8(const float* f) {
    __half2 h0 = __floats2half2_rn(f[0], f[1]);
    __half2 h1 = __floats2half2_rn(f[2], f[3]);
    __half2 h2 = __floats2half2_rn(f[4], f[5]);
    __half2 h3 = __floats2half2_rn(f[6], f[7]);
    uint4 u;
    u.x = *(unsigned*)&h0; u.y = *(unsigned*)&h1;
    u.z = *(unsigned*)&h2; u.w = *(unsigned*)&h3;
    return u;
}

// ---------------- init slots ----------------
__global__ void k_init_slots(const float* __restrict__ init_slots) {
    int i = blockIdx.x * 256 + threadIdx.x;
    g_slots[i] = init_slots[i];
}

// ---------------- token LN -> fp16 g_xh ----------------
__global__ __launch_bounds__(256) void k_ln_apply(const float* __restrict__ t,
                                                  const float* __restrict__ g,
                                                  const float* __restrict__ b) {
    int row  = blockIdx.x * 8 + (threadIdx.x >> 5);
    int lane = threadIdx.x & 31;
    const float* p = t + (size_t)row * DD;
    float vals[8]; float s = 0.f, s2 = 0.f;
#pragma unroll
    for (int i = 0; i < 8; i++) { float x = p[lane + i * 32]; vals[i] = x; s += x; s2 += x * x; }
#pragma unroll
    for (int o = 16; o; o >>= 1) {
        s  += __shfl_xor_sync(0xFFFFFFFFu, s,  o);
        s2 += __shfl_xor_sync(0xFFFFFFFFu, s2, o);
    }
    float mean = s * (1.f / DD);
    float inv  = rsqrtf(s2 * (1.f / DD) - mean * mean + LN_EPS);
#pragma unroll
    for (int i = 0; i < 8; i++) {
        int c = lane + i * 32;
        g_xh[(size_t)row * DD + c] = __float2half_rn((vals[i] - mean) * inv * g[c] + b[c]);
    }
}

// ---------------- pack [Wk|Wv] fp16 ----------------
__global__ void k_prep_wkv(const float* __restrict__ Wk, const float* __restrict__ Wv) {
    int idx = blockIdx.x * 256 + threadIdx.x;   // over 256*512
    int k = idx >> 9, c = idx & 511;
    float v = (c < 256) ? Wk[k * 256 + c] : Wv[k * 256 + (c - 256)];
    g_wh[idx] = __float2half_rn(v);
}

// ---------------- GRU weight/bias prep ----------------
__global__ void k_prep_gru(const float* __restrict__ Wih, const float* __restrict__ Whh,
                           const float* __restrict__ bih, const float* __restrict__ bhh) {
    int idx = blockIdx.x * 256 + threadIdx.x;      // over 512*1024
    int k = idx >> 10, c = idx & 1023;
    int grp = c >> 8, cc = c & 255;
    float v = 0.f;
    if (k < 256) {
        if (grp < 3) v = Wih[k * 768 + grp * 256 + cc];
    } else {
        int kk = k - 256;
        if (grp < 2)       v = Whh[kk * 768 + grp * 256 + cc];
        else if (grp == 3) v = Whh[kk * 768 + 512 + cc];
    }
    g_wgru[idx] = v;
    if (idx < 1024) {
        int g2 = idx >> 8, c2 = idx & 255;
        float bb;
        if (g2 < 2)       bb = bih[g2 * 256 + c2] + bhh[g2 * 256 + c2];
        else if (g2 == 2) bb = bih[512 + c2];
        else              bb = bhh[512 + c2];
        g_bgru[idx] = bb;
    }
}

// ================= fp16 KV GEMM (cp.async, prepacked operands) =================
// C[131072,512] = g_xh @ g_wh + bias.  BM=BN=128, BK=32 halves, 2-stage cp.async.
// 8 warps (2 M x 4 N), warp tile 64x32.
__global__ __launch_bounds__(256, 2) void k_gemm_kv_a(const float* __restrict__ bk,
                                                      const float* __restrict__ bv) {
    __shared__ __half sA[2][128 * 40];   // 80B row stride: ldmatrix conflict-free
    __shared__ __half sB[2][32 * 136];   // 272B row stride: conflict-free

    int tid = threadIdx.x;
    int warp = tid >> 5, lane = tid & 31;
    int wm = warp & 1, wn = warp >> 1;
    int lr = lane >> 2, lc = lane & 3;
    int col0 = blockIdx.x * 128;
    int row0 = blockIdx.y * 128;
    const float* bias = (col0 < 256) ? bk : bv;
    int wcol0 = (col0 < 256) ? col0 : col0 - 256;

    unsigned baseA0 = smem_u32(&sA[0][0]);
    unsigned baseB0 = smem_u32(&sB[0][0]);

    auto load_stage = [&](int k0, int bf) {
#pragma unroll
        for (int l = 0; l < 2; l++) {
            int task = tid + l * 256;          // 0..511
            int r = task >> 2, ch = task & 3;  // A: 128 rows x 4 chunks(8 halves)
            const __half* src = g_xh + (size_t)(row0 + r) * DD + k0 + ch * 8;
            cp_async16(baseA0 + (unsigned)(bf * 128 * 40 + r * 40 + ch * 8) * 2, src);
        }
#pragma unroll
        for (int l = 0; l < 2; l++) {
            int task = tid + l * 256;
            int r = task >> 4, ch = task & 15; // B: 32 k-rows x 16 chunks
            const __half* src = g_wh + (size_t)(k0 + r) * 512 + col0 + ch * 8;
            cp_async16(baseB0 + (unsigned)(bf * 32 * 136 + r * 136 + ch * 8) * 2, src);
        }
        CP_COMMIT();
    };

    load_stage(0, 0);

    float acc[4][4][4];
#pragma unroll
    for (int mt = 0; mt < 4; mt++)
#pragma unroll
        for (int nt = 0; nt < 4; nt++)
#pragma unroll
            for (int i = 0; i < 4; i++) acc[mt][nt][i] = 0.f;

    for (int s = 0; s < 8; s++) {
        if (s < 7) { load_stage((s + 1) * 32, (s + 1) & 1); CP_WAIT1(); }
        else       { CP_WAIT0(); }
        __syncthreads();
        int bf = s & 1;
        unsigned baseA = baseA0 + (unsigned)(bf * 128 * 40) * 2;
        unsigned baseB = baseB0 + (unsigned)(bf * 32 * 136) * 2;
#pragma unroll
        for (int ks = 0; ks < 2; ks++) {
            int kb = ks * 16;
            unsigned a[4][4], b[2][4];
#pragma unroll
            for (int mt = 0; mt < 4; mt++) {
                int r = wm * 64 + mt * 16 + (lane & 15);
                ldsm_x4(a[mt], baseA + (unsigned)(r * 40 + kb + (lane >> 4) * 8) * 2);
            }
#pragma unroll
            for (int p = 0; p < 2; p++) {
                int kr = kb + (lane & 7) + ((lane >> 3) & 1) * 8;
                int cn = wn * 32 + p * 16 + (lane >> 4) * 8;
                ldsm_x4_t(b[p], baseB + (unsigned)(kr * 136 + cn) * 2);
            }
#pragma unroll
            for (int mt = 0; mt < 4; mt++)
#pragma unroll
                for (int p = 0; p < 2; p++) {
                    mma_f16(acc[mt][2 * p],     a[mt], &b[p][0]);
                    mma_f16(acc[mt][2 * p + 1], a[mt], &b[p][2]);
                }
        }
        __syncthreads();
    }

    // ---- epilogue ----
#pragma unroll
    for (int mt = 0; mt < 4; mt++)
#pragma unroll
        for (int nt = 0; nt < 4; nt++) {
            int r  = row0 + wm * 64 + mt * 16 + lr;
            int cl = wn * 32 + nt * 8 + lc * 2;
            int wc = wcol0 + cl;
            float b0 = bias[wc], b1 = bias[wc + 1];
            size_t o0 = (size_t)r * 512 + col0 + cl;
            size_t o1 = (size_t)(r + 8) * 512 + col0 + cl;
            g_kv[o0]     = acc[mt][nt][0] + b0;
            g_kv[o0 + 1] = acc[mt][nt][1] + b1;
            g_kv[o1]     = acc[mt][nt][2] + b0;
            g_kv[o1 + 1] = acc[mt][nt][3] + b1;
        }
}

// ================= unified small fp16 GEMM (iteration chain) =================
// MODE 1: qprj C[1024,256]=g_sln@Wq+bq
// MODE 2: gru  C[1024,1024]=[g_updates|g_slots]@g_wgru+g_bgru (ASPLIT)
// MODE 3: mlp1 C[1024,1024]=gelu(g_sln@W1+b1) -> g_hidden
// MODE 4: mlp2 g_slots += g_hidden@W2+b2 (resid)
template<int MODE>
__global__ __launch_bounds__(128) void hgemm(const float* __restrict__ W,
                                             const float* __restrict__ bias_in) {
    constexpr int N   = (MODE == 2 || MODE == 3) ? 1024 : 256;
    constexpr int K   = (MODE == 2) ? 512 : (MODE == 4) ? 1024 : 256;
    constexpr int LDB = (MODE == 2 || MODE == 3) ? 1024 : 256;
    constexpr bool ASPLIT = (MODE == 2);
    constexpr int LDA = ASPLIT ? 256 : K;

    __shared__ __half sA[2][64 * 40];
    __shared__ __half sB[2][32 * 72];

    const float* Ag  = (MODE == 2) ? g_updates : (MODE == 4) ? g_hidden : g_sln;
    const float* Bp  = (MODE == 2) ? g_wgru : W;
    const float* biasp = (MODE == 2) ? g_bgru : bias_in;
    float* C = (MODE == 1) ? g_q : (MODE == 2) ? g_gates
             : (MODE == 3) ? g_hidden : g_slots;

    int tid = threadIdx.x;
    int warp = tid >> 5, lane = tid & 31;
    int wm = warp & 1, wn = warp >> 1;
    int lr = lane >> 2, lc = lane & 3;
    int row0 = blockIdx.y * 64;
    int col0 = blockIdx.x * 64;

    int arow = tid >> 1, aseg = tid & 1;
    int brow = tid >> 2, bseg = tid & 3;

    float fA[16], fB[16];

    auto fetch = [&](int k0) {
        const float* Ab = Ag; int koff = k0;
        if (ASPLIT && k0 >= 256) { Ab = g_slots; koff = k0 - 256; }
        const float* ap = Ab + (size_t)(row0 + arow) * LDA + koff + aseg * 16;
#pragma unroll
        for (int q = 0; q < 4; q++) {
            float4 x = *(const float4*)(ap + q * 4);
            fA[q * 4 + 0] = x.x; fA[q * 4 + 1] = x.y;
            fA[q * 4 + 2] = x.z; fA[q * 4 + 3] = x.w;
        }
        const float* bp = Bp + (size_t)(k0 + brow) * LDB + col0 + bseg * 16;
#pragma unroll
        for (int q = 0; q < 4; q++) {
            float4 x = *(const float4*)(bp + q * 4);
            fB[q * 4 + 0] = x.x; fB[q * 4 + 1] = x.y;
            fB[q * 4 + 2] = x.z; fB[q * 4 + 3] = x.w;
        }
    };
    auto stage = [&](int bf) {
        uint4* dA = (uint4*)&sA[bf][arow * 40 + aseg * 16];
        dA[0] = pack8(fA); dA[1] = pack8(fA + 8);
        uint4* dB = (uint4*)&sB[bf][brow * 72 + bseg * 16];
        dB[0] = pack8(fB); dB[1] = pack8(fB + 8);
    };

    fetch(0);
    stage(0);
    __syncthreads();

    float acc[2][4][4];
#pragma unroll
    for (int mt = 0; mt < 2; mt++)
#pragma unroll
        for (int nt = 0; nt < 4; nt++)
#pragma unroll
            for (int i = 0; i < 4; i++) acc[mt][nt][i] = 0.f;

    constexpr int NSTAGE = K / 32;
    for (int s = 0; s < NSTAGE; s++) {
        if (s + 1 < NSTAGE) fetch((s + 1) * 32);
        int bf = s & 1;
        unsigned baseA = smem_u32(&sA[bf][0]);
        unsigned baseB = smem_u32(&sB[bf][0]);
#pragma unroll
        for (int ks = 0; ks < 2; ks++) {
            int kb = ks * 16;
            unsigned a[2][4], b[2][4];
#pragma unroll
            for (int mt = 0; mt < 2; mt++) {
                int r = wm * 32 + mt * 16 + (lane & 15);
                ldsm_x4(a[mt], baseA + (unsigned)(r * 40 + kb + (lane >> 4) * 8) * 2);
            }
#pragma unroll
            for (int p = 0; p < 2; p++) {
                int kr = kb + (lane & 7) + ((lane >> 3) & 1) * 8;
                int cn = wn * 32 + p * 16 + (lane >> 4) * 8;
                ldsm_x4_t(b[p], baseB + (unsigned)(kr * 72 + cn) * 2);
            }
#pragma unroll
            for (int mt = 0; mt < 2; mt++)
#pragma unroll
                for (int p = 0; p < 2; p++) {
                    mma_f16(acc[mt][2 * p],     a[mt], &b[p][0]);
                    mma_f16(acc[mt][2 * p + 1], a[mt], &b[p][2]);
                }
        }
        if (s + 1 < NSTAGE) stage((s + 1) & 1);
        __syncthreads();
    }

#pragma unroll
    for (int mt = 0; mt < 2; mt++)
#pragma unroll
        for (int nt = 0; nt < 4; nt++) {
            int r = row0 + wm * 32 + mt * 16 + lr;
            int c = col0 + wn * 32 + nt * 8 + lc * 2;
            float b0 = biasp[c], b1 = biasp[c + 1];
            float v0 = acc[mt][nt][0] + b0, v1 = acc[mt][nt][1] + b1;
            float v2 = acc[mt][nt][2] + b0, v3 = acc[mt][nt][3] + b1;
            if (MODE == 3) {
                v0 = 0.5f * v0 * (1.f + erff(v0 * 0.70710678118654752f));
                v1 = 0.5f * v1 * (1.f + erff(v1 * 0.70710678118654752f));
                v2 = 0.5f * v2 * (1.f + erff(v2 * 0.70710678118654752f));
                v3 = 0.5f * v3 * (1.f + erff(v3 * 0.70710678118654752f));
            }
            if (MODE == 4) {
                v0 += g_slots[(size_t)r * N + c];       v1 += g_slots[(size_t)r * N + c + 1];
                v2 += g_slots[(size_t)(r + 8) * N + c]; v3 += g_slots[(size_t)(r + 8) * N + c + 1];
            }
            C[(size_t)r * N + c] = v0;       C[(size_t)r * N + c + 1] = v1;
            C[(size_t)(r + 8) * N + c] = v2; C[(size_t)(r + 8) * N + c + 1] = v3;
        }
}

// ---------------- LN of slots -> g_sln ----------------
__global__ __launch_bounds__(256) void k_ln_slots(const float* __restrict__ g,
                                                  const float* __restrict__ b) {
    int row = blockIdx.x, c = threadIdx.x;
    float x = g_slots[row * DD + c];
    float s1 = x, s2 = x * x;
#pragma unroll
    for (int o = 16; o; o >>= 1) {
        s1 += __shfl_xor_sync(0xFFFFFFFFu, s1, o);
        s2 += __shfl_xor_sync(0xFFFFFFFFu, s2, o);
    }
    __shared__ float r1[8], r2[8];
    if ((c & 31) == 0) { r1[c >> 5] = s1; r2[c >> 5] = s2; }
    __syncthreads();
    float t1 = 0.f, t2 = 0.f;
#pragma unroll
    for (int w = 0; w < 8; w++) { t1 += r1[w]; t2 += r2[w]; }
    float mean = t1 * (1.f / DD);
    float inv  = rsqrtf(t2 * (1.f / DD) - mean * mean + LN_EPS);
    g_sln[row * DD + c] = (x - mean) * inv * g[c] + b[c];
}

// ---------------- logits + softmax over slots + per-chunk mask sums ----------------
__global__ __launch_bounds__(256) void k_logits_softmax() {
    __shared__ float qs[256][8];
    __shared__ float ks[256][33];
    __shared__ float msm[8][33];
    int b  = blockIdx.y;
    int n0 = blockIdx.x * 32;
    int tid = threadIdx.x;
#pragma unroll
    for (int t = 0; t < 8; t++) {
        int flat = tid + t * 256; int s = flat >> 8; int i = flat & 255;
        qs[i][s] = g_q[((size_t)b * KS + s) * DD + i];
    }
#pragma unroll 4
    for (int t = 0; t < 32; t++) {
        int flat = tid + t * 256; int tok = flat >> 8; int i = flat & 255;
        ks[i][tok] = g_kv[(size_t)(b * NN + n0 + tok) * 512 + i];
    }
    __syncthreads();
    int tok = tid >> 3, s = tid & 7;
    float acc = 0.f;
#pragma unroll 4
    for (int i = 0; i < 256; i++) acc += qs[i][s] * ks[i][tok];
    acc *= SCALE_QK;
    float m = acc;
#pragma unroll
    for (int o = 1; o < 8; o <<= 1) m = fmaxf(m, __shfl_xor_sync(0xFFFFFFFFu, m, o));
    float e = expf(acc - m);
    float sum = e;
#pragma unroll
    for (int o = 1; o < 8; o <<= 1) sum += __shfl_xor_sync(0xFFFFFFFFu, sum, o);
    float mask = e / sum;
    g_masks[((size_t)b * KS + s) * NN + n0 + tok] = mask;
    msm[s][tok] = mask;
    __syncthreads();
    if (tid < 8) {
        float tot = 0.f;
#pragma unroll
        for (int j = 0; j < 32; j++) tot += msm[tid][j];
        g_msum[((size_t)b * KS + tid) * 32 + blockIdx.x] = tot;
    }
}

// ---------------- updates partials: (mask+eps) @ v over 128-token chunks ----------------
__global__ __launch_bounds__(256) void k_updates() {
    int b = blockIdx.x, ch = blockIdx.y;
    int n0 = ch * 128;
    int tid = threadIdx.x;
    __shared__ float attw[KS][128];
#pragma unroll
    for (int t = 0; t < 4; t++) {
        int flat = tid + t * 256; int kk = flat >> 7; int j = flat & 127;
        attw[kk][j] = g_masks[((size_t)b * KS + kk) * NN + n0 + j] + EPSF;
    }
    __syncthreads();
    float acc[KS];
#pragma unroll
    for (int k = 0; k < KS; k++) acc[k] = 0.f;
    for (int j = 0; j < 128; j++) {
        float vj = g_kv[(size_t)(b * NN + n0 + j) * 512 + 256 + tid];
#pragma unroll
        for (int kk = 0; kk < KS; kk++) acc[kk] += attw[kk][j] * vj;
    }
#pragma unroll
    for (int kk = 0; kk < KS; kk++)
        g_upart[ch][(b * KS + kk) * DD + tid] = acc[kk];
}

// ---------------- reduce partials; compute invden from chunk sums ----------------
__global__ __launch_bounds__(256) void k_ureduce() {
    int row = blockIdx.x;          // 0..1023 = b*8+k
    int tid = threadIdx.x;
    __shared__ float sden;
    if (tid < 32) {
        float p = g_msum[(size_t)row * 32 + tid];
#pragma unroll
        for (int o = 16; o; o >>= 1) p += __shfl_xor_sync(0xFFFFFFFFu, p, o);
        if (tid == 0) sden = 1.f / (p + (float)NN * EPSF + EPSF);
    }
    __syncthreads();
    float inv = sden;
    float s = 0.f;
#pragma unroll
    for (int c = 0; c < 8; c++) s += g_upart[c][row * DD + tid];
    g_updates[row * DD + tid] = s * inv;
}

// ---------------- GRU gating + LN(slots) for MLP ----------------
__global__ __launch_bounds__(256) void k_gru_combine_ln(const float* __restrict__ lg,
                                                        const float* __restrict__ lb) {
    int row = blockIdx.x, c = threadIdx.x;
    const float* gt = g_gates + (size_t)row * 1024;
    float sp = g_slots[row * DD + c];
    float r = 1.f / (1.f + expf(-gt[c]));
    float z = 1.f / (1.f + expf(-gt[256 + c]));
    float n = tanhf(gt[512 + c] + r * gt[768 + c]);
    float sN = (1.f - z) * n + z * sp;
    g_slots[row * DD + c] = sN;
    float s1 = sN, s2 = sN * sN;
#pragma unroll
    for (int o = 16; o; o >>= 1) {
        s1 += __shfl_xor_sync(0xFFFFFFFFu, s1, o);
        s2 += __shfl_xor_sync(0xFFFFFFFFu, s2, o);
    }
    __shared__ float r1[8], r2[8];
    if ((c & 31) == 0) { r1[c >> 5] = s1; r2[c >> 5] = s2; }
    __syncthreads();
    float t1 = 0.f, t2 = 0.f;
#pragma unroll
    for (int w = 0; w < 8; w++) { t1 += r1[w]; t2 += r2[w]; }
    float mean = t1 * (1.f / DD);
    float inv  = rsqrtf(t2 * (1.f / DD) - mean * mean + LN_EPS);
    g_sln[row * DD + c] = (sN - mean) * inv * lg[c] + lb[c];
}

// ---------------- pack output ----------------
__global__ void k_out(float* __restrict__ out, int total) {
    for (int idx = blockIdx.x * blockDim.x + threadIdx.x; idx < total;
         idx += gridDim.x * blockDim.x) {
        out[idx] = (idx < BB * KS * DD) ? g_slots[idx] : g_masks[idx - BB * KS * DD];
    }
}

// ---------------- launch ----------------
extern "C" void kernel_launch(void* const* d_in, const int* in_sizes, int n_in,
                              void* d_out, int out_size) {
    const float* tokens     = (const float*)d_in[0];
    const float* init_slots = (const float*)d_in[1];
    const float* ln_in_g    = (const float*)d_in[2];
    const float* ln_in_b    = (const float*)d_in[3];
    const float* Wk         = (const float*)d_in[4];
    const float* bk         = (const float*)d_in[5];
    const float* Wv         = (const float*)d_in[6];
    const float* bv         = (const float*)d_in[7];
    const float* ln_s_g     = (const float*)d_in[8];
    const float* ln_s_b     = (const float*)d_in[9];
    const float* Wq         = (const float*)d_in[10];
    const float* bq         = (const float*)d_in[11];
    const float* W_ih       = (const float*)d_in[12];
    const float* b_ih       = (const float*)d_in[13];
    const float* W_hh       = (const float*)d_in[14];
    const float* b_hh       = (const float*)d_in[15];
    const float* ln_m_g     = (const float*)d_in[16];
    const float* ln_m_b     = (const float*)d_in[17];
    const float* W1         = (const float*)d_in[18];
    const float* b1         = (const float*)d_in[19];
    const float* W2         = (const float*)d_in[20];
    const float* b2         = (const float*)d_in[21];

    k_init_slots<<<BB * KS * DD / 256, 256>>>(init_slots);
    k_ln_apply<<<BB * NN / 8, 256>>>(tokens, ln_in_g, ln_in_b);
    k_prep_wkv<<<256 * 512 / 256, 256>>>(Wk, Wv);
    k_prep_gru<<<512 * 1024 / 256, 256>>>(W_ih, W_hh, b_ih, b_hh);
    k_gemm_kv_a<<<dim3(4, 1024), 256>>>(bk, bv);

    for (int it = 0; it < 3; it++) {
        k_ln_slots<<<BB * KS, 256>>>(ln_s_g, ln_s_b);
        hgemm<1><<<dim3(4, 16), 128>>>(Wq, bq);
        k_logits_softmax<<<dim3(NN / 32, BB), 256>>>();
        k_updates<<<dim3(BB, 8), 256>>>();
        k_ureduce<<<BB * KS, 256>>>();
        hgemm<2><<<dim3(16, 16), 128>>>(nullptr, nullptr);
        k_gru_combine_ln<<<BB * KS, 256>>>(ln_m_g, ln_m_b);
        hgemm<3><<<dim3(16, 16), 128>>>(W1, b1);
        hgemm<4><<<dim3(4, 16), 128>>>(W2, b2);
    }

    k_out<<<2560, 256>>>((float*)d_out, out_size);
}

// round 11
// speedup vs baseline: 4.5007x; 1.2161x over previous
#include <cuda_runtime.h>
#include <cuda_fp16.h>
#include <math.h>

#define BB 128
#define NN 1024
#define DD 256
#define KS 8
#define HID 1024
#define EPSF 1e-6f
#define LN_EPS 1e-6f
#define SCALE_QK 0.0625f

// ---------------- device scratch ----------------
__device__ __half g_kvh[(size_t)BB * NN * 512]; // [token][0:256]=k fp16, [256:512]=v fp16
__device__ __half g_xh[(size_t)BB * NN * DD];   // LN'd tokens, fp16
__device__ __half g_wh[256 * 512];              // [Wk|Wv] fp16, k-major
__device__ float  g_slots[BB * KS * DD];
__device__ __half g_slotsh[BB * KS * DD];
__device__ __half g_slnh[BB * KS * DD];         // LN'd slots fp16
__device__ float  g_q[BB * KS * DD];
__device__ float  g_masks[BB * KS * NN];        // softmax masks (output #2)
__device__ float  g_msum[BB * KS * 32];
__device__ float  g_upart[8][BB * KS * DD];
__device__ __half g_updatesh[BB * KS * DD];
__device__ float  g_gates[BB * KS * 1024];      // [rsum|zsum|inn|hn]
__device__ __half g_hiddenh[BB * KS * HID];
__device__ __half g_wgruh[512 * 1024];          // padded GRU weight fp16
__device__ float  g_bgru[1024];
__device__ __half g_whq[256 * 256];
__device__ __half g_wh1[256 * 1024];
__device__ __half g_wh2[1024 * 256];

// ---------------- helpers ----------------
__device__ __forceinline__ unsigned smem_u32(const void* p) {
    unsigned a;
    asm("{ .reg .u64 t; cvta.to.shared.u64 t, %1; cvt.u32.u64 %0, t; }" : "=r"(a) : "l"(p));
    return a;
}
__device__ __forceinline__ void ldsm_x4(unsigned* r, unsigned addr) {
    asm volatile("ldmatrix.sync.aligned.m8n8.x4.shared.b16 {%0,%1,%2,%3}, [%4];"
                 : "=r"(r[0]), "=r"(r[1]), "=r"(r[2]), "=r"(r[3]) : "r"(addr));
}
__device__ __forceinline__ void ldsm_x4_t(unsigned* r, unsigned addr) {
    asm volatile("ldmatrix.sync.aligned.m8n8.x4.trans.shared.b16 {%0,%1,%2,%3}, [%4];"
                 : "=r"(r[0]), "=r"(r[1]), "=r"(r[2]), "=r"(r[3]) : "r"(addr));
}
__device__ __forceinline__ void mma_f16(float* d, const unsigned* a, const unsigned* b) {
    asm volatile(
        "mma.sync.aligned.m16n8k16.row.col.f32.f16.f16.f32 "
        "{%0,%1,%2,%3}, {%4,%5,%6,%7}, {%8,%9}, {%0,%1,%2,%3};\n"
        : "+f"(d[0]), "+f"(d[1]), "+f"(d[2]), "+f"(d[3])
        : "r"(a[0]), "r"(a[1]), "r"(a[2]), "r"(a[3]), "r"(b[0]), "r"(b[1]));
}
__device__ __forceinline__ void cp_async16(unsigned dst, const void* src) {
    asm volatile("cp.async.cg.shared.global [%0], [%1], 16;" :: "r"(dst), "l"(src) : "memory");
}
#define CP_COMMIT() asm volatile("cp.async.commit_group;" ::: "memory")
#define CP_WAIT1()  asm volatile("cp.async.wait_group 1;" ::: "memory")
#define CP_WAIT0()  asm volatile("cp.async.wait_group 0;" ::: "memory")

// ---------------- init slots ----------------
__global__ void k_init_slots(const float* __restrict__ init_slots) {
    int i = blockIdx.x * 256 + threadIdx.x;
    float v = init_slots[i];
    g_slots[i] = v;
    g_slotsh[i] = __float2half_rn(v);
}

// ---------------- generic fp32 -> fp16 pack ----------------
__global__ void k_pack(const float* __restrict__ s, __half* __restrict__ d, int n) {
    int i = blockIdx.x * 256 + threadIdx.x;
    if (i < n) d[i] = __float2half_rn(s[i]);
}

// ---------------- token LN -> fp16 g_xh ----------------
__global__ __launch_bounds__(256) void k_ln_apply(const float* __restrict__ t,
                                                  const float* __restrict__ g,
                                                  const float* __restrict__ b) {
    int row  = blockIdx.x * 8 + (threadIdx.x >> 5);
    int lane = threadIdx.x & 31;
    const float* p = t + (size_t)row * DD;
    float vals[8]; float s = 0.f, s2 = 0.f;
#pragma unroll
    for (int i = 0; i < 8; i++) { float x = p[lane + i * 32]; vals[i] = x; s += x; s2 += x * x; }
#pragma unroll
    for (int o = 16; o; o >>= 1) {
        s  += __shfl_xor_sync(0xFFFFFFFFu, s,  o);
        s2 += __shfl_xor_sync(0xFFFFFFFFu, s2, o);
    }
    float mean = s * (1.f / DD);
    float inv  = rsqrtf(s2 * (1.f / DD) - mean * mean + LN_EPS);
#pragma unroll
    for (int i = 0; i < 8; i++) {
        int c = lane + i * 32;
        g_xh[(size_t)row * DD + c] = __float2half_rn((vals[i] - mean) * inv * g[c] + b[c]);
    }
}

// ---------------- pack [Wk|Wv] fp16 ----------------
__global__ void k_prep_wkv(const float* __restrict__ Wk, const float* __restrict__ Wv) {
    int idx = blockIdx.x * 256 + threadIdx.x;   // over 256*512
    int k = idx >> 9, c = idx & 511;
    float v = (c < 256) ? Wk[k * 256 + c] : Wv[k * 256 + (c - 256)];
    g_wh[idx] = __float2half_rn(v);
}

// ---------------- GRU weight/bias prep (fp16 weight) ----------------
__global__ void k_prep_gru(const float* __restrict__ Wih, const float* __restrict__ Whh,
                           const float* __restrict__ bih, const float* __restrict__ bhh) {
    int idx = blockIdx.x * 256 + threadIdx.x;      // over 512*1024
    int k = idx >> 10, c = idx & 1023;
    int grp = c >> 8, cc = c & 255;
    float v = 0.f;
    if (k < 256) {
        if (grp < 3) v = Wih[k * 768 + grp * 256 + cc];
    } else {
        int kk = k - 256;
        if (grp < 2)       v = Whh[kk * 768 + grp * 256 + cc];
        else if (grp == 3) v = Whh[kk * 768 + 512 + cc];
    }
    g_wgruh[idx] = __float2half_rn(v);
    if (idx < 1024) {
        int g2 = idx >> 8, c2 = idx & 255;
        float bb;
        if (g2 < 2)       bb = bih[g2 * 256 + c2] + bhh[g2 * 256 + c2];
        else if (g2 == 2) bb = bih[512 + c2];
        else              bb = bhh[512 + c2];
        g_bgru[idx] = bb;
    }
}

// ================= fp16 KV GEMM (cp.async) -> g_kvh =================
__global__ __launch_bounds__(256, 2) void k_gemm_kv_a(const float* __restrict__ bk,
                                                      const float* __restrict__ bv) {
    __shared__ __half sA[2][128 * 40];
    __shared__ __half sB[2][32 * 136];

    int tid = threadIdx.x;
    int warp = tid >> 5, lane = tid & 31;
    int wm = warp & 1, wn = warp >> 1;
    int lr = lane >> 2, lc = lane & 3;
    int col0 = blockIdx.x * 128;
    int row0 = blockIdx.y * 128;
    const float* bias = (col0 < 256) ? bk : bv;
    int wcol0 = (col0 < 256) ? col0 : col0 - 256;

    unsigned baseA0 = smem_u32(&sA[0][0]);
    unsigned baseB0 = smem_u32(&sB[0][0]);

    auto load_stage = [&](int k0, int bf) {
#pragma unroll
        for (int l = 0; l < 2; l++) {
            int task = tid + l * 256;
            int r = task >> 2, ch = task & 3;
            const __half* src = g_xh + (size_t)(row0 + r) * DD + k0 + ch * 8;
            cp_async16(baseA0 + (unsigned)(bf * 128 * 40 + r * 40 + ch * 8) * 2, src);
        }
#pragma unroll
        for (int l = 0; l < 2; l++) {
            int task = tid + l * 256;
            int r = task >> 4, ch = task & 15;
            const __half* src = g_wh + (size_t)(k0 + r) * 512 + col0 + ch * 8;
            cp_async16(baseB0 + (unsigned)(bf * 32 * 136 + r * 136 + ch * 8) * 2, src);
        }
        CP_COMMIT();
    };

    load_stage(0, 0);

    float acc[4][4][4];
#pragma unroll
    for (int mt = 0; mt < 4; mt++)
#pragma unroll
        for (int nt = 0; nt < 4; nt++)
#pragma unroll
            for (int i = 0; i < 4; i++) acc[mt][nt][i] = 0.f;

    for (int s = 0; s < 8; s++) {
        if (s < 7) { load_stage((s + 1) * 32, (s + 1) & 1); CP_WAIT1(); }
        else       { CP_WAIT0(); }
        __syncthreads();
        int bf = s & 1;
        unsigned baseA = baseA0 + (unsigned)(bf * 128 * 40) * 2;
        unsigned baseB = baseB0 + (unsigned)(bf * 32 * 136) * 2;
#pragma unroll
        for (int ks = 0; ks < 2; ks++) {
            int kb = ks * 16;
            unsigned a[4][4], b[2][4];
#pragma unroll
            for (int mt = 0; mt < 4; mt++) {
                int r = wm * 64 + mt * 16 + (lane & 15);
                ldsm_x4(a[mt], baseA + (unsigned)(r * 40 + kb + (lane >> 4) * 8) * 2);
            }
#pragma unroll
            for (int p = 0; p < 2; p++) {
                int kr = kb + (lane & 7) + ((lane >> 3) & 1) * 8;
                int cn = wn * 32 + p * 16 + (lane >> 4) * 8;
                ldsm_x4_t(b[p], baseB + (unsigned)(kr * 136 + cn) * 2);
            }
#pragma unroll
            for (int mt = 0; mt < 4; mt++)
#pragma unroll
                for (int p = 0; p < 2; p++) {
                    mma_f16(acc[mt][2 * p],     a[mt], &b[p][0]);
                    mma_f16(acc[mt][2 * p + 1], a[mt], &b[p][2]);
                }
        }
        __syncthreads();
    }

    // ---- epilogue: fp16 output ----
#pragma unroll
    for (int mt = 0; mt < 4; mt++)
#pragma unroll
        for (int nt = 0; nt < 4; nt++) {
            int r  = row0 + wm * 64 + mt * 16 + lr;
            int cl = wn * 32 + nt * 8 + lc * 2;
            int wc = wcol0 + cl;
            float b0 = bias[wc], b1 = bias[wc + 1];
            size_t o0 = (size_t)r * 512 + col0 + cl;
            size_t o1 = (size_t)(r + 8) * 512 + col0 + cl;
            *(__half2*)(g_kvh + o0) = __floats2half2_rn(acc[mt][nt][0] + b0, acc[mt][nt][1] + b1);
            *(__half2*)(g_kvh + o1) = __floats2half2_rn(acc[mt][nt][2] + b0, acc[mt][nt][3] + b1);
        }
}

// ================= unified small fp16 GEMM (cp.async, prepacked) =================
// MODE 1: qprj C[1024,256]=g_slnh@g_whq+bq (fp32 out g_q)
// MODE 2: gru  C[1024,1024]=[g_updatesh|g_slotsh]@g_wgruh+g_bgru -> g_gates fp32
// MODE 3: mlp1 gelu(g_slnh@g_wh1+b1) -> g_hiddenh fp16
// MODE 4: mlp2 g_slots += g_hiddenh@g_wh2+b2 -> g_slots fp32 + g_slotsh fp16
template<int MODE>
__global__ __launch_bounds__(128) void hgemm(const float* __restrict__ bias_in) {
    constexpr int N   = (MODE == 2 || MODE == 3) ? 1024 : 256;
    constexpr int K   = (MODE == 2) ? 512 : (MODE == 4) ? 1024 : 256;
    constexpr int LDB = (MODE == 2 || MODE == 3) ? 1024 : 256;
    constexpr int LDA = (MODE == 4) ? 1024 : 256;

    __shared__ __half sA[2][64 * 40];
    __shared__ __half sB[2][32 * 72];

    const __half* Abase = (MODE == 2) ? g_updatesh : (MODE == 4) ? g_hiddenh : g_slnh;
    const __half* Bh    = (MODE == 1) ? g_whq : (MODE == 2) ? g_wgruh
                        : (MODE == 3) ? g_wh1 : g_wh2;
    const float* biasp  = (MODE == 2) ? g_bgru : bias_in;

    int tid = threadIdx.x;
    int warp = tid >> 5, lane = tid & 31;
    int wm = warp & 1, wn = warp >> 1;
    int lr = lane >> 2, lc = lane & 3;
    int row0 = blockIdx.y * 64;
    int col0 = blockIdx.x * 64;

    unsigned baseA0 = smem_u32(&sA[0][0]);
    unsigned baseB0 = smem_u32(&sB[0][0]);

    auto load_stage = [&](int k0, int bf) {
        const __half* Ah = Abase; int koff = k0;
        if (MODE == 2 && k0 >= 256) { Ah = g_slotsh; koff = k0 - 256; }
#pragma unroll
        for (int l = 0; l < 2; l++) {
            int task = tid + l * 128;          // 0..255
            int r = task >> 2, ch = task & 3;  // 64 rows x 4 chunks
            cp_async16(baseA0 + (unsigned)(bf * 64 * 40 + r * 40 + ch * 8) * 2,
                       Ah + (size_t)(row0 + r) * LDA + koff + ch * 8);
        }
#pragma unroll
        for (int l = 0; l < 2; l++) {
            int task = tid + l * 128;
            int r = task >> 3, ch = task & 7;  // 32 k-rows x 8 chunks
            cp_async16(baseB0 + (unsigned)(bf * 32 * 72 + r * 72 + ch * 8) * 2,
                       Bh + (size_t)(k0 + r) * LDB + col0 + ch * 8);
        }
        CP_COMMIT();
    };

    load_stage(0, 0);

    float acc[2][4][4];
#pragma unroll
    for (int mt = 0; mt < 2; mt++)
#pragma unroll
        for (int nt = 0; nt < 4; nt++)
#pragma unroll
            for (int i = 0; i < 4; i++) acc[mt][nt][i] = 0.f;

    constexpr int NSTAGE = K / 32;
    for (int s = 0; s < NSTAGE; s++) {
        if (s + 1 < NSTAGE) { load_stage((s + 1) * 32, (s + 1) & 1); CP_WAIT1(); }
        else                { CP_WAIT0(); }
        __syncthreads();
        int bf = s & 1;
        unsigned baseA = baseA0 + (unsigned)(bf * 64 * 40) * 2;
        unsigned baseB = baseB0 + (unsigned)(bf * 32 * 72) * 2;
#pragma unroll
        for (int ks = 0; ks < 2; ks++) {
            int kb = ks * 16;
            unsigned a[2][4], b[2][4];
#pragma unroll
            for (int mt = 0; mt < 2; mt++) {
                int r = wm * 32 + mt * 16 + (lane & 15);
                ldsm_x4(a[mt], baseA + (unsigned)(r * 40 + kb + (lane >> 4) * 8) * 2);
            }
#pragma unroll
            for (int p = 0; p < 2; p++) {
                int kr = kb + (lane & 7) + ((lane >> 3) & 1) * 8;
                int cn = wn * 32 + p * 16 + (lane >> 4) * 8;
                ldsm_x4_t(b[p], baseB + (unsigned)(kr * 72 + cn) * 2);
            }
#pragma unroll
            for (int mt = 0; mt < 2; mt++)
#pragma unroll
                for (int p = 0; p < 2; p++) {
                    mma_f16(acc[mt][2 * p],     a[mt], &b[p][0]);
                    mma_f16(acc[mt][2 * p + 1], a[mt], &b[p][2]);
                }
        }
        __syncthreads();
    }

#pragma unroll
    for (int mt = 0; mt < 2; mt++)
#pragma unroll
        for (int nt = 0; nt < 4; nt++) {
            int r = row0 + wm * 32 + mt * 16 + lr;
            int c = col0 + wn * 32 + nt * 8 + lc * 2;
            float b0 = biasp[c], b1 = biasp[c + 1];
            float v0 = acc[mt][nt][0] + b0, v1 = acc[mt][nt][1] + b1;
            float v2 = acc[mt][nt][2] + b0, v3 = acc[mt][nt][3] + b1;
            if (MODE == 3) {
                v0 = 0.5f * v0 * (1.f + erff(v0 * 0.70710678118654752f));
                v1 = 0.5f * v1 * (1.f + erff(v1 * 0.70710678118654752f));
                v2 = 0.5f * v2 * (1.f + erff(v2 * 0.70710678118654752f));
                v3 = 0.5f * v3 * (1.f + erff(v3 * 0.70710678118654752f));
                *(__half2*)(g_hiddenh + (size_t)r * N + c)       = __floats2half2_rn(v0, v1);
                *(__half2*)(g_hiddenh + (size_t)(r + 8) * N + c) = __floats2half2_rn(v2, v3);
            } else if (MODE == 4) {
                v0 += g_slots[(size_t)r * N + c];       v1 += g_slots[(size_t)r * N + c + 1];
                v2 += g_slots[(size_t)(r + 8) * N + c]; v3 += g_slots[(size_t)(r + 8) * N + c + 1];
                g_slots[(size_t)r * N + c] = v0;        g_slots[(size_t)r * N + c + 1] = v1;
                g_slots[(size_t)(r + 8) * N + c] = v2;  g_slots[(size_t)(r + 8) * N + c + 1] = v3;
                *(__half2*)(g_slotsh + (size_t)r * N + c)       = __floats2half2_rn(v0, v1);
                *(__half2*)(g_slotsh + (size_t)(r + 8) * N + c) = __floats2half2_rn(v2, v3);
            } else {
                float* C = (MODE == 1) ? g_q : g_gates;
                C[(size_t)r * N + c] = v0;       C[(size_t)r * N + c + 1] = v1;
                C[(size_t)(r + 8) * N + c] = v2; C[(size_t)(r + 8) * N + c + 1] = v3;
            }
        }
}

// ---------------- LN of slots -> g_slnh ----------------
__global__ __launch_bounds__(256) void k_ln_slots(const float* __restrict__ g,
                                                  const float* __restrict__ b) {
    int row = blockIdx.x, c = threadIdx.x;
    float x = g_slots[row * DD + c];
    float s1 = x, s2 = x * x;
#pragma unroll
    for (int o = 16; o; o >>= 1) {
        s1 += __shfl_xor_sync(0xFFFFFFFFu, s1, o);
        s2 += __shfl_xor_sync(0xFFFFFFFFu, s2, o);
    }
    __shared__ float r1[8], r2[8];
    if ((c & 31) == 0) { r1[c >> 5] = s1; r2[c >> 5] = s2; }
    __syncthreads();
    float t1 = 0.f, t2 = 0.f;
#pragma unroll
    for (int w = 0; w < 8; w++) { t1 += r1[w]; t2 += r2[w]; }
    float mean = t1 * (1.f / DD);
    float inv  = rsqrtf(t2 * (1.f / DD) - mean * mean + LN_EPS);
    g_slnh[row * DD + c] = __float2half_rn((x - mean) * inv * g[c] + b[c]);
}

// ---------------- logits + softmax over slots + per-chunk mask sums ----------------
__global__ __launch_bounds__(256) void k_logits_softmax() {
    __shared__ float qs[256][8];
    __shared__ float ks[256][33];
    __shared__ float msm[8][33];
    int b  = blockIdx.y;
    int n0 = blockIdx.x * 32;
    int tid = threadIdx.x;
#pragma unroll
    for (int t = 0; t < 8; t++) {
        int flat = tid + t * 256; int s = flat >> 8; int i = flat & 255;
        qs[i][s] = g_q[((size_t)b * KS + s) * DD + i];
    }
    // k: fp16 loads (half2 over feature dim)
#pragma unroll 4
    for (int t = 0; t < 16; t++) {
        int flat = tid + t * 256;         // 0..4095 half2 elems
        int i2 = flat & 127, tok = flat >> 7;
        __half2 h = *(const __half2*)(g_kvh + (size_t)(b * NN + n0 + tok) * 512 + i2 * 2);
        float2 f = __half22float2(h);
        ks[i2 * 2][tok]     = f.x;
        ks[i2 * 2 + 1][tok] = f.y;
    }
    __syncthreads();
    int tok = tid >> 3, s = tid & 7;
    float acc = 0.f;
#pragma unroll 4
    for (int i = 0; i < 256; i++) acc += qs[i][s] * ks[i][tok];
    acc *= SCALE_QK;
    float m = acc;
#pragma unroll
    for (int o = 1; o < 8; o <<= 1) m = fmaxf(m, __shfl_xor_sync(0xFFFFFFFFu, m, o));
    float e = expf(acc - m);
    float sum = e;
#pragma unroll
    for (int o = 1; o < 8; o <<= 1) sum += __shfl_xor_sync(0xFFFFFFFFu, sum, o);
    float mask = e / sum;
    g_masks[((size_t)b * KS + s) * NN + n0 + tok] = mask;
    msm[s][tok] = mask;
    __syncthreads();
    if (tid < 8) {
        float tot = 0.f;
#pragma unroll
        for (int j = 0; j < 32; j++) tot += msm[tid][j];
        g_msum[((size_t)b * KS + tid) * 32 + blockIdx.x] = tot;
    }
}

// ---------------- updates partials: (mask+eps) @ v (fp16 v) ----------------
__global__ __launch_bounds__(256) void k_updates() {
    int b = blockIdx.x, ch = blockIdx.y;
    int n0 = ch * 128;
    int tid = threadIdx.x;
    __shared__ float attw[KS][128];
#pragma unroll
    for (int t = 0; t < 4; t++) {
        int flat = tid + t * 256; int kk = flat >> 7; int j = flat & 127;
        attw[kk][j] = g_masks[((size_t)b * KS + kk) * NN + n0 + j] + EPSF;
    }
    __syncthreads();
    float acc[KS];
#pragma unroll
    for (int k = 0; k < KS; k++) acc[k] = 0.f;
    for (int j = 0; j < 128; j++) {
        float vj = __half2float(g_kvh[(size_t)(b * NN + n0 + j) * 512 + 256 + tid]);
#pragma unroll
        for (int kk = 0; kk < KS; kk++) acc[kk] += attw[kk][j] * vj;
    }
#pragma unroll
    for (int kk = 0; kk < KS; kk++)
        g_upart[ch][(b * KS + kk) * DD + tid] = acc[kk];
}

// ---------------- reduce partials; fp16 updates ----------------
__global__ __launch_bounds__(256) void k_ureduce() {
    int row = blockIdx.x;
    int tid = threadIdx.x;
    __shared__ float sden;
    if (tid < 32) {
        float p = g_msum[(size_t)row * 32 + tid];
#pragma unroll
        for (int o = 16; o; o >>= 1) p += __shfl_xor_sync(0xFFFFFFFFu, p, o);
        if (tid == 0) sden = 1.f / (p + (float)NN * EPSF + EPSF);
    }
    __syncthreads();
    float inv = sden;
    float s = 0.f;
#pragma unroll
    for (int c = 0; c < 8; c++) s += g_upart[c][row * DD + tid];
    g_updatesh[row * DD + tid] = __float2half_rn(s * inv);
}

// ---------------- GRU gating + LN(slots) for MLP ----------------
__global__ __launch_bounds__(256) void k_gru_combine_ln(const float* __restrict__ lg,
                                                        const float* __restrict__ lb) {
    int row = blockIdx.x, c = threadIdx.x;
    const float* gt = g_gates + (size_t)row * 1024;
    float sp = g_slots[row * DD + c];
    float r = 1.f / (1.f + expf(-gt[c]));
    float z = 1.f / (1.f + expf(-gt[256 + c]));
    float n = tanhf(gt[512 + c] + r * gt[768 + c]);
    float sN = (1.f - z) * n + z * sp;
    g_slots[row * DD + c] = sN;
    float s1 = sN, s2 = sN * sN;
#pragma unroll
    for (int o = 16; o; o >>= 1) {
        s1 += __shfl_xor_sync(0xFFFFFFFFu, s1, o);
        s2 += __shfl_xor_sync(0xFFFFFFFFu, s2, o);
    }
    __shared__ float r1[8], r2[8];
    if ((c & 31) == 0) { r1[c >> 5] = s1; r2[c >> 5] = s2; }
    __syncthreads();
    float t1 = 0.f, t2 = 0.f;
#pragma unroll
    for (int w = 0; w < 8; w++) { t1 += r1[w]; t2 += r2[w]; }
    float mean = t1 * (1.f / DD);
    float inv  = rsqrtf(t2 * (1.f / DD) - mean * mean + LN_EPS);
    g_slnh[row * DD + c] = __float2half_rn((sN - mean) * inv * lg[c] + lb[c]);
}

// ---------------- pack output ----------------
__global__ void k_out(float* __restrict__ out, int total) {
    for (int idx = blockIdx.x * blockDim.x + threadIdx.x; idx < total;
         idx += gridDim.x * blockDim.x) {
        out[idx] = (idx < BB * KS * DD) ? g_slots[idx] : g_masks[idx - BB * KS * DD];
    }
}

// ---------------- launch ----------------
extern "C" void kernel_launch(void* const* d_in, const int* in_sizes, int n_in,
                              void* d_out, int out_size) {
    const float* tokens     = (const float*)d_in[0];
    const float* init_slots = (const float*)d_in[1];
    const float* ln_in_g    = (const float*)d_in[2];
    const float* ln_in_b    = (const float*)d_in[3];
    const float* Wk         = (const float*)d_in[4];
    const float* bk         = (const float*)d_in[5];
    const float* Wv         = (const float*)d_in[6];
    const float* bv         = (const float*)d_in[7];
    const float* ln_s_g     = (const float*)d_in[8];
    const float* ln_s_b     = (const float*)d_in[9];
    const float* Wq         = (const float*)d_in[10];
    const float* bq         = (const float*)d_in[11];
    const float* W_ih       = (const float*)d_in[12];
    const float* b_ih       = (const float*)d_in[13];
    const float* W_hh       = (const float*)d_in[14];
    const float* b_hh       = (const float*)d_in[15];
    const float* ln_m_g     = (const float*)d_in[16];
    const float* ln_m_b     = (const float*)d_in[17];
    const float* W1         = (const float*)d_in[18];
    const float* b1         = (const float*)d_in[19];
    const float* W2         = (const float*)d_in[20];
    const float* b2         = (const float*)d_in[21];

    __half* d_whq; cudaGetSymbolAddress((void**)&d_whq, g_whq);
    __half* d_wh1; cudaGetSymbolAddress((void**)&d_wh1, g_wh1);
    __half* d_wh2; cudaGetSymbolAddress((void**)&d_wh2, g_wh2);

    k_init_slots<<<BB * KS * DD / 256, 256>>>(init_slots);
    k_ln_apply<<<BB * NN / 8, 256>>>(tokens, ln_in_g, ln_in_b);
    k_prep_wkv<<<256 * 512 / 256, 256>>>(Wk, Wv);
    k_prep_gru<<<512 * 1024 / 256, 256>>>(W_ih, W_hh, b_ih, b_hh);
    k_pack<<<(256 * 256 + 255) / 256, 256>>>(Wq, d_whq, 256 * 256);
    k_pack<<<(256 * 1024 + 255) / 256, 256>>>(W1, d_wh1, 256 * 1024);
    k_pack<<<(1024 * 256 + 255) / 256, 256>>>(W2, d_wh2, 1024 * 256);
    k_gemm_kv_a<<<dim3(4, 1024), 256>>>(bk, bv);

    for (int it = 0; it < 3; it++) {
        k_ln_slots<<<BB * KS, 256>>>(ln_s_g, ln_s_b);
        hgemm<1><<<dim3(4, 16), 128>>>(bq);
        k_logits_softmax<<<dim3(NN / 32, BB), 256>>>();
        k_updates<<<dim3(BB, 8), 256>>>();
        k_ureduce<<<BB * KS, 256>>>();
        hgemm<2><<<dim3(16, 16), 128>>>(nullptr);
        k_gru_combine_ln<<<BB * KS, 256>>>(ln_m_g, ln_m_b);
        hgemm<3><<<dim3(16, 16), 128>>>(b1);
        hgemm<4><<<dim3(4, 16), 128>>>(b2);
    }

    k_out<<<2560, 256>>>((float*)d_out, out_size);
}

// round 13
// speedup vs baseline: 6.6893x; 1.4863x over previous
#include <cuda_runtime.h>
#include <cuda_fp16.h>
#include <math.h>

#define BB 128
#define NN 1024
#define DD 256
#define KS 8
#define HID 1024
#define EPSF 1e-6f
#define LN_EPS 1e-6f
#define SCALE_QK 0.0625f

// ---------------- device scratch ----------------
__device__ __half g_kvh[(size_t)BB * NN * 512]; // [token][0:256]=k fp16, [256:512]=v fp16
__device__ __half g_xh[(size_t)BB * NN * DD];   // LN'd tokens, fp16
__device__ __half g_wh[256 * 512];              // [Wk|Wv] fp16, k-major
__device__ float  g_slots[BB * KS * DD];
__device__ __half g_slotsh[BB * KS * DD];
__device__ __half g_slnh[BB * KS * DD];         // LN'd slots fp16
__device__ __half g_qh[BB * KS * DD];           // q fp16
__device__ float  g_masks[BB * KS * NN];        // softmax masks (output #2)
__device__ __half g_maskh[BB * KS * NN];        // (mask+eps) fp16 for updates GEMM
__device__ float  g_msum[BB * KS * 16];         // per-64tok-chunk mask sums
__device__ __half g_updatesh[BB * KS * DD];
__device__ float  g_gates[BB * KS * 1024];      // [rsum|zsum|inn|hn]
__device__ __half g_hiddenh[BB * KS * HID];
__device__ __half g_wgruh[512 * 1024];          // padded GRU weight fp16
__device__ float  g_bgru[1024];
__device__ __half g_whq[256 * 256];
__device__ __half g_wh1[256 * 1024];
__device__ __half g_wh2[1024 * 256];

// ---------------- helpers ----------------
__device__ __forceinline__ unsigned smem_u32(const void* p) {
    unsigned a;
    asm("{ .reg .u64 t; cvta.to.shared.u64 t, %1; cvt.u32.u64 %0, t; }" : "=r"(a) : "l"(p));
    return a;
}
__device__ __forceinline__ void ldsm_x4(unsigned* r, unsigned addr) {
    asm volatile("ldmatrix.sync.aligned.m8n8.x4.shared.b16 {%0,%1,%2,%3}, [%4];"
                 : "=r"(r[0]), "=r"(r[1]), "=r"(r[2]), "=r"(r[3]) : "r"(addr));
}
__device__ __forceinline__ void ldsm_x4_t(unsigned* r, unsigned addr) {
    asm volatile("ldmatrix.sync.aligned.m8n8.x4.trans.shared.b16 {%0,%1,%2,%3}, [%4];"
                 : "=r"(r[0]), "=r"(r[1]), "=r"(r[2]), "=r"(r[3]) : "r"(addr));
}
__device__ __forceinline__ void mma_f16(float* d, const unsigned* a, const unsigned* b) {
    asm volatile(
        "mma.sync.aligned.m16n8k16.row.col.f32.f16.f16.f32 "
        "{%0,%1,%2,%3}, {%4,%5,%6,%7}, {%8,%9}, {%0,%1,%2,%3};\n"
        : "+f"(d[0]), "+f"(d[1]), "+f"(d[2]), "+f"(d[3])
        : "r"(a[0]), "r"(a[1]), "r"(a[2]), "r"(a[3]), "r"(b[0]), "r"(b[1]));
}
__device__ __forceinline__ void cp_async16(unsigned dst, const void* src) {
    asm volatile("cp.async.cg.shared.global [%0], [%1], 16;" :: "r"(dst), "l"(src) : "memory");
}
#define CP_COMMIT() asm volatile("cp.async.commit_group;" ::: "memory")
#define CP_WAIT1()  asm volatile("cp.async.wait_group 1;" ::: "memory")
#define CP_WAIT0()  asm volatile("cp.async.wait_group 0;" ::: "memory")

// ---------------- init slots ----------------
__global__ void k_init_slots(const float* __restrict__ init_slots) {
    int i = blockIdx.x * 256 + threadIdx.x;
    float v = init_slots[i];
    g_slots[i] = v;
    g_slotsh[i] = __float2half_rn(v);
}

// ---------------- generic fp32 -> fp16 pack ----------------
__global__ void k_pack(const float* __restrict__ s, __half* __restrict__ d, int n) {
    int i = blockIdx.x * 256 + threadIdx.x;
    if (i < n) d[i] = __float2half_rn(s[i]);
}

// ---------------- token LN -> fp16 g_xh ----------------
__global__ __launch_bounds__(256) void k_ln_apply(const float* __restrict__ t,
                                                  const float* __restrict__ g,
                                                  const float* __restrict__ b) {
    int row  = blockIdx.x * 8 + (threadIdx.x >> 5);
    int lane = threadIdx.x & 31;
    const float* p = t + (size_t)row * DD;
    float vals[8]; float s = 0.f, s2 = 0.f;
#pragma unroll
    for (int i = 0; i < 8; i++) { float x = p[lane + i * 32]; vals[i] = x; s += x; s2 += x * x; }
#pragma unroll
    for (int o = 16; o; o >>= 1) {
        s  += __shfl_xor_sync(0xFFFFFFFFu, s,  o);
        s2 += __shfl_xor_sync(0xFFFFFFFFu, s2, o);
    }
    float mean = s * (1.f / DD);
    float inv  = rsqrtf(s2 * (1.f / DD) - mean * mean + LN_EPS);
#pragma unroll
    for (int i = 0; i < 8; i++) {
        int c = lane + i * 32;
        g_xh[(size_t)row * DD + c] = __float2half_rn((vals[i] - mean) * inv * g[c] + b[c]);
    }
}

// ---------------- pack [Wk|Wv] fp16 ----------------
__global__ void k_prep_wkv(const float* __restrict__ Wk, const float* __restrict__ Wv) {
    int idx = blockIdx.x * 256 + threadIdx.x;
    int k = idx >> 9, c = idx & 511;
    float v = (c < 256) ? Wk[k * 256 + c] : Wv[k * 256 + (c - 256)];
    g_wh[idx] = __float2half_rn(v);
}

// ---------------- GRU weight/bias prep (fp16 weight) ----------------
__global__ void k_prep_gru(const float* __restrict__ Wih, const float* __restrict__ Whh,
                           const float* __restrict__ bih, const float* __restrict__ bhh) {
    int idx = blockIdx.x * 256 + threadIdx.x;
    int k = idx >> 10, c = idx & 1023;
    int grp = c >> 8, cc = c & 255;
    float v = 0.f;
    if (k < 256) {
        if (grp < 3) v = Wih[k * 768 + grp * 256 + cc];
    } else {
        int kk = k - 256;
        if (grp < 2)       v = Whh[kk * 768 + grp * 256 + cc];
        else if (grp == 3) v = Whh[kk * 768 + 512 + cc];
    }
    g_wgruh[idx] = __float2half_rn(v);
    if (idx < 1024) {
        int g2 = idx >> 8, c2 = idx & 255;
        float bb;
        if (g2 < 2)       bb = bih[g2 * 256 + c2] + bhh[g2 * 256 + c2];
        else if (g2 == 2) bb = bih[512 + c2];
        else              bb = bhh[512 + c2];
        g_bgru[idx] = bb;
    }
}

// ================= fp16 KV GEMM (cp.async) -> g_kvh =================
__global__ __launch_bounds__(256, 2) void k_gemm_kv_a(const float* __restrict__ bk,
                                                      const float* __restrict__ bv) {
    __shared__ __half sA[2][128 * 40];
    __shared__ __half sB[2][32 * 136];

    int tid = threadIdx.x;
    int warp = tid >> 5, lane = tid & 31;
    int wm = warp & 1, wn = warp >> 1;
    int lr = lane >> 2, lc = lane & 3;
    int col0 = blockIdx.x * 128;
    int row0 = blockIdx.y * 128;
    const float* bias = (col0 < 256) ? bk : bv;
    int wcol0 = (col0 < 256) ? col0 : col0 - 256;

    unsigned baseA0 = smem_u32(&sA[0][0]);
    unsigned baseB0 = smem_u32(&sB[0][0]);

    auto load_stage = [&](int k0, int bf) {
#pragma unroll
        for (int l = 0; l < 2; l++) {
            int task = tid + l * 256;
            int r = task >> 2, ch = task & 3;
            const __half* src = g_xh + (size_t)(row0 + r) * DD + k0 + ch * 8;
            cp_async16(baseA0 + (unsigned)(bf * 128 * 40 + r * 40 + ch * 8) * 2, src);
        }
#pragma unroll
        for (int l = 0; l < 2; l++) {
            int task = tid + l * 256;
            int r = task >> 4, ch = task & 15;
            const __half* src = g_wh + (size_t)(k0 + r) * 512 + col0 + ch * 8;
            cp_async16(baseB0 + (unsigned)(bf * 32 * 136 + r * 136 + ch * 8) * 2, src);
        }
        CP_COMMIT();
    };

    load_stage(0, 0);

    float acc[4][4][4];
#pragma unroll
    for (int mt = 0; mt < 4; mt++)
#pragma unroll
        for (int nt = 0; nt < 4; nt++)
#pragma unroll
            for (int i = 0; i < 4; i++) acc[mt][nt][i] = 0.f;

    for (int s = 0; s < 8; s++) {
        if (s < 7) { load_stage((s + 1) * 32, (s + 1) & 1); CP_WAIT1(); }
        else       { CP_WAIT0(); }
        __syncthreads();
        int bf = s & 1;
        unsigned baseA = baseA0 + (unsigned)(bf * 128 * 40) * 2;
        unsigned baseB = baseB0 + (unsigned)(bf * 32 * 136) * 2;
#pragma unroll
        for (int ks = 0; ks < 2; ks++) {
            int kb = ks * 16;
            unsigned a[4][4], b[2][4];
#pragma unroll
            for (int mt = 0; mt < 4; mt++) {
                int r = wm * 64 + mt * 16 + (lane & 15);
                ldsm_x4(a[mt], baseA + (unsigned)(r * 40 + kb + (lane >> 4) * 8) * 2);
            }
#pragma unroll
            for (int p = 0; p < 2; p++) {
                int kr = kb + (lane & 7) + ((lane >> 3) & 1) * 8;
                int cn = wn * 32 + p * 16 + (lane >> 4) * 8;
                ldsm_x4_t(b[p], baseB + (unsigned)(kr * 136 + cn) * 2);
            }
#pragma unroll
            for (int mt = 0; mt < 4; mt++)
#pragma unroll
                for (int p = 0; p < 2; p++) {
                    mma_f16(acc[mt][2 * p],     a[mt], &b[p][0]);
                    mma_f16(acc[mt][2 * p + 1], a[mt], &b[p][2]);
                }
        }
        __syncthreads();
    }

#pragma unroll
    for (int mt = 0; mt < 4; mt++)
#pragma unroll
        for (int nt = 0; nt < 4; nt++) {
            int r  = row0 + wm * 64 + mt * 16 + lr;
            int cl = wn * 32 + nt * 8 + lc * 2;
            int wc = wcol0 + cl;
            float b0 = bias[wc], b1 = bias[wc + 1];
            size_t o0 = (size_t)r * 512 + col0 + cl;
            size_t o1 = (size_t)(r + 8) * 512 + col0 + cl;
            *(__half2*)(g_kvh + o0) = __floats2half2_rn(acc[mt][nt][0] + b0, acc[mt][nt][1] + b1);
            *(__half2*)(g_kvh + o1) = __floats2half2_rn(acc[mt][nt][2] + b0, acc[mt][nt][3] + b1);
        }
}

// ================= unified small fp16 GEMM (cp.async, prepacked) =================
// MODE 1: qprj g_slnh@g_whq+bq -> g_qh fp16
// MODE 2: gru  [g_updatesh|g_slotsh]@g_wgruh+g_bgru -> g_gates fp32
// MODE 3: mlp1 gelu(g_slnh@g_wh1+b1) -> g_hiddenh fp16
// MODE 4: mlp2 g_slots += g_hiddenh@g_wh2+b2 -> g_slots fp32 + g_slotsh fp16
template<int MODE>
__global__ __launch_bounds__(128) void hgemm(const float* __restrict__ bias_in) {
    constexpr int N   = (MODE == 2 || MODE == 3) ? 1024 : 256;
    constexpr int K   = (MODE == 2) ? 512 : (MODE == 4) ? 1024 : 256;
    constexpr int LDB = (MODE == 2 || MODE == 3) ? 1024 : 256;
    constexpr int LDA = (MODE == 4) ? 1024 : 256;

    __shared__ __half sA[2][64 * 40];
    __shared__ __half sB[2][32 * 72];

    const __half* Abase = (MODE == 2) ? g_updatesh : (MODE == 4) ? g_hiddenh : g_slnh;
    const __half* Bh    = (MODE == 1) ? g_whq : (MODE == 2) ? g_wgruh
                        : (MODE == 3) ? g_wh1 : g_wh2;
    const float* biasp  = (MODE == 2) ? g_bgru : bias_in;

    int tid = threadIdx.x;
    int warp = tid >> 5, lane = tid & 31;
    int wm = warp & 1, wn = warp >> 1;
    int lr = lane >> 2, lc = lane & 3;
    int row0 = blockIdx.y * 64;
    int col0 = blockIdx.x * 64;

    unsigned baseA0 = smem_u32(&sA[0][0]);
    unsigned baseB0 = smem_u32(&sB[0][0]);

    auto load_stage = [&](int k0, int bf) {
        const __half* Ah = Abase; int koff = k0;
        if (MODE == 2 && k0 >= 256) { Ah = g_slotsh; koff = k0 - 256; }
#pragma unroll
        for (int l = 0; l < 2; l++) {
            int task = tid + l * 128;
            int r = task >> 2, ch = task & 3;
            cp_async16(baseA0 + (unsigned)(bf * 64 * 40 + r * 40 + ch * 8) * 2,
                       Ah + (size_t)(row0 + r) * LDA + koff + ch * 8);
        }
#pragma unroll
        for (int l = 0; l < 2; l++) {
            int task = tid + l * 128;
            int r = task >> 3, ch = task & 7;
            cp_async16(baseB0 + (unsigned)(bf * 32 * 72 + r * 72 + ch * 8) * 2,
                       Bh + (size_t)(k0 + r) * LDB + col0 + ch * 8);
        }
        CP_COMMIT();
    };

    load_stage(0, 0);

    float acc[2][4][4];
#pragma unroll
    for (int mt = 0; mt < 2; mt++)
#pragma unroll
        for (int nt = 0; nt < 4; nt++)
#pragma unroll
            for (int i = 0; i < 4; i++) acc[mt][nt][i] = 0.f;

    constexpr int NSTAGE = K / 32;
    for (int s = 0; s < NSTAGE; s++) {
        if (s + 1 < NSTAGE) { load_stage((s + 1) * 32, (s + 1) & 1); CP_WAIT1(); }
        else                { CP_WAIT0(); }
        __syncthreads();
        int bf = s & 1;
        unsigned baseA = baseA0 + (unsigned)(bf * 64 * 40) * 2;
        unsigned baseB = baseB0 + (unsigned)(bf * 32 * 72) * 2;
#pragma unroll
        for (int ks = 0; ks < 2; ks++) {
            int kb = ks * 16;
            unsigned a[2][4], b[2][4];
#pragma unroll
            for (int mt = 0; mt < 2; mt++) {
                int r = wm * 32 + mt * 16 + (lane & 15);
                ldsm_x4(a[mt], baseA + (unsigned)(r * 40 + kb + (lane >> 4) * 8) * 2);
            }
#pragma unroll
            for (int p = 0; p < 2; p++) {
                int kr = kb + (lane & 7) + ((lane >> 3) & 1) * 8;
                int cn = wn * 32 + p * 16 + (lane >> 4) * 8;
                ldsm_x4_t(b[p], baseB + (unsigned)(kr * 72 + cn) * 2);
            }
#pragma unroll
            for (int mt = 0; mt < 2; mt++)
#pragma unroll
                for (int p = 0; p < 2; p++) {
                    mma_f16(acc[mt][2 * p],     a[mt], &b[p][0]);
                    mma_f16(acc[mt][2 * p + 1], a[mt], &b[p][2]);
                }
        }
        __syncthreads();
    }

#pragma unroll
    for (int mt = 0; mt < 2; mt++)
#pragma unroll
        for (int nt = 0; nt < 4; nt++) {
            int r = row0 + wm * 32 + mt * 16 + lr;
            int c = col0 + wn * 32 + nt * 8 + lc * 2;
            float b0 = biasp[c], b1 = biasp[c + 1];
            float v0 = acc[mt][nt][0] + b0, v1 = acc[mt][nt][1] + b1;
            float v2 = acc[mt][nt][2] + b0, v3 = acc[mt][nt][3] + b1;
            if (MODE == 3) {
                v0 = 0.5f * v0 * (1.f + erff(v0 * 0.70710678118654752f));
                v1 = 0.5f * v1 * (1.f + erff(v1 * 0.70710678118654752f));
                v2 = 0.5f * v2 * (1.f + erff(v2 * 0.70710678118654752f));
                v3 = 0.5f * v3 * (1.f + erff(v3 * 0.70710678118654752f));
                *(__half2*)(g_hiddenh + (size_t)r * N + c)       = __floats2half2_rn(v0, v1);
                *(__half2*)(g_hiddenh + (size_t)(r + 8) * N + c) = __floats2half2_rn(v2, v3);
            } else if (MODE == 4) {
                v0 += g_slots[(size_t)r * N + c];       v1 += g_slots[(size_t)r * N + c + 1];
                v2 += g_slots[(size_t)(r + 8) * N + c]; v3 += g_slots[(size_t)(r + 8) * N + c + 1];
                g_slots[(size_t)r * N + c] = v0;        g_slots[(size_t)r * N + c + 1] = v1;
                g_slots[(size_t)(r + 8) * N + c] = v2;  g_slots[(size_t)(r + 8) * N + c + 1] = v3;
                *(__half2*)(g_slotsh + (size_t)r * N + c)       = __floats2half2_rn(v0, v1);
                *(__half2*)(g_slotsh + (size_t)(r + 8) * N + c) = __floats2half2_rn(v2, v3);
            } else if (MODE == 1) {
                *(__half2*)(g_qh + (size_t)r * N + c)       = __floats2half2_rn(v0, v1);
                *(__half2*)(g_qh + (size_t)(r + 8) * N + c) = __floats2half2_rn(v2, v3);
            } else {
                g_gates[(size_t)r * N + c] = v0;       g_gates[(size_t)r * N + c + 1] = v1;
                g_gates[(size_t)(r + 8) * N + c] = v2; g_gates[(size_t)(r + 8) * N + c + 1] = v3;
            }
        }
}

// ================= logits via mma + softmax =================
// Per block: C[16 slots(8 real), 64 tokens] = q_pad[16,256] @ k^T; softmax over slots.
// grid (16, BB), block 128 (4 warps x 16 tokens).
__global__ __launch_bounds__(128) void k_logits_mma() {
    __shared__ __half sQ[16 * 264];     // 8448 B
    __shared__ __half sK[64 * 264];     // 33792 B
    __shared__ float  sC[16 * 72];      // 4608 B
    int b  = blockIdx.y;
    int n0 = blockIdx.x * 64;
    int tid = threadIdx.x;
    int warp = tid >> 5, lane = tid & 31;

    unsigned qb = smem_u32(sQ);
    unsigned kb_ = smem_u32(sK);

    // load q (rows 0-7 real, 8-15 zero)
#pragma unroll
    for (int l = 0; l < 4; l++) {
        int task = tid + l * 128;
        int row = task >> 5, seg = task & 31;
        uint4 v = make_uint4(0, 0, 0, 0);
        if (row < 8) v = *(const uint4*)(g_qh + (size_t)(b * KS + row) * DD + seg * 8);
        *(uint4*)&sQ[row * 264 + seg * 8] = v;
    }
    // load k chunk via cp.async
#pragma unroll
    for (int l = 0; l < 16; l++) {
        int task = tid + l * 128;
        int row = task >> 5, seg = task & 31;
        cp_async16(kb_ + (unsigned)(row * 264 + seg * 8) * 2,
                   g_kvh + (size_t)(b * NN + n0 + row) * 512 + seg * 8);
    }
    CP_COMMIT(); CP_WAIT0();
    __syncthreads();

    unsigned aw[16][4];
#pragma unroll
    for (int ks = 0; ks < 16; ks++)
        ldsm_x4(aw[ks], qb + (unsigned)((lane & 15) * 264 + ks * 16 + (lane >> 4) * 8) * 2);

    float acc[2][4];
#pragma unroll
    for (int f = 0; f < 2; f++)
#pragma unroll
        for (int i = 0; i < 4; i++) acc[f][i] = 0.f;

    int tokw = warp * 16;
#pragma unroll
    for (int ks = 0; ks < 16; ks++) {
        unsigned r[4];
        int nl = tokw + (lane & 7) + ((lane >> 4) & 1) * 8;
        int kh = ((lane >> 3) & 1) * 8;
        ldsm_x4(r, kb_ + (unsigned)(nl * 264 + ks * 16 + kh) * 2);
        mma_f16(acc[0], aw[ks], &r[0]);
        mma_f16(acc[1], aw[ks], &r[2]);
    }

    int lr = lane >> 2, lc = lane & 3;
#pragma unroll
    for (int f = 0; f < 2; f++) {
        int col = tokw + f * 8 + lc * 2;
        sC[lr * 72 + col]           = acc[f][0];
        sC[lr * 72 + col + 1]       = acc[f][1];
        sC[(lr + 8) * 72 + col]     = acc[f][2];
        sC[(lr + 8) * 72 + col + 1] = acc[f][3];
    }
    __syncthreads();

    if (tid < 64) {
        int tok = tid;
        float lg[8];
        float m = -1e30f;
#pragma unroll
        for (int s = 0; s < 8; s++) { lg[s] = sC[s * 72 + tok] * SCALE_QK; m = fmaxf(m, lg[s]); }
        float sum = 0.f;
#pragma unroll
        for (int s = 0; s < 8; s++) { lg[s] = expf(lg[s] - m); sum += lg[s]; }
        float inv = 1.f / sum;
#pragma unroll
        for (int s = 0; s < 8; s++) {
            float mask = lg[s] * inv;
            g_masks[((size_t)b * KS + s) * NN + n0 + tok] = mask;
            g_maskh[((size_t)b * KS + s) * NN + n0 + tok] = __float2half_rn(mask + EPSF);
            sC[s * 72 + tok] = mask;
        }
    }
    __syncthreads();
    if (tid < 8) {
        float tot = 0.f;
#pragma unroll
        for (int j = 0; j < 64; j++) tot += sC[tid * 72 + j];
        g_msum[((size_t)b * KS + tid) * 16 + blockIdx.x] = tot;
    }
}

// ================= updates via mma (+ invden epilogue) =================
// C[16 slots(8 real), 256] = attn_pad[16,1024] @ v[1024,256], scaled by invden.
// grid BB, block 128. K chunks of 32 tokens, double-buffered (issue-before-wait).
__global__ __launch_bounds__(128) void k_updates_mma() {
    __shared__ __half sAt[2][16 * 72];
    __shared__ __half sV[2][32 * 264];
    __shared__ float sden[8];
    int b = blockIdx.x;
    int tid = threadIdx.x;
    int warp = tid >> 5, lane = tid & 31;

    unsigned ab = smem_u32(&sAt[0][0]);
    unsigned vb = smem_u32(&sV[0][0]);

    if (tid < 8) {
        float tot = 0.f;
#pragma unroll
        for (int c = 0; c < 16; c++) tot += g_msum[((size_t)b * KS + tid) * 16 + c];
        sden[tid] = 1.f / (tot + (float)NN * EPSF + EPSF);
    }

    auto load_A = [&](int ch, int bf) {
        if (tid < 64) {
            int row = tid >> 2, seg = tid & 3;
            uint4 v = make_uint4(0, 0, 0, 0);
            if (row < 8)
                v = *(const uint4*)(g_maskh + (size_t)(b * KS + row) * NN + ch * 32 + seg * 8);
            *(uint4*)&sAt[bf][row * 72 + seg * 8] = v;
        }
    };
    auto load_V = [&](int ch, int bf) {
#pragma unroll
        for (int l = 0; l < 8; l++) {
            int task = tid + l * 128;
            int row = task >> 5, seg = task & 31;
            cp_async16(vb + (unsigned)(bf * 32 * 264 + row * 264 + seg * 8) * 2,
                       g_kvh + (size_t)(b * NN + ch * 32 + row) * 512 + 256 + seg * 8);
        }
        CP_COMMIT();
    };

    load_A(0, 0);
    load_V(0, 0);

    float acc[8][4];
#pragma unroll
    for (int g = 0; g < 8; g++)
#pragma unroll
        for (int i = 0; i < 4; i++) acc[g][i] = 0.f;

    for (int ch = 0; ch < 32; ch++) {
        // proven pipeline order: issue next stage, THEN wait, sync, compute, sync
        if (ch < 31) { load_A(ch + 1, (ch + 1) & 1); load_V(ch + 1, (ch + 1) & 1); CP_WAIT1(); }
        else         { CP_WAIT0(); }
        __syncthreads();
        int bf = ch & 1;
        unsigned aB = ab + (unsigned)(bf * 16 * 72) * 2;
        unsigned vB = vb + (unsigned)(bf * 32 * 264) * 2;
#pragma unroll
        for (int ks = 0; ks < 2; ks++) {
            int kb = ks * 16;
            unsigned a[4];
            ldsm_x4(a, aB + (unsigned)((lane & 15) * 72 + kb + (lane >> 4) * 8) * 2);
#pragma unroll
            for (int g2 = 0; g2 < 4; g2++) {
                unsigned bfrag[4];
                int kr = kb + (lane & 7) + ((lane >> 3) & 1) * 8;
                int cn = warp * 64 + g2 * 16 + (lane >> 4) * 8;
                ldsm_x4_t(bfrag, vB + (unsigned)(kr * 264 + cn) * 2);
                mma_f16(acc[g2 * 2],     a, &bfrag[0]);
                mma_f16(acc[g2 * 2 + 1], a, &bfrag[2]);
            }
        }
        __syncthreads();
    }

    int lr = lane >> 2, lc = lane & 3;
    float inv = sden[lr];
#pragma unroll
    for (int g = 0; g < 8; g++) {
        int col = warp * 64 + (g >> 1) * 16 + (g & 1) * 8 + lc * 2;
        *(__half2*)(g_updatesh + (size_t)(b * KS + lr) * DD + col) =
            __floats2half2_rn(acc[g][0] * inv, acc[g][1] * inv);
    }
}

// ---------------- LN of slots -> g_slnh ----------------
__global__ __launch_bounds__(256) void k_ln_slots(const float* __restrict__ g,
                                                  const float* __restrict__ b) {
    int row = blockIdx.x, c = threadIdx.x;
    float x = g_slots[row * DD + c];
    float s1 = x, s2 = x * x;
#pragma unroll
    for (int o = 16; o; o >>= 1) {
        s1 += __shfl_xor_sync(0xFFFFFFFFu, s1, o);
        s2 += __shfl_xor_sync(0xFFFFFFFFu, s2, o);
    }
    __shared__ float r1[8], r2[8];
    if ((c & 31) == 0) { r1[c >> 5] = s1; r2[c >> 5] = s2; }
    __syncthreads();
    float t1 = 0.f, t2 = 0.f;
#pragma unroll
    for (int w = 0; w < 8; w++) { t1 += r1[w]; t2 += r2[w]; }
    float mean = t1 * (1.f / DD);
    float inv  = rsqrtf(t2 * (1.f / DD) - mean * mean + LN_EPS);
    g_slnh[row * DD + c] = __float2half_rn((x - mean) * inv * g[c] + b[c]);
}

// ---------------- GRU gating + LN(slots) for MLP ----------------
__global__ __launch_bounds__(256) void k_gru_combine_ln(const float* __restrict__ lg,
                                                        const float* __restrict__ lb) {
    int row = blockIdx.x, c = threadIdx.x;
    const float* gt = g_gates + (size_t)row * 1024;
    float sp = g_slots[row * DD + c];
    float r = 1.f / (1.f + expf(-gt[c]));
    float z = 1.f / (1.f + expf(-gt[256 + c]));
    float n = tanhf(gt[512 + c] + r * gt[768 + c]);
    float sN = (1.f - z) * n + z * sp;
    g_slots[row * DD + c] = sN;
    float s1 = sN, s2 = sN * sN;
#pragma unroll
    for (int o = 16; o; o >>= 1) {
        s1 += __shfl_xor_sync(0xFFFFFFFFu, s1, o);
        s2 += __shfl_xor_sync(0xFFFFFFFFu, s2, o);
    }
    __shared__ float r1[8], r2[8];
    if ((c & 31) == 0) { r1[c >> 5] = s1; r2[c >> 5] = s2; }
    __syncthreads();
    float t1 = 0.f, t2 = 0.f;
#pragma unroll
    for (int w = 0; w < 8; w++) { t1 += r1[w]; t2 += r2[w]; }
    float mean = t1 * (1.f / DD);
    float inv  = rsqrtf(t2 * (1.f / DD) - mean * mean + LN_EPS);
    g_slnh[row * DD + c] = __float2half_rn((sN - mean) * inv * lg[c] + lb[c]);
}

// ---------------- pack output ----------------
__global__ void k_out(float* __restrict__ out, int total) {
    for (int idx = blockIdx.x * blockDim.x + threadIdx.x; idx < total;
         idx += gridDim.x * blockDim.x) {
        out[idx] = (idx < BB * KS * DD) ? g_slots[idx] : g_masks[idx - BB * KS * DD];
    }
}

// ---------------- launch ----------------
extern "C" void kernel_launch(void* const* d_in, const int* in_sizes, int n_in,
                              void* d_out, int out_size) {
    const float* tokens     = (const float*)d_in[0];
    const float* init_slots = (const float*)d_in[1];
    const float* ln_in_g    = (const float*)d_in[2];
    const float* ln_in_b    = (const float*)d_in[3];
    const float* Wk         = (const float*)d_in[4];
    const float* bk         = (const float*)d_in[5];
    const float* Wv         = (const float*)d_in[6];
    const float* bv         = (const float*)d_in[7];
    const float* ln_s_g     = (const float*)d_in[8];
    const float* ln_s_b     = (const float*)d_in[9];
    const float* Wq         = (const float*)d_in[10];
    const float* bq         = (const float*)d_in[11];
    const float* W_ih       = (const float*)d_in[12];
    const float* b_ih       = (const float*)d_in[13];
    const float* W_hh       = (const float*)d_in[14];
    const float* b_hh       = (const float*)d_in[15];
    const float* ln_m_g     = (const float*)d_in[16];
    const float* ln_m_b     = (const float*)d_in[17];
    const float* W1         = (const float*)d_in[18];
    const float* b1         = (const float*)d_in[19];
    const float* W2         = (const float*)d_in[20];
    const float* b2         = (const float*)d_in[21];

    __half* d_whq; cudaGetSymbolAddress((void**)&d_whq, g_whq);
    __half* d_wh1; cudaGetSymbolAddress((void**)&d_wh1, g_wh1);
    __half* d_wh2; cudaGetSymbolAddress((void**)&d_wh2, g_wh2);

    k_init_slots<<<BB * KS * DD / 256, 256>>>(init_slots);
    k_ln_apply<<<BB * NN / 8, 256>>>(tokens, ln_in_g, ln_in_b);
    k_prep_wkv<<<256 * 512 / 256, 256>>>(Wk, Wv);
    k_prep_gru<<<512 * 1024 / 256, 256>>>(W_ih, W_hh, b_ih, b_hh);
    k_pack<<<(256 * 256 + 255) / 256, 256>>>(Wq, d_whq, 256 * 256);
    k_pack<<<(256 * 1024 + 255) / 256, 256>>>(W1, d_wh1, 256 * 1024);
    k_pack<<<(1024 * 256 + 255) / 256, 256>>>(W2, d_wh2, 1024 * 256);
    k_gemm_kv_a<<<dim3(4, 1024), 256>>>(bk, bv);

    for (int it = 0; it < 3; it++) {
        k_ln_slots<<<BB * KS, 256>>>(ln_s_g, ln_s_b);
        hgemm<1><<<dim3(4, 16), 128>>>(bq);
        k_logits_mma<<<dim3(16, BB), 128>>>();
        k_updates_mma<<<BB, 128>>>();
        hgemm<2><<<dim3(16, 16), 128>>>(nullptr);
        k_gru_combine_ln<<<BB * KS, 256>>>(ln_m_g, ln_m_b);
        hgemm<3><<<dim3(16, 16), 128>>>(b1);
        hgemm<4><<<dim3(4, 16), 128>>>(b2);
    }

    k_out<<<2560, 256>>>((float*)d_out, out_size);
}

// round 15
// speedup vs baseline: 6.8636x; 1.0261x over previous
#include <cuda_runtime.h>
#include <cuda_fp16.h>
#include <math.h>

#define BB 128
#define NN 1024
#define DD 256
#define KS 8
#define HID 1024
#define EPSF 1e-6f
#define LN_EPS 1e-6f
#define SCALE_QK 0.0625f

// ---------------- device scratch ----------------
__device__ __half g_kvh[(size_t)BB * NN * 512]; // [token][0:256]=k fp16, [256:512]=v fp16
__device__ __half g_xh[(size_t)BB * NN * DD];   // LN'd tokens, fp16
__device__ __half g_wh[256 * 512];              // [Wk|Wv] fp16, k-major
__device__ float  g_slots[BB * KS * DD];
__device__ __half g_slotsh[BB * KS * DD];
__device__ __half g_slnh[BB * KS * DD];         // LN'd slots fp16
__device__ __half g_qh[BB * KS * DD];           // q fp16
__device__ float  g_masks[BB * KS * NN];        // softmax masks (output #2)
__device__ __half g_maskh[BB * KS * NN];        // (mask+eps) fp16 for updates GEMM
__device__ float  g_msum[BB * KS * 16];         // per-64tok-chunk mask sums
__device__ __half g_updatesh[BB * KS * DD];
__device__ float  g_gates[BB * KS * 1024];      // [rsum|zsum|inn|hn]
__device__ __half g_hiddenh[BB * KS * HID];
__device__ __half g_wgruh[512 * 1024];          // padded GRU weight fp16
__device__ float  g_bgru[1024];
__device__ __half g_whq[256 * 256];
__device__ __half g_wh1[256 * 1024];
__device__ __half g_wh2[1024 * 256];

// ---------------- helpers ----------------
__device__ __forceinline__ unsigned smem_u32(const void* p) {
    unsigned a;
    asm("{ .reg .u64 t; cvta.to.shared.u64 t, %1; cvt.u32.u64 %0, t; }" : "=r"(a) : "l"(p));
    return a;
}
__device__ __forceinline__ void ldsm_x4(unsigned* r, unsigned addr) {
    asm volatile("ldmatrix.sync.aligned.m8n8.x4.shared.b16 {%0,%1,%2,%3}, [%4];"
                 : "=r"(r[0]), "=r"(r[1]), "=r"(r[2]), "=r"(r[3]) : "r"(addr));
}
__device__ __forceinline__ void ldsm_x4_t(unsigned* r, unsigned addr) {
    asm volatile("ldmatrix.sync.aligned.m8n8.x4.trans.shared.b16 {%0,%1,%2,%3}, [%4];"
                 : "=r"(r[0]), "=r"(r[1]), "=r"(r[2]), "=r"(r[3]) : "r"(addr));
}
__device__ __forceinline__ void mma_f16(float* d, const unsigned* a, const unsigned* b) {
    asm volatile(
        "mma.sync.aligned.m16n8k16.row.col.f32.f16.f16.f32 "
        "{%0,%1,%2,%3}, {%4,%5,%6,%7}, {%8,%9}, {%0,%1,%2,%3};\n"
        : "+f"(d[0]), "+f"(d[1]), "+f"(d[2]), "+f"(d[3])
        : "r"(a[0]), "r"(a[1]), "r"(a[2]), "r"(a[3]), "r"(b[0]), "r"(b[1]));
}
__device__ __forceinline__ void cp_async16(unsigned dst, const void* src) {
    asm volatile("cp.async.cg.shared.global [%0], [%1], 16;" :: "r"(dst), "l"(src) : "memory");
}
#define CP_COMMIT() asm volatile("cp.async.commit_group;" ::: "memory")
#define CP_WAIT1()  asm volatile("cp.async.wait_group 1;" ::: "memory")
#define CP_WAIT0()  asm volatile("cp.async.wait_group 0;" ::: "memory")

// ---------------- init slots ----------------
__global__ void k_init_slots(const float* __restrict__ init_slots) {
    int i = blockIdx.x * 256 + threadIdx.x;
    float v = init_slots[i];
    g_slots[i] = v;
    g_slotsh[i] = __float2half_rn(v);
}

// ---------------- generic fp32 -> fp16 pack ----------------
__global__ void k_pack(const float* __restrict__ s, __half* __restrict__ d, int n) {
    int i = blockIdx.x * 256 + threadIdx.x;
    if (i < n) d[i] = __float2half_rn(s[i]);
}

// ---------------- token LN -> fp16 g_xh ----------------
__global__ __launch_bounds__(256) void k_ln_apply(const float* __restrict__ t,
                                                  const float* __restrict__ g,
                                                  const float* __restrict__ b) {
    int row  = blockIdx.x * 8 + (threadIdx.x >> 5);
    int lane = threadIdx.x & 31;
    const float* p = t + (size_t)row * DD;
    float vals[8]; float s = 0.f, s2 = 0.f;
#pragma unroll
    for (int i = 0; i < 8; i++) { float x = p[lane + i * 32]; vals[i] = x; s += x; s2 += x * x; }
#pragma unroll
    for (int o = 16; o; o >>= 1) {
        s  += __shfl_xor_sync(0xFFFFFFFFu, s,  o);
        s2 += __shfl_xor_sync(0xFFFFFFFFu, s2, o);
    }
    float mean = s * (1.f / DD);
    float inv  = rsqrtf(s2 * (1.f / DD) - mean * mean + LN_EPS);
#pragma unroll
    for (int i = 0; i < 8; i++) {
        int c = lane + i * 32;
        g_xh[(size_t)row * DD + c] = __float2half_rn((vals[i] - mean) * inv * g[c] + b[c]);
    }
}

// ---------------- pack [Wk|Wv] fp16 ----------------
__global__ void k_prep_wkv(const float* __restrict__ Wk, const float* __restrict__ Wv) {
    int idx = blockIdx.x * 256 + threadIdx.x;
    int k = idx >> 9, c = idx & 511;
    float v = (c < 256) ? Wk[k * 256 + c] : Wv[k * 256 + (c - 256)];
    g_wh[idx] = __float2half_rn(v);
}

// ---------------- GRU weight/bias prep (fp16 weight) ----------------
__global__ void k_prep_gru(const float* __restrict__ Wih, const float* __restrict__ Whh,
                           const float* __restrict__ bih, const float* __restrict__ bhh) {
    int idx = blockIdx.x * 256 + threadIdx.x;
    int k = idx >> 10, c = idx & 1023;
    int grp = c >> 8, cc = c & 255;
    float v = 0.f;
    if (k < 256) {
        if (grp < 3) v = Wih[k * 768 + grp * 256 + cc];
    } else {
        int kk = k - 256;
        if (grp < 2)       v = Whh[kk * 768 + grp * 256 + cc];
        else if (grp == 3) v = Whh[kk * 768 + 512 + cc];
    }
    g_wgruh[idx] = __float2half_rn(v);
    if (idx < 1024) {
        int g2 = idx >> 8, c2 = idx & 255;
        float bb;
        if (g2 < 2)       bb = bih[g2 * 256 + c2] + bhh[g2 * 256 + c2];
        else if (g2 == 2) bb = bih[512 + c2];
        else              bb = bhh[512 + c2];
        g_bgru[idx] = bb;
    }
}

// ================= fp16 KV GEMM (cp.async, 2-stage proven) -> g_kvh =================
__global__ __launch_bounds__(256, 2) void k_gemm_kv_a(const float* __restrict__ bk,
                                                      const float* __restrict__ bv) {
    __shared__ __half sA[2][128 * 40];
    __shared__ __half sB[2][32 * 136];

    int tid = threadIdx.x;
    int warp = tid >> 5, lane = tid & 31;
    int wm = warp & 1, wn = warp >> 1;
    int lr = lane >> 2, lc = lane & 3;
    int col0 = blockIdx.x * 128;
    int row0 = blockIdx.y * 128;
    const float* bias = (col0 < 256) ? bk : bv;
    int wcol0 = (col0 < 256) ? col0 : col0 - 256;

    unsigned baseA0 = smem_u32(&sA[0][0]);
    unsigned baseB0 = smem_u32(&sB[0][0]);

    auto load_stage = [&](int k0, int bf) {
#pragma unroll
        for (int l = 0; l < 2; l++) {
            int task = tid + l * 256;
            int r = task >> 2, ch = task & 3;
            const __half* src = g_xh + (size_t)(row0 + r) * DD + k0 + ch * 8;
            cp_async16(baseA0 + (unsigned)(bf * 128 * 40 + r * 40 + ch * 8) * 2, src);
        }
#pragma unroll
        for (int l = 0; l < 2; l++) {
            int task = tid + l * 256;
            int r = task >> 4, ch = task & 15;
            const __half* src = g_wh + (size_t)(k0 + r) * 512 + col0 + ch * 8;
            cp_async16(baseB0 + (unsigned)(bf * 32 * 136 + r * 136 + ch * 8) * 2, src);
        }
        CP_COMMIT();
    };

    load_stage(0, 0);

    float acc[4][4][4];
#pragma unroll
    for (int mt = 0; mt < 4; mt++)
#pragma unroll
        for (int nt = 0; nt < 4; nt++)
#pragma unroll
            for (int i = 0; i < 4; i++) acc[mt][nt][i] = 0.f;

    for (int s = 0; s < 8; s++) {
        if (s < 7) { load_stage((s + 1) * 32, (s + 1) & 1); CP_WAIT1(); }
        else       { CP_WAIT0(); }
        __syncthreads();
        int bf = s & 1;
        unsigned baseA = baseA0 + (unsigned)(bf * 128 * 40) * 2;
        unsigned baseB = baseB0 + (unsigned)(bf * 32 * 136) * 2;
#pragma unroll
        for (int ks = 0; ks < 2; ks++) {
            int kb = ks * 16;
            unsigned a[4][4], b[2][4];
#pragma unroll
            for (int mt = 0; mt < 4; mt++) {
                int r = wm * 64 + mt * 16 + (lane & 15);
                ldsm_x4(a[mt], baseA + (unsigned)(r * 40 + kb + (lane >> 4) * 8) * 2);
            }
#pragma unroll
            for (int p = 0; p < 2; p++) {
                int kr = kb + (lane & 7) + ((lane >> 3) & 1) * 8;
                int cn = wn * 32 + p * 16 + (lane >> 4) * 8;
                ldsm_x4_t(b[p], baseB + (unsigned)(kr * 136 + cn) * 2);
            }
#pragma unroll
            for (int mt = 0; mt < 4; mt++)
#pragma unroll
                for (int p = 0; p < 2; p++) {
                    mma_f16(acc[mt][2 * p],     a[mt], &b[p][0]);
                    mma_f16(acc[mt][2 * p + 1], a[mt], &b[p][2]);
                }
        }
        __syncthreads();
    }

#pragma unroll
    for (int mt = 0; mt < 4; mt++)
#pragma unroll
        for (int nt = 0; nt < 4; nt++) {
            int r  = row0 + wm * 64 + mt * 16 + lr;
            int cl = wn * 32 + nt * 8 + lc * 2;
            int wc = wcol0 + cl;
            float b0 = bias[wc], b1 = bias[wc + 1];
            size_t o0 = (size_t)r * 512 + col0 + cl;
            size_t o1 = (size_t)(r + 8) * 512 + col0 + cl;
            *(__half2*)(g_kvh + o0) = __floats2half2_rn(acc[mt][nt][0] + b0, acc[mt][nt][1] + b1);
            *(__half2*)(g_kvh + o1) = __floats2half2_rn(acc[mt][nt][2] + b0, acc[mt][nt][3] + b1);
        }
}

// ================= unified small fp16 GEMM (3-stage ring, single sync/stage) =================
// MODE 1: qprj g_slnh@g_whq+bq -> g_qh fp16
// MODE 2: gru  [g_updatesh|g_slotsh]@g_wgruh+g_bgru -> g_gates fp32
// MODE 3: mlp1 gelu(g_slnh@g_wh1+b1) -> g_hiddenh fp16
// MODE 4: mlp2 g_slots += g_hiddenh@g_wh2+b2 -> g_slots fp32 + g_slotsh fp16
template<int MODE>
__global__ __launch_bounds__(128) void hgemm(const float* __restrict__ bias_in) {
    constexpr int N   = (MODE == 2 || MODE == 3) ? 1024 : 256;
    constexpr int K   = (MODE == 2) ? 512 : (MODE == 4) ? 1024 : 256;
    constexpr int LDB = (MODE == 2 || MODE == 3) ? 1024 : 256;
    constexpr int LDA = (MODE == 4) ? 1024 : 256;
    constexpr int NSTAGE = K / 32;

    __shared__ __half sA[3][64 * 40];
    __shared__ __half sB[3][32 * 72];

    const __half* Abase = (MODE == 2) ? g_updatesh : (MODE == 4) ? g_hiddenh : g_slnh;
    const __half* Bh    = (MODE == 1) ? g_whq : (MODE == 2) ? g_wgruh
                        : (MODE == 3) ? g_wh1 : g_wh2;
    const float* biasp  = (MODE == 2) ? g_bgru : bias_in;

    int tid = threadIdx.x;
    int warp = tid >> 5, lane = tid & 31;
    int wm = warp & 1, wn = warp >> 1;
    int lr = lane >> 2, lc = lane & 3;
    int row0 = blockIdx.y * 64;
    int col0 = blockIdx.x * 64;

    unsigned baseA0 = smem_u32(&sA[0][0]);
    unsigned baseB0 = smem_u32(&sB[0][0]);

    auto load_stage = [&](int sidx, int bf) {
        int k0 = sidx * 32;
        const __half* Ah = Abase; int koff = k0;
        if (MODE == 2 && k0 >= 256) { Ah = g_slotsh; koff = k0 - 256; }
#pragma unroll
        for (int l = 0; l < 2; l++) {
            int task = tid + l * 128;
            int r = task >> 2, ch = task & 3;
            cp_async16(baseA0 + (unsigned)(bf * 64 * 40 + r * 40 + ch * 8) * 2,
                       Ah + (size_t)(row0 + r) * LDA + koff + ch * 8);
        }
#pragma unroll
        for (int l = 0; l < 2; l++) {
            int task = tid + l * 128;
            int r = task >> 3, ch = task & 7;
            cp_async16(baseB0 + (unsigned)(bf * 32 * 72 + r * 72 + ch * 8) * 2,
                       Bh + (size_t)(k0 + r) * LDB + col0 + ch * 8);
        }
        CP_COMMIT();
    };

    load_stage(0, 0);
    load_stage(1, 1);

    float acc[2][4][4];
#pragma unroll
    for (int mt = 0; mt < 2; mt++)
#pragma unroll
        for (int nt = 0; nt < 4; nt++)
#pragma unroll
            for (int i = 0; i < 4; i++) acc[mt][nt][i] = 0.f;

    for (int s = 0; s < NSTAGE; s++) {
        if (s + 1 < NSTAGE) CP_WAIT1(); else CP_WAIT0();
        __syncthreads();
        int bf = s % 3;
        unsigned baseA = baseA0 + (unsigned)(bf * 64 * 40) * 2;
        unsigned baseB = baseB0 + (unsigned)(bf * 32 * 72) * 2;
#pragma unroll
        for (int ks = 0; ks < 2; ks++) {
            int kb = ks * 16;
            unsigned a[2][4], b[2][4];
#pragma unroll
            for (int mt = 0; mt < 2; mt++) {
                int r = wm * 32 + mt * 16 + (lane & 15);
                ldsm_x4(a[mt], baseA + (unsigned)(r * 40 + kb + (lane >> 4) * 8) * 2);
            }
#pragma unroll
            for (int p = 0; p < 2; p++) {
                int kr = kb + (lane & 7) + ((lane >> 3) & 1) * 8;
                int cn = wn * 32 + p * 16 + (lane >> 4) * 8;
                ldsm_x4_t(b[p], baseB + (unsigned)(kr * 72 + cn) * 2);
            }
#pragma unroll
            for (int mt = 0; mt < 2; mt++)
#pragma unroll
                for (int p = 0; p < 2; p++) {
                    mma_f16(acc[mt][2 * p],     a[mt], &b[p][0]);
                    mma_f16(acc[mt][2 * p + 1], a[mt], &b[p][2]);
                }
        }
        if (s + 2 < NSTAGE) load_stage(s + 2, (s + 2) % 3);
    }

#pragma unroll
    for (int mt = 0; mt < 2; mt++)
#pragma unroll
        for (int nt = 0; nt < 4; nt++) {
            int r = row0 + wm * 32 + mt * 16 + lr;
            int c = col0 + wn * 32 + nt * 8 + lc * 2;
            float b0 = biasp[c], b1 = biasp[c + 1];
            float v0 = acc[mt][nt][0] + b0, v1 = acc[mt][nt][1] + b1;
            float v2 = acc[mt][nt][2] + b0, v3 = acc[mt][nt][3] + b1;
            if (MODE == 3) {
                v0 = 0.5f * v0 * (1.f + erff(v0 * 0.70710678118654752f));
                v1 = 0.5f * v1 * (1.f + erff(v1 * 0.70710678118654752f));
                v2 = 0.5f * v2 * (1.f + erff(v2 * 0.70710678118654752f));
                v3 = 0.5f * v3 * (1.f + erff(v3 * 0.70710678118654752f));
                *(__half2*)(g_hiddenh + (size_t)r * N + c)       = __floats2half2_rn(v0, v1);
                *(__half2*)(g_hiddenh + (size_t)(r + 8) * N + c) = __floats2half2_rn(v2, v3);
            } else if (MODE == 4) {
                v0 += g_slots[(size_t)r * N + c];       v1 += g_slots[(size_t)r * N + c + 1];
                v2 += g_slots[(size_t)(r + 8) * N + c]; v3 += g_slots[(size_t)(r + 8) * N + c + 1];
                g_slots[(size_t)r * N + c] = v0;        g_slots[(size_t)r * N + c + 1] = v1;
                g_slots[(size_t)(r + 8) * N + c] = v2;  g_slots[(size_t)(r + 8) * N + c + 1] = v3;
                *(__half2*)(g_slotsh + (size_t)r * N + c)       = __floats2half2_rn(v0, v1);
                *(__half2*)(g_slotsh + (size_t)(r + 8) * N + c) = __floats2half2_rn(v2, v3);
            } else if (MODE == 1) {
                *(__half2*)(g_qh + (size_t)r * N + c)       = __floats2half2_rn(v0, v1);
                *(__half2*)(g_qh + (size_t)(r + 8) * N + c) = __floats2half2_rn(v2, v3);
            } else {
                g_gates[(size_t)r * N + c] = v0;       g_gates[(size_t)r * N + c + 1] = v1;
                g_gates[(size_t)(r + 8) * N + c] = v2; g_gates[(size_t)(r + 8) * N + c + 1] = v3;
            }
        }
}

// ================= logits via mma + softmax =================
__global__ __launch_bounds__(128) void k_logits_mma() {
    __shared__ __half sQ[16 * 264];
    __shared__ __half sK[64 * 264];
    __shared__ float  sC[16 * 72];
    int b  = blockIdx.y;
    int n0 = blockIdx.x * 64;
    int tid = threadIdx.x;
    int warp = tid >> 5, lane = tid & 31;

    unsigned qb = smem_u32(sQ);
    unsigned kb_ = smem_u32(sK);

#pragma unroll
    for (int l = 0; l < 4; l++) {
        int task = tid + l * 128;
        int row = task >> 5, seg = task & 31;
        uint4 v = make_uint4(0, 0, 0, 0);
        if (row < 8) v = *(const uint4*)(g_qh + (size_t)(b * KS + row) * DD + seg * 8);
        *(uint4*)&sQ[row * 264 + seg * 8] = v;
    }
#pragma unroll
    for (int l = 0; l < 16; l++) {
        int task = tid + l * 128;
        int row = task >> 5, seg = task & 31;
        cp_async16(kb_ + (unsigned)(row * 264 + seg * 8) * 2,
                   g_kvh + (size_t)(b * NN + n0 + row) * 512 + seg * 8);
    }
    CP_COMMIT(); CP_WAIT0();
    __syncthreads();

    unsigned aw[16][4];
#pragma unroll
    for (int ks = 0; ks < 16; ks++)
        ldsm_x4(aw[ks], qb + (unsigned)((lane & 15) * 264 + ks * 16 + (lane >> 4) * 8) * 2);

    float acc[2][4];
#pragma unroll
    for (int f = 0; f < 2; f++)
#pragma unroll
        for (int i = 0; i < 4; i++) acc[f][i] = 0.f;

    int tokw = warp * 16;
#pragma unroll
    for (int ks = 0; ks < 16; ks++) {
        unsigned r[4];
        int nl = tokw + (lane & 7) + ((lane >> 4) & 1) * 8;
        int kh = ((lane >> 3) & 1) * 8;
        ldsm_x4(r, kb_ + (unsigned)(nl * 264 + ks * 16 + kh) * 2);
        mma_f16(acc[0], aw[ks], &r[0]);
        mma_f16(acc[1], aw[ks], &r[2]);
    }

    int lr = lane >> 2, lc = lane & 3;
#pragma unroll
    for (int f = 0; f < 2; f++) {
        int col = tokw + f * 8 + lc * 2;
        sC[lr * 72 + col]           = acc[f][0];
        sC[lr * 72 + col + 1]       = acc[f][1];
        sC[(lr + 8) * 72 + col]     = acc[f][2];
        sC[(lr + 8) * 72 + col + 1] = acc[f][3];
    }
    __syncthreads();

    if (tid < 64) {
        int tok = tid;
        float lg[8];
        float m = -1e30f;
#pragma unroll
        for (int s = 0; s < 8; s++) { lg[s] = sC[s * 72 + tok] * SCALE_QK; m = fmaxf(m, lg[s]); }
        float sum = 0.f;
#pragma unroll
        for (int s = 0; s < 8; s++) { lg[s] = expf(lg[s] - m); sum += lg[s]; }
        float inv = 1.f / sum;
#pragma unroll
        for (int s = 0; s < 8; s++) {
            float mask = lg[s] * inv;
            g_masks[((size_t)b * KS + s) * NN + n0 + tok] = mask;
            g_maskh[((size_t)b * KS + s) * NN + n0 + tok] = __float2half_rn(mask + EPSF);
            sC[s * 72 + tok] = mask;
        }
    }
    __syncthreads();
    if (tid < 8) {
        float tot = 0.f;
#pragma unroll
        for (int j = 0; j < 64; j++) tot += sC[tid * 72 + j];
        g_msum[((size_t)b * KS + tid) * 16 + blockIdx.x] = tot;
    }
}

// ================= updates via mma, N-split x2 =================
// grid (BB, 2): block computes C[16 slots(8 real), 128 feats] with invden epilogue.
__global__ __launch_bounds__(128) void k_updates_mma() {
    __shared__ __half sAt[2][16 * 72];
    __shared__ __half sV[2][32 * 136];
    __shared__ float sden[8];
    int b = blockIdx.x;
    int colbase = blockIdx.y * 128;
    int tid = threadIdx.x;
    int warp = tid >> 5, lane = tid & 31;

    unsigned ab = smem_u32(&sAt[0][0]);
    unsigned vb = smem_u32(&sV[0][0]);

    if (tid < 8) {
        float tot = 0.f;
#pragma unroll
        for (int c = 0; c < 16; c++) tot += g_msum[((size_t)b * KS + tid) * 16 + c];
        sden[tid] = 1.f / (tot + (float)NN * EPSF + EPSF);
    }

    auto load_A = [&](int ch, int bf) {
        if (tid < 64) {
            int row = tid >> 2, seg = tid & 3;
            uint4 v = make_uint4(0, 0, 0, 0);
            if (row < 8)
                v = *(const uint4*)(g_maskh + (size_t)(b * KS + row) * NN + ch * 32 + seg * 8);
            *(uint4*)&sAt[bf][row * 72 + seg * 8] = v;
        }
    };
    auto load_V = [&](int ch, int bf) {
#pragma unroll
        for (int l = 0; l < 4; l++) {
            int task = tid + l * 128;         // 0..511
            int row = task >> 4, seg = task & 15;
            cp_async16(vb + (unsigned)(bf * 32 * 136 + row * 136 + seg * 8) * 2,
                       g_kvh + (size_t)(b * NN + ch * 32 + row) * 512 + 256 + colbase + seg * 8);
        }
        CP_COMMIT();
    };

    load_A(0, 0);
    load_V(0, 0);

    float acc[4][4];
#pragma unroll
    for (int g = 0; g < 4; g++)
#pragma unroll
        for (int i = 0; i < 4; i++) acc[g][i] = 0.f;

    for (int ch = 0; ch < 32; ch++) {
        if (ch < 31) { load_A(ch + 1, (ch + 1) & 1); load_V(ch + 1, (ch + 1) & 1); CP_WAIT1(); }
        else         { CP_WAIT0(); }
        __syncthreads();
        int bf = ch & 1;
        unsigned aB = ab + (unsigned)(bf * 16 * 72) * 2;
        unsigned vB = vb + (unsigned)(bf * 32 * 136) * 2;
#pragma unroll
        for (int ks = 0; ks < 2; ks++) {
            int kb = ks * 16;
            unsigned a[4];
            ldsm_x4(a, aB + (unsigned)((lane & 15) * 72 + kb + (lane >> 4) * 8) * 2);
#pragma unroll
            for (int g2 = 0; g2 < 2; g2++) {       // warp covers 32 cols: 2 n16 groups
                unsigned bfrag[4];
                int kr = kb + (lane & 7) + ((lane >> 3) & 1) * 8;
                int cn = warp * 32 + g2 * 16 + (lane >> 4) * 8;
                ldsm_x4_t(bfrag, vB + (unsigned)(kr * 136 + cn) * 2);
                mma_f16(acc[g2 * 2],     a, &bfrag[0]);
                mma_f16(acc[g2 * 2 + 1], a, &bfrag[2]);
            }
        }
        __syncthreads();
    }

    int lr = lane >> 2, lc = lane & 3;
    float inv = sden[lr];
#pragma unroll
    for (int g = 0; g < 4; g++) {
        int col = colbase + warp * 32 + (g >> 1) * 16 + (g & 1) * 8 + lc * 2;
        *(__half2*)(g_updatesh + (size_t)(b * KS + lr) * DD + col) =
            __floats2half2_rn(acc[g][0] * inv, acc[g][1] * inv);
    }
}

// ---------------- LN of slots -> g_slnh ----------------
__global__ __launch_bounds__(256) void k_ln_slots(const float* __restrict__ g,
                                                  const float* __restrict__ b) {
    int row = blockIdx.x, c = threadIdx.x;
    float x = g_slots[row * DD + c];
    float s1 = x, s2 = x * x;
#pragma unroll
    for (int o = 16; o; o >>= 1) {
        s1 += __shfl_xor_sync(0xFFFFFFFFu, s1, o);
        s2 += __shfl_xor_sync(0xFFFFFFFFu, s2, o);
    }
    __shared__ float r1[8], r2[8];
    if ((c & 31) == 0) { r1[c >> 5] = s1; r2[c >> 5] = s2; }
    __syncthreads();
    float t1 = 0.f, t2 = 0.f;
#pragma unroll
    for (int w = 0; w < 8; w++) { t1 += r1[w]; t2 += r2[w]; }
    float mean = t1 * (1.f / DD);
    float inv  = rsqrtf(t2 * (1.f / DD) - mean * mean + LN_EPS);
    g_slnh[row * DD + c] = __float2half_rn((x - mean) * inv * g[c] + b[c]);
}

// ---------------- GRU gating + LN(slots) for MLP ----------------
__global__ __launch_bounds__(256) void k_gru_combine_ln(const float* __restrict__ lg,
                                                        const float* __restrict__ lb) {
    int row = blockIdx.x, c = threadIdx.x;
    const float* gt = g_gates + (size_t)row * 1024;
    float sp = g_slots[row * DD + c];
    float r = 1.f / (1.f + expf(-gt[c]));
    float z = 1.f / (1.f + expf(-gt[256 + c]));
    float n = tanhf(gt[512 + c] + r * gt[768 + c]);
    float sN = (1.f - z) * n + z * sp;
    g_slots[row * DD + c] = sN;
    float s1 = sN, s2 = sN * sN;
#pragma unroll
    for (int o = 16; o; o >>= 1) {
        s1 += __shfl_xor_sync(0xFFFFFFFFu, s1, o);
        s2 += __shfl_xor_sync(0xFFFFFFFFu, s2, o);
    }
    __shared__ float r1[8], r2[8];
    if ((c & 31) == 0) { r1[c >> 5] = s1; r2[c >> 5] = s2; }
    __syncthreads();
    float t1 = 0.f, t2 = 0.f;
#pragma unroll
    for (int w = 0; w < 8; w++) { t1 += r1[w]; t2 += r2[w]; }
    float mean = t1 * (1.f / DD);
    float inv  = rsqrtf(t2 * (1.f / DD) - mean * mean + LN_EPS);
    g_slnh[row * DD + c] = __float2half_rn((sN - mean) * inv * lg[c] + lb[c]);
}

// ---------------- pack output ----------------
__global__ void k_out(float* __restrict__ out, int total) {
    for (int idx = blockIdx.x * blockDim.x + threadIdx.x; idx < total;
         idx += gridDim.x * blockDim.x) {
        out[idx] = (idx < BB * KS * DD) ? g_slots[idx] : g_masks[idx - BB * KS * DD];
    }
}

// ---------------- launch ----------------
extern "C" void kernel_launch(void* const* d_in, const int* in_sizes, int n_in,
                              void* d_out, int out_size) {
    const float* tokens     = (const float*)d_in[0];
    const float* init_slots = (const float*)d_in[1];
    const float* ln_in_g    = (const float*)d_in[2];
    const float* ln_in_b    = (const float*)d_in[3];
    const float* Wk         = (const float*)d_in[4];
    const float* bk         = (const float*)d_in[5];
    const float* Wv         = (const float*)d_in[6];
    const float* bv         = (const float*)d_in[7];
    const float* ln_s_g     = (const float*)d_in[8];
    const float* ln_s_b     = (const float*)d_in[9];
    const float* Wq         = (const float*)d_in[10];
    const float* bq         = (const float*)d_in[11];
    const float* W_ih       = (const float*)d_in[12];
    const float* b_ih       = (const float*)d_in[13];
    const float* W_hh       = (const float*)d_in[14];
    const float* b_hh       = (const float*)d_in[15];
    const float* ln_m_g     = (const float*)d_in[16];
    const float* ln_m_b     = (const float*)d_in[17];
    const float* W1         = (const float*)d_in[18];
    const float* b1         = (const float*)d_in[19];
    const float* W2         = (const float*)d_in[20];
    const float* b2         = (const float*)d_in[21];

    __half* d_whq; cudaGetSymbolAddress((void**)&d_whq, g_whq);
    __half* d_wh1; cudaGetSymbolAddress((void**)&d_wh1, g_wh1);
    __half* d_wh2; cudaGetSymbolAddress((void**)&d_wh2, g_wh2);

    k_init_slots<<<BB * KS * DD / 256, 256>>>(init_slots);
    k_ln_apply<<<BB * NN / 8, 256>>>(tokens, ln_in_g, ln_in_b);
    k_prep_wkv<<<256 * 512 / 256, 256>>>(Wk, Wv);
    k_prep_gru<<<512 * 1024 / 256, 256>>>(W_ih, W_hh, b_ih, b_hh);
    k_pack<<<(256 * 256 + 255) / 256, 256>>>(Wq, d_whq, 256 * 256);
    k_pack<<<(256 * 1024 + 255) / 256, 256>>>(W1, d_wh1, 256 * 1024);
    k_pack<<<(1024 * 256 + 255) / 256, 256>>>(W2, d_wh2, 1024 * 256);
    k_gemm_kv_a<<<dim3(4, 1024), 256>>>(bk, bv);

    for (int it = 0; it < 3; it++) {
        k_ln_slots<<<BB * KS, 256>>>(ln_s_g, ln_s_b);
        hgemm<1><<<dim3(4, 16), 128>>>(bq);
        k_logits_mma<<<dim3(16, BB), 128>>>();
        k_updates_mma<<<dim3(BB, 2), 128>>>();
        hgemm<2><<<dim3(16, 16), 128>>>(nullptr);
        k_gru_combine_ln<<<BB * KS, 256>>>(ln_m_g, ln_m_b);
        hgemm<3><<<dim3(16, 16), 128>>>(b1);
        hgemm<4><<<dim3(4, 16), 128>>>(b2);
    }

    k_out<<<2560, 256>>>((float*)d_out, out_size);
}